// round 1
// baseline (speedup 1.0000x reference)
#include <cuda_runtime.h>
#include <math.h>

// Problem constants
#define BATCH 4
#define TSEQ  1024
#define DMODEL 1024
#define NH 16
#define DHEAD 64
#define QKV_N 3072   // 3*DMODEL
#define MROWS 4096   // BATCH*TSEQ

// Scratch (device globals: allocation-free)
__device__ float g_qkv[(size_t)MROWS * QKV_N];   // [B*T, 3D]
__device__ float g_attn[(size_t)MROWS * DMODEL]; // [B*T, D]

// ---------------------------------------------------------------------------
// SGEMM: C[M,N] = A[M,K] @ B[K,N] + bias[N]
// 128x128x16 block tile, 256 threads, 8x8 microtile (2x2 of 4x4 chunks).
// Requires M%128==0, N%128==0, K%16==0 (true for all our shapes).
// ---------------------------------------------------------------------------
__global__ __launch_bounds__(256) void sgemm_bias(
    const float* __restrict__ A, const float* __restrict__ B,
    const float* __restrict__ bias, float* __restrict__ C,
    int M, int N, int K)
{
    __shared__ float As[16][132];  // transposed: As[k][m], padded
    __shared__ float Bs[16][128];  // Bs[k][n]

    const int t  = threadIdx.x;
    const int tx = t & 15;
    const int ty = t >> 4;
    const int bm = blockIdx.y << 7;
    const int bn = blockIdx.x << 7;

    float acc[2][2][4][4];
#pragma unroll
    for (int ri = 0; ri < 2; ri++)
#pragma unroll
        for (int ci = 0; ci < 2; ci++)
#pragma unroll
            for (int i = 0; i < 4; i++)
#pragma unroll
                for (int j = 0; j < 4; j++) acc[ri][ci][i][j] = 0.0f;

    for (int kt = 0; kt < K; kt += 16) {
        // Load A tile 128x16, store transposed
#pragma unroll
        for (int p = 0; p < 2; p++) {
            int f   = t + (p << 8);
            int row = f >> 2;            // 0..127
            int cg  = (f & 3) << 2;      // 0,4,8,12
            const float4 v = *reinterpret_cast<const float4*>(
                A + (size_t)(bm + row) * K + kt + cg);
            As[cg + 0][row] = v.x;
            As[cg + 1][row] = v.y;
            As[cg + 2][row] = v.z;
            As[cg + 3][row] = v.w;
        }
        // Load B tile 16x128
#pragma unroll
        for (int p = 0; p < 2; p++) {
            int f   = t + (p << 8);
            int row = f >> 5;            // 0..15
            int cg  = (f & 31) << 2;     // 0..124
            *reinterpret_cast<float4*>(&Bs[row][cg]) =
                *reinterpret_cast<const float4*>(B + (size_t)(kt + row) * N + bn + cg);
        }
        __syncthreads();

#pragma unroll
        for (int k = 0; k < 16; k++) {
            float4 a0 = *reinterpret_cast<float4*>(&As[k][ty << 2]);
            float4 a1 = *reinterpret_cast<float4*>(&As[k][64 + (ty << 2)]);
            float4 b0 = *reinterpret_cast<float4*>(&Bs[k][tx << 2]);
            float4 b1 = *reinterpret_cast<float4*>(&Bs[k][64 + (tx << 2)]);
            float a[2][4] = {{a0.x, a0.y, a0.z, a0.w}, {a1.x, a1.y, a1.z, a1.w}};
            float b[2][4] = {{b0.x, b0.y, b0.z, b0.w}, {b1.x, b1.y, b1.z, b1.w}};
#pragma unroll
            for (int ri = 0; ri < 2; ri++)
#pragma unroll
                for (int i = 0; i < 4; i++)
#pragma unroll
                    for (int ci = 0; ci < 2; ci++)
#pragma unroll
                        for (int j = 0; j < 4; j++)
                            acc[ri][ci][i][j] += a[ri][i] * b[ci][j];
        }
        __syncthreads();
    }

    // Epilogue: add bias, store
#pragma unroll
    for (int ri = 0; ri < 2; ri++)
#pragma unroll
        for (int i = 0; i < 4; i++) {
            int r = bm + ri * 64 + (ty << 2) + i;
#pragma unroll
            for (int ci = 0; ci < 2; ci++) {
                int c = bn + ci * 64 + (tx << 2);
                float4 bv = *reinterpret_cast<const float4*>(bias + c);
                float4 o;
                o.x = acc[ri][ci][i][0] + bv.x;
                o.y = acc[ri][ci][i][1] + bv.y;
                o.z = acc[ri][ci][i][2] + bv.z;
                o.w = acc[ri][ci][i][3] + bv.w;
                *reinterpret_cast<float4*>(C + (size_t)r * N + c) = o;
            }
        }
}

// ---------------------------------------------------------------------------
// Fused causal flash attention (fp32).
// Grid: (8, B*H). Each block processes q-tiles {15-bx, bx} of one (b,h):
// total K-tile visits per block = (16-bx) + (bx+1) = 17 -> perfectly balanced.
// Block: 256 threads as 16(ty rows) x 16(tx cols); 4x4 microtiles.
// Shared: Qs[d][row] (64x68), KPs union: Ks[d][key] then Ps[key][row] (64x68),
//         Vs[key][d] (64x64). Total 51200 bytes dynamic.
// ---------------------------------------------------------------------------
#define QPAD 68
#define ATTN_SMEM_BYTES ((2 * 64 * QPAD + 64 * 64) * 4)

__global__ __launch_bounds__(256) void attn_kernel(
    const float* __restrict__ qkv, const int* __restrict__ mask,
    float* __restrict__ out)
{
    extern __shared__ float sm[];
    float* Qs  = sm;                 // [64][QPAD]  Qs[d*QPAD + row], pre-scaled
    float* KPs = sm + 64 * QPAD;     // [64][QPAD]  Ks[d*QPAD + key] / Ps[key*QPAD + row]
    float* Vs  = sm + 2 * 64 * QPAD; // [64][64]    Vs[key*64 + d]

    const int t  = threadIdx.x;
    const int tx = t & 15;
    const int ty = t >> 4;
    const int bh = blockIdx.y;
    const int b  = bh >> 4;
    const int h  = bh & 15;
    const float* qkv_b = qkv + (size_t)b * TSEQ * QKV_N;

#pragma unroll 1
    for (int pass = 0; pass < 2; pass++) {
        const int qt = (pass == 0) ? (15 - (int)blockIdx.x) : (int)blockIdx.x;

        __syncthreads();  // protect Qs across passes (no-op on first)

        // Load Q tile, transposed + pre-scaled by 1/sqrt(DH)=0.125
#pragma unroll
        for (int p = 0; p < 4; p++) {
            int f   = t + (p << 8);
            int row = f >> 4;
            int d   = (f & 15) << 2;
            const float4 v = *reinterpret_cast<const float4*>(
                qkv_b + (size_t)(qt * 64 + row) * QKV_N + h * DHEAD + d);
            Qs[(d + 0) * QPAD + row] = v.x * 0.125f;
            Qs[(d + 1) * QPAD + row] = v.y * 0.125f;
            Qs[(d + 2) * QPAD + row] = v.z * 0.125f;
            Qs[(d + 3) * QPAD + row] = v.w * 0.125f;
        }

        float o_acc[4][4];
        float m_i[4], l_i[4];
#pragma unroll
        for (int i = 0; i < 4; i++) {
            m_i[i] = -INFINITY;
            l_i[i] = 0.0f;
#pragma unroll
            for (int j = 0; j < 4; j++) o_acc[i][j] = 0.0f;
        }

        const int row0 = qt * 64 + (ty << 2);

#pragma unroll 1
        for (int kt = 0; kt <= qt; kt++) {
            __syncthreads();  // prior readers of KPs/Vs done; also orders Qs stores

            // Load K (transposed) and V tiles
#pragma unroll
            for (int p = 0; p < 4; p++) {
                int f   = t + (p << 8);
                int key = f >> 4;
                int d   = (f & 15) << 2;
                const size_t base = (size_t)(kt * 64 + key) * QKV_N + h * DHEAD + d;
                const float4 kv = *reinterpret_cast<const float4*>(qkv_b + DMODEL + base);
                KPs[(d + 0) * QPAD + key] = kv.x;
                KPs[(d + 1) * QPAD + key] = kv.y;
                KPs[(d + 2) * QPAD + key] = kv.z;
                KPs[(d + 3) * QPAD + key] = kv.w;
                const float4 vv = *reinterpret_cast<const float4*>(qkv_b + 2 * DMODEL + base);
                *reinterpret_cast<float4*>(&Vs[key * 64 + d]) = vv;
            }
            __syncthreads();

            // S = Qs^T @ Ks  (4x4 per thread)
            float s[4][4];
#pragma unroll
            for (int i = 0; i < 4; i++)
#pragma unroll
                for (int j = 0; j < 4; j++) s[i][j] = 0.0f;
#pragma unroll
            for (int k = 0; k < 64; k++) {
                float4 av = *reinterpret_cast<float4*>(&Qs[k * QPAD + (ty << 2)]);
                float4 bv = *reinterpret_cast<float4*>(&KPs[k * QPAD + (tx << 2)]);
                float a[4] = {av.x, av.y, av.z, av.w};
                float bb[4] = {bv.x, bv.y, bv.z, bv.w};
#pragma unroll
                for (int i = 0; i < 4; i++)
#pragma unroll
                    for (int j = 0; j < 4; j++) s[i][j] += a[i] * bb[j];
            }

            // Causal + key mask
            const int col0 = kt * 64 + (tx << 2);
#pragma unroll
            for (int j = 0; j < 4; j++) {
                const int c = col0 + j;
                const bool mk = (mask[b * TSEQ + c] != 0);
#pragma unroll
                for (int i = 0; i < 4; i++)
                    if (!mk || c > row0 + i) s[i][j] = -INFINITY;
            }

            // Online softmax (reduce across the 16 tx lanes of each row)
#pragma unroll
            for (int i = 0; i < 4; i++) {
                float rmax = fmaxf(fmaxf(s[i][0], s[i][1]), fmaxf(s[i][2], s[i][3]));
#pragma unroll
                for (int o = 8; o > 0; o >>= 1)
                    rmax = fmaxf(rmax, __shfl_xor_sync(0xffffffffu, rmax, o));
                const float mnew  = fmaxf(m_i[i], rmax);
                const float alpha = __expf(m_i[i] - mnew);
                m_i[i] = mnew;
                float ls = 0.0f;
#pragma unroll
                for (int j = 0; j < 4; j++) {
                    const float p = __expf(s[i][j] - mnew);
                    s[i][j] = p;
                    ls += p;
                }
#pragma unroll
                for (int o = 8; o > 0; o >>= 1)
                    ls += __shfl_xor_sync(0xffffffffu, ls, o);
                l_i[i] = l_i[i] * alpha + ls;
#pragma unroll
                for (int j = 0; j < 4; j++) o_acc[i][j] *= alpha;
            }

            __syncthreads();  // everyone done reading Ks

            // Store P into the K buffer, transposed: Ps[key][row]
#pragma unroll
            for (int j = 0; j < 4; j++)
#pragma unroll
                for (int i = 0; i < 4; i++)
                    KPs[((tx << 2) + j) * QPAD + (ty << 2) + i] = s[i][j];
            __syncthreads();

            // O += P @ V
#pragma unroll
            for (int kk = 0; kk < 64; kk++) {
                float4 av = *reinterpret_cast<float4*>(&KPs[kk * QPAD + (ty << 2)]);
                float4 bv = *reinterpret_cast<float4*>(&Vs[kk * 64 + (tx << 2)]);
                float a[4] = {av.x, av.y, av.z, av.w};
                float bb[4] = {bv.x, bv.y, bv.z, bv.w};
#pragma unroll
                for (int i = 0; i < 4; i++)
#pragma unroll
                    for (int j = 0; j < 4; j++) o_acc[i][j] += a[i] * bb[j];
            }
        }

        // Normalize and write out: [B*T, D] with col = h*64 + d
#pragma unroll
        for (int i = 0; i < 4; i++) {
            const float inv = 1.0f / l_i[i];
            const int rg = row0 + i;
            float4 o;
            o.x = o_acc[i][0] * inv;
            o.y = o_acc[i][1] * inv;
            o.z = o_acc[i][2] * inv;
            o.w = o_acc[i][3] * inv;
            *reinterpret_cast<float4*>(
                out + (size_t)(b * TSEQ + rg) * DMODEL + h * DHEAD + (tx << 2)) = o;
        }
    }
}

// ---------------------------------------------------------------------------
extern "C" void kernel_launch(void* const* d_in, const int* in_sizes, int n_in,
                              void* d_out, int out_size)
{
    const float* x     = (const float*)d_in[0];  // [4,1024,1024]
    const float* Wqkv  = (const float*)d_in[1];  // [1024,3072]
    const float* bqkv  = (const float*)d_in[2];  // [3072]
    const float* Wproj = (const float*)d_in[3];  // [1024,1024]
    const float* bproj = (const float*)d_in[4];  // [1024]
    const int*   mask  = (const int*)d_in[5];    // [4,1024]
    float* out = (float*)d_out;                  // [4,1024,1024]

    float* qkv  = nullptr;
    float* attn = nullptr;
    cudaGetSymbolAddress((void**)&qkv,  g_qkv);
    cudaGetSymbolAddress((void**)&attn, g_attn);

    // Idempotent; first applied on the (non-captured) correctness call.
    cudaFuncSetAttribute(attn_kernel,
                         cudaFuncAttributeMaxDynamicSharedMemorySize,
                         ATTN_SMEM_BYTES);

    // 1) QKV = x @ Wqkv + bqkv
    sgemm_bias<<<dim3(QKV_N / 128, MROWS / 128), 256>>>(
        x, Wqkv, bqkv, qkv, MROWS, QKV_N, DMODEL);

    // 2) Fused causal attention
    attn_kernel<<<dim3(8, BATCH * NH), 256, ATTN_SMEM_BYTES>>>(qkv, mask, attn);

    // 3) out = attn @ Wproj + bproj
    sgemm_bias<<<dim3(DMODEL / 128, MROWS / 128), 256>>>(
        attn, Wproj, bproj, out, MROWS, DMODEL, DMODEL);
}

// round 3
// speedup vs baseline: 1.5192x; 1.5192x over previous
#include <cuda_runtime.h>
#include <cuda_bf16.h>
#include <math.h>
#include <cstdint>

// Problem constants
#define BATCH 4
#define TSEQ  1024
#define DMODEL 1024
#define NH 16
#define DHEAD 64
#define QKV_N 3072   // 3*DMODEL
#define MROWS 4096   // BATCH*TSEQ
#define KDIM 1024    // K is 1024 for both GEMMs

// ---------------------------------------------------------------------------
// Scratch (device globals: allocation-free)
// ---------------------------------------------------------------------------
__device__ float g_qkv[(size_t)MROWS * QKV_N];    // [B*T, 3D] fp32
__device__ float g_attn[(size_t)MROWS * DMODEL];  // [B*T, D]  fp32
__device__ __nv_bfloat16 g_xh[(size_t)MROWS * DMODEL];
__device__ __nv_bfloat16 g_xl[(size_t)MROWS * DMODEL];
__device__ __nv_bfloat16 g_ah[(size_t)MROWS * DMODEL];
__device__ __nv_bfloat16 g_al[(size_t)MROWS * DMODEL];
__device__ __nv_bfloat16 g_wqh[(size_t)QKV_N * DMODEL];   // Wqkv^T [3072][1024]
__device__ __nv_bfloat16 g_wql[(size_t)QKV_N * DMODEL];
__device__ __nv_bfloat16 g_wph[(size_t)DMODEL * DMODEL];  // Wproj^T [1024][1024]
__device__ __nv_bfloat16 g_wpl[(size_t)DMODEL * DMODEL];

// ---------------------------------------------------------------------------
// PTX helpers (base ISA only — NO tcgen05: harness compiles via compute_103)
// ---------------------------------------------------------------------------
__device__ __forceinline__ uint32_t smem_to_u32(const void* p) {
    uint32_t a;
    asm("{ .reg .u64 t; cvta.to.shared.u64 t, %1; cvt.u32.u64 %0, t; }"
        : "=r"(a) : "l"(p));
    return a;
}

#define CP_ASYNC16(smem, gptr) \
    asm volatile("cp.async.cg.shared.global [%0], [%1], 16;" \
        :: "r"(smem), "l"(gptr) : "memory")
#define CP_COMMIT() asm volatile("cp.async.commit_group;" ::: "memory")
#define CP_WAIT(n)  asm volatile("cp.async.wait_group %0;" :: "n"(n) : "memory")

#define LDSM_X4(r0, r1, r2, r3, addr) \
    asm volatile("ldmatrix.sync.aligned.m8n8.x4.shared.b16 {%0,%1,%2,%3}, [%4];" \
        : "=r"(r0), "=r"(r1), "=r"(r2), "=r"(r3) : "r"(addr))

#define MMA16816(c, a, b0, b1) \
    asm volatile("mma.sync.aligned.m16n8k16.row.col.f32.bf16.bf16.f32 " \
        "{%0,%1,%2,%3}, {%4,%5,%6,%7}, {%8,%9}, {%0,%1,%2,%3};" \
        : "+f"((c)[0]), "+f"((c)[1]), "+f"((c)[2]), "+f"((c)[3]) \
        : "r"((a)[0]), "r"((a)[1]), "r"((a)[2]), "r"((a)[3]), \
          "r"(b0), "r"(b1))

// ---------------------------------------------------------------------------
// Split-bf16 HMMA GEMM: C[M,Ntot] = (Ah+Al)[M,K] @ ((Bh+Bl)[Ntot,K])^T + bias
// (3-product: Ah*Bh + Ah*Bl + Al*Bh, fp32 accumulate)
// CTA 128x128, K-tile 32, 3-stage cp.async pipeline, 8 warps (2x4), each 64x32.
// smem per matrix per stage: 128 rows x 40 bf16 (80B padded rows) = 10240B.
// ---------------------------------------------------------------------------
#define MATB   10240
#define STAGEB 40960
#define NSTAGE 3
#define GEMM_SMEM (NSTAGE * STAGEB)

__global__ __launch_bounds__(256, 1) void gemm_hmma(
    const __nv_bfloat16* __restrict__ Ah, const __nv_bfloat16* __restrict__ Al,
    const __nv_bfloat16* __restrict__ Bh, const __nv_bfloat16* __restrict__ Bl,
    const float* __restrict__ bias, float* __restrict__ C,
    int M, int Ntot)
{
    extern __shared__ char dsm[];
    const uint32_t sb = smem_to_u32(dsm);

    const int t    = threadIdx.x;
    const int lane = t & 31;
    const int wid  = t >> 5;
    const int wm   = wid >> 2;          // 0..1  (64-row slab)
    const int wn   = wid & 3;           // 0..3  (32-col slab)
    const int bm   = blockIdx.y << 7;
    const int bn   = blockIdx.x << 7;

    // ---- per-thread cp.async plan: 8 chunks (2 per matrix) ----
    // matrix m: 0=Ah 1=Al 2=Bh 3=Bl; 512 16B-chunks each (128 rows x 4)
    const int row0 = t >> 2;        // 0..63
    const int ch0  = t & 3;         // 0..3
    uint32_t soff[8];
    const __nv_bfloat16* gp[8];
    {
        const __nv_bfloat16* bases[4] = {Ah, Al, Bh, Bl};
        const int rb[4] = {bm, bm, bn, bn};
#pragma unroll
        for (int m = 0; m < 4; m++)
#pragma unroll
            for (int h = 0; h < 2; h++) {
                const int r = row0 + h * 64;
                soff[m * 2 + h] = (uint32_t)(m * MATB + r * 80 + ch0 * 16);
                gp[m * 2 + h]   = bases[m] + (size_t)(rb[m] + r) * KDIM + ch0 * 8;
            }
    }

    // ---- fragment smem addresses (stage-relative) ----
    // A: row = wm*64 + mi*16 + (lane&15), chunk = (lane>>4) + 2*ks
    const uint32_t a_base = (uint32_t)((wm * 64 + (lane & 15)) * 80 + (lane >> 4) * 16);
    // B: row = wn*32 + g*16 + (lane&7) + ((lane>>4)<<3), chunk = ((lane>>3)&1) + 2*ks
    const uint32_t b_base = (uint32_t)(2 * MATB +
        (wn * 32 + (lane & 7) + ((lane >> 4) << 3)) * 80 + ((lane >> 3) & 1) * 16);

    float acc[4][4][4];
#pragma unroll
    for (int mi = 0; mi < 4; mi++)
#pragma unroll
        for (int ni = 0; ni < 4; ni++)
#pragma unroll
            for (int e = 0; e < 4; e++) acc[mi][ni][e] = 0.0f;

    const int NT = KDIM / 32;   // 32 k-tiles

    // ---- prologue: stages 0..NSTAGE-2 ----
#pragma unroll
    for (int s = 0; s < NSTAGE - 1; s++) {
        const uint32_t st = sb + (uint32_t)s * STAGEB;
        const int ko = s * 32;
#pragma unroll
        for (int i = 0; i < 8; i++) CP_ASYNC16(st + soff[i], gp[i] + ko);
        CP_COMMIT();
    }

#pragma unroll 1
    for (int kt = 0; kt < NT; kt++) {
        CP_WAIT(NSTAGE - 2);
        __syncthreads();

        // issue next stage load
        if (kt + NSTAGE - 1 < NT) {
            const uint32_t st = sb + (uint32_t)((kt + NSTAGE - 1) % NSTAGE) * STAGEB;
            const int ko = (kt + NSTAGE - 1) * 32;
#pragma unroll
            for (int i = 0; i < 8; i++) CP_ASYNC16(st + soff[i], gp[i] + ko);
        }
        CP_COMMIT();

        const uint32_t stg = sb + (uint32_t)(kt % NSTAGE) * STAGEB;

#pragma unroll
        for (int ks = 0; ks < 2; ks++) {
            const uint32_t ko = (uint32_t)(ks * 32);   // bytes within 80B row
            uint32_t ah[4][4], al[4][4];
#pragma unroll
            for (int mi = 0; mi < 4; mi++) {
                LDSM_X4(ah[mi][0], ah[mi][1], ah[mi][2], ah[mi][3],
                        stg + a_base + (uint32_t)(mi * 1280) + ko);
                LDSM_X4(al[mi][0], al[mi][1], al[mi][2], al[mi][3],
                        stg + MATB + a_base + (uint32_t)(mi * 1280) + ko);
            }
            uint32_t rbh[2][4], rbl[2][4];
#pragma unroll
            for (int g = 0; g < 2; g++) {
                LDSM_X4(rbh[g][0], rbh[g][1], rbh[g][2], rbh[g][3],
                        stg + b_base + (uint32_t)(g * 1280) + ko);
                LDSM_X4(rbl[g][0], rbl[g][1], rbl[g][2], rbl[g][3],
                        stg + MATB + b_base + (uint32_t)(g * 1280) + ko);
            }
#pragma unroll
            for (int mi = 0; mi < 4; mi++)
#pragma unroll
                for (int ni = 0; ni < 4; ni++) {
                    const int g = ni >> 1, u = (ni & 1) * 2;
                    MMA16816(acc[mi][ni], ah[mi], rbh[g][u], rbh[g][u + 1]);
                    MMA16816(acc[mi][ni], ah[mi], rbl[g][u], rbl[g][u + 1]);
                    MMA16816(acc[mi][ni], al[mi], rbh[g][u], rbh[g][u + 1]);
                }
        }
    }

    // ---- epilogue: add bias, store fp32 ----
    const int er = bm + wm * 64 + (lane >> 2);
    const int ec = bn + wn * 32 + (lane & 3) * 2;
#pragma unroll
    for (int ni = 0; ni < 4; ni++) {
        const int col = ec + ni * 8;
        const float2 bv = *reinterpret_cast<const float2*>(bias + col);
#pragma unroll
        for (int mi = 0; mi < 4; mi++) {
            const int r0 = er + mi * 16;
            float2 o0, o1;
            o0.x = acc[mi][ni][0] + bv.x;
            o0.y = acc[mi][ni][1] + bv.y;
            o1.x = acc[mi][ni][2] + bv.x;
            o1.y = acc[mi][ni][3] + bv.y;
            *reinterpret_cast<float2*>(C + (size_t)r0 * Ntot + col) = o0;
            *reinterpret_cast<float2*>(C + (size_t)(r0 + 8) * Ntot + col) = o1;
        }
    }
}

// ---------------------------------------------------------------------------
// fp32 -> (bf16 hi, bf16 lo) elementwise split, 4 elems/thread
// ---------------------------------------------------------------------------
__global__ __launch_bounds__(256) void convert_split(
    const float* __restrict__ A, __nv_bfloat16* __restrict__ H,
    __nv_bfloat16* __restrict__ L)
{
    const int i = blockIdx.x * blockDim.x + threadIdx.x;
    const float4 v = reinterpret_cast<const float4*>(A)[i];
    __nv_bfloat16 h0 = __float2bfloat16(v.x), h1 = __float2bfloat16(v.y);
    __nv_bfloat16 h2 = __float2bfloat16(v.z), h3 = __float2bfloat16(v.w);
    __nv_bfloat16 l0 = __float2bfloat16(v.x - __bfloat162float(h0));
    __nv_bfloat16 l1 = __float2bfloat16(v.y - __bfloat162float(h1));
    __nv_bfloat16 l2 = __float2bfloat16(v.z - __bfloat162float(h2));
    __nv_bfloat16 l3 = __float2bfloat16(v.w - __bfloat162float(h3));
    reinterpret_cast<__nv_bfloat162*>(H)[2 * i + 0] = __halves2bfloat162(h0, h1);
    reinterpret_cast<__nv_bfloat162*>(H)[2 * i + 1] = __halves2bfloat162(h2, h3);
    reinterpret_cast<__nv_bfloat162*>(L)[2 * i + 0] = __halves2bfloat162(l0, l1);
    reinterpret_cast<__nv_bfloat162*>(L)[2 * i + 1] = __halves2bfloat162(l2, l3);
}

// ---------------------------------------------------------------------------
// W[K][N] fp32 -> Wt_hi/lo[N][K] bf16 (transpose + split), block (32,8)
// ---------------------------------------------------------------------------
__global__ __launch_bounds__(256) void convert_transpose(
    const float* __restrict__ W, __nv_bfloat16* __restrict__ Th,
    __nv_bfloat16* __restrict__ Tl, int K, int N)
{
    __shared__ float tile[32][33];
    const int tx = threadIdx.x, ty = threadIdx.y;
    const int n0 = blockIdx.x * 32, k0 = blockIdx.y * 32;
#pragma unroll
    for (int i = 0; i < 4; i++)
        tile[ty + i * 8][tx] = W[(size_t)(k0 + ty + i * 8) * N + n0 + tx];
    __syncthreads();
#pragma unroll
    for (int i = 0; i < 4; i++) {
        const float v = tile[tx][ty + i * 8];
        const __nv_bfloat16 h = __float2bfloat16(v);
        const __nv_bfloat16 l = __float2bfloat16(v - __bfloat162float(h));
        const size_t o = (size_t)(n0 + ty + i * 8) * K + k0 + tx;
        Th[o] = h;
        Tl[o] = l;
    }
}

// ---------------------------------------------------------------------------
// Fused causal flash attention (fp32) — unchanged (known-good, ~305us)
// ---------------------------------------------------------------------------
#define QPAD 68
#define ATTN_SMEM_BYTES ((2 * 64 * QPAD + 64 * 64) * 4)

__global__ __launch_bounds__(256) void attn_kernel(
    const float* __restrict__ qkv, const int* __restrict__ mask,
    float* __restrict__ out)
{
    extern __shared__ float sm[];
    float* Qs  = sm;
    float* KPs = sm + 64 * QPAD;
    float* Vs  = sm + 2 * 64 * QPAD;

    const int t  = threadIdx.x;
    const int tx = t & 15;
    const int ty = t >> 4;
    const int bh = blockIdx.y;
    const int b  = bh >> 4;
    const int h  = bh & 15;
    const float* qkv_b = qkv + (size_t)b * TSEQ * QKV_N;

#pragma unroll 1
    for (int pass = 0; pass < 2; pass++) {
        const int qt = (pass == 0) ? (15 - (int)blockIdx.x) : (int)blockIdx.x;
        __syncthreads();

#pragma unroll
        for (int p = 0; p < 4; p++) {
            int f   = t + (p << 8);
            int row = f >> 4;
            int d   = (f & 15) << 2;
            const float4 v = *reinterpret_cast<const float4*>(
                qkv_b + (size_t)(qt * 64 + row) * QKV_N + h * DHEAD + d);
            Qs[(d + 0) * QPAD + row] = v.x * 0.125f;
            Qs[(d + 1) * QPAD + row] = v.y * 0.125f;
            Qs[(d + 2) * QPAD + row] = v.z * 0.125f;
            Qs[(d + 3) * QPAD + row] = v.w * 0.125f;
        }

        float o_acc[4][4];
        float m_i[4], l_i[4];
#pragma unroll
        for (int i = 0; i < 4; i++) {
            m_i[i] = -INFINITY;
            l_i[i] = 0.0f;
#pragma unroll
            for (int j = 0; j < 4; j++) o_acc[i][j] = 0.0f;
        }

        const int row0 = qt * 64 + (ty << 2);

#pragma unroll 1
        for (int kt = 0; kt <= qt; kt++) {
            __syncthreads();
#pragma unroll
            for (int p = 0; p < 4; p++) {
                int f   = t + (p << 8);
                int key = f >> 4;
                int d   = (f & 15) << 2;
                const size_t base = (size_t)(kt * 64 + key) * QKV_N + h * DHEAD + d;
                const float4 kv = *reinterpret_cast<const float4*>(qkv_b + DMODEL + base);
                KPs[(d + 0) * QPAD + key] = kv.x;
                KPs[(d + 1) * QPAD + key] = kv.y;
                KPs[(d + 2) * QPAD + key] = kv.z;
                KPs[(d + 3) * QPAD + key] = kv.w;
                const float4 vv = *reinterpret_cast<const float4*>(qkv_b + 2 * DMODEL + base);
                *reinterpret_cast<float4*>(&Vs[key * 64 + d]) = vv;
            }
            __syncthreads();

            float s[4][4];
#pragma unroll
            for (int i = 0; i < 4; i++)
#pragma unroll
                for (int j = 0; j < 4; j++) s[i][j] = 0.0f;
#pragma unroll
            for (int k = 0; k < 64; k++) {
                float4 av = *reinterpret_cast<float4*>(&Qs[k * QPAD + (ty << 2)]);
                float4 bv = *reinterpret_cast<float4*>(&KPs[k * QPAD + (tx << 2)]);
                float a[4] = {av.x, av.y, av.z, av.w};
                float bb[4] = {bv.x, bv.y, bv.z, bv.w};
#pragma unroll
                for (int i = 0; i < 4; i++)
#pragma unroll
                    for (int j = 0; j < 4; j++) s[i][j] += a[i] * bb[j];
            }

            const int col0 = kt * 64 + (tx << 2);
#pragma unroll
            for (int j = 0; j < 4; j++) {
                const int c = col0 + j;
                const bool mk = (mask[b * TSEQ + c] != 0);
#pragma unroll
                for (int i = 0; i < 4; i++)
                    if (!mk || c > row0 + i) s[i][j] = -INFINITY;
            }

#pragma unroll
            for (int i = 0; i < 4; i++) {
                float rmax = fmaxf(fmaxf(s[i][0], s[i][1]), fmaxf(s[i][2], s[i][3]));
#pragma unroll
                for (int o = 8; o > 0; o >>= 1)
                    rmax = fmaxf(rmax, __shfl_xor_sync(0xffffffffu, rmax, o));
                const float mnew  = fmaxf(m_i[i], rmax);
                const float alpha = __expf(m_i[i] - mnew);
                m_i[i] = mnew;
                float ls = 0.0f;
#pragma unroll
                for (int j = 0; j < 4; j++) {
                    const float p = __expf(s[i][j] - mnew);
                    s[i][j] = p;
                    ls += p;
                }
#pragma unroll
                for (int o = 8; o > 0; o >>= 1)
                    ls += __shfl_xor_sync(0xffffffffu, ls, o);
                l_i[i] = l_i[i] * alpha + ls;
#pragma unroll
                for (int j = 0; j < 4; j++) o_acc[i][j] *= alpha;
            }

            __syncthreads();
#pragma unroll
            for (int j = 0; j < 4; j++)
#pragma unroll
                for (int i = 0; i < 4; i++)
                    KPs[((tx << 2) + j) * QPAD + (ty << 2) + i] = s[i][j];
            __syncthreads();

#pragma unroll
            for (int kk = 0; kk < 64; kk++) {
                float4 av = *reinterpret_cast<float4*>(&KPs[kk * QPAD + (ty << 2)]);
                float4 bv = *reinterpret_cast<float4*>(&Vs[kk * 64 + (tx << 2)]);
                float a[4] = {av.x, av.y, av.z, av.w};
                float bb[4] = {bv.x, bv.y, bv.z, bv.w};
#pragma unroll
                for (int i = 0; i < 4; i++)
#pragma unroll
                    for (int j = 0; j < 4; j++) o_acc[i][j] += a[i] * bb[j];
            }
        }

#pragma unroll
        for (int i = 0; i < 4; i++) {
            const float inv = 1.0f / l_i[i];
            const int rg = row0 + i;
            float4 o;
            o.x = o_acc[i][0] * inv;
            o.y = o_acc[i][1] * inv;
            o.z = o_acc[i][2] * inv;
            o.w = o_acc[i][3] * inv;
            *reinterpret_cast<float4*>(
                out + (size_t)(b * TSEQ + rg) * DMODEL + h * DHEAD + (tx << 2)) = o;
        }
    }
}

// ---------------------------------------------------------------------------
extern "C" void kernel_launch(void* const* d_in, const int* in_sizes, int n_in,
                              void* d_out, int out_size)
{
    const float* x     = (const float*)d_in[0];
    const float* Wqkv  = (const float*)d_in[1];
    const float* bqkv  = (const float*)d_in[2];
    const float* Wproj = (const float*)d_in[3];
    const float* bproj = (const float*)d_in[4];
    const int*   mask  = (const int*)d_in[5];
    float* out = (float*)d_out;

    float *qkv = nullptr, *attn = nullptr;
    __nv_bfloat16 *xh, *xl, *ah, *al, *wqh, *wql, *wph, *wpl;
    cudaGetSymbolAddress((void**)&qkv,  g_qkv);
    cudaGetSymbolAddress((void**)&attn, g_attn);
    cudaGetSymbolAddress((void**)&xh, g_xh);   cudaGetSymbolAddress((void**)&xl, g_xl);
    cudaGetSymbolAddress((void**)&ah, g_ah);   cudaGetSymbolAddress((void**)&al, g_al);
    cudaGetSymbolAddress((void**)&wqh, g_wqh); cudaGetSymbolAddress((void**)&wql, g_wql);
    cudaGetSymbolAddress((void**)&wph, g_wph); cudaGetSymbolAddress((void**)&wpl, g_wpl);

    cudaFuncSetAttribute(attn_kernel,
                         cudaFuncAttributeMaxDynamicSharedMemorySize, ATTN_SMEM_BYTES);
    cudaFuncSetAttribute(gemm_hmma,
                         cudaFuncAttributeMaxDynamicSharedMemorySize, GEMM_SMEM);

    // Split-convert inputs and weights (weights transposed to [N][K])
    convert_split<<<(MROWS * DMODEL) / 1024, 256>>>(x, xh, xl);
    convert_transpose<<<dim3(QKV_N / 32, DMODEL / 32), dim3(32, 8)>>>(
        Wqkv, wqh, wql, DMODEL, QKV_N);
    convert_transpose<<<dim3(DMODEL / 32, DMODEL / 32), dim3(32, 8)>>>(
        Wproj, wph, wpl, DMODEL, DMODEL);

    // 1) QKV = x @ Wqkv + bqkv  (HMMA split-bf16)
    gemm_hmma<<<dim3(QKV_N / 128, MROWS / 128), 256, GEMM_SMEM>>>(
        xh, xl, wqh, wql, bqkv, qkv, MROWS, QKV_N);

    // 2) Fused causal attention (fp32 SIMT)
    attn_kernel<<<dim3(8, BATCH * NH), 256, ATTN_SMEM_BYTES>>>(qkv, mask, attn);

    // 3) out = attn @ Wproj + bproj
    convert_split<<<(MROWS * DMODEL) / 1024, 256>>>(attn, ah, al);
    gemm_hmma<<<dim3(DMODEL / 128, MROWS / 128), 256, GEMM_SMEM>>>(
        ah, al, wph, wpl, bproj, out, MROWS, DMODEL);
}

// round 4
// speedup vs baseline: 2.2208x; 1.4618x over previous
#include <cuda_runtime.h>
#include <cuda_bf16.h>
#include <math.h>
#include <cstdint>

// Problem constants
#define BATCH 4
#define TSEQ  1024
#define DMODEL 1024
#define NH 16
#define DHEAD 64
#define QKV_N 3072   // 3*DMODEL
#define MROWS 4096   // BATCH*TSEQ
#define KDIM 1024    // K is 1024 for both GEMMs

// ---------------------------------------------------------------------------
// Scratch (device globals: allocation-free)
// ---------------------------------------------------------------------------
__device__ float g_qkv[(size_t)MROWS * QKV_N];    // [B*T, 3D] fp32
__device__ float g_attn[(size_t)MROWS * DMODEL];  // [B*T, D]  fp32
__device__ __nv_bfloat16 g_xh[(size_t)MROWS * DMODEL];
__device__ __nv_bfloat16 g_xl[(size_t)MROWS * DMODEL];
__device__ __nv_bfloat16 g_ah[(size_t)MROWS * DMODEL];
__device__ __nv_bfloat16 g_al[(size_t)MROWS * DMODEL];
__device__ __nv_bfloat16 g_wqh[(size_t)QKV_N * DMODEL];   // Wqkv^T [3072][1024]
__device__ __nv_bfloat16 g_wql[(size_t)QKV_N * DMODEL];
__device__ __nv_bfloat16 g_wph[(size_t)DMODEL * DMODEL];  // Wproj^T [1024][1024]
__device__ __nv_bfloat16 g_wpl[(size_t)DMODEL * DMODEL];

// ---------------------------------------------------------------------------
// PTX helpers (base ISA only — compute_103 virtual arch, no tcgen05)
// ---------------------------------------------------------------------------
__device__ __forceinline__ uint32_t smem_to_u32(const void* p) {
    uint32_t a;
    asm("{ .reg .u64 t; cvta.to.shared.u64 t, %1; cvt.u32.u64 %0, t; }"
        : "=r"(a) : "l"(p));
    return a;
}

#define CP_ASYNC16(smem, gptr) \
    asm volatile("cp.async.cg.shared.global [%0], [%1], 16;" \
        :: "r"(smem), "l"(gptr) : "memory")
#define CP_COMMIT() asm volatile("cp.async.commit_group;" ::: "memory")
#define CP_WAIT(n)  asm volatile("cp.async.wait_group %0;" :: "n"(n) : "memory")

#define LDSM_X4(r0, r1, r2, r3, addr) \
    asm volatile("ldmatrix.sync.aligned.m8n8.x4.shared.b16 {%0,%1,%2,%3}, [%4];" \
        : "=r"(r0), "=r"(r1), "=r"(r2), "=r"(r3) : "r"(addr))

#define MMA16816(c, a, b0, b1) \
    asm volatile("mma.sync.aligned.m16n8k16.row.col.f32.bf16.bf16.f32 " \
        "{%0,%1,%2,%3}, {%4,%5,%6,%7}, {%8,%9}, {%0,%1,%2,%3};" \
        : "+f"((c)[0]), "+f"((c)[1]), "+f"((c)[2]), "+f"((c)[3]) \
        : "r"((a)[0]), "r"((a)[1]), "r"((a)[2]), "r"((a)[3]), \
          "r"(b0), "r"(b1))

// pack two floats to bf16x2 (lo = first arg)
__device__ __forceinline__ uint32_t packbf(float lo, float hi) {
    uint32_t r;
    asm("cvt.rn.bf16x2.f32 %0, %1, %2;" : "=r"(r) : "f"(hi), "f"(lo));
    return r;
}

// ---------------------------------------------------------------------------
// Split-bf16 HMMA GEMM: C = (Ah+Al)[M,K] @ ((Bh+Bl)[N,K])^T + bias
// CTA 128x128, K-tile 32, 2-stage cp.async pipeline, 2 CTAs/SM, 8 warps (2x4).
// smem per matrix per stage: 128 rows x 40 bf16 (80B padded rows) = 10240B.
// ---------------------------------------------------------------------------
#define MATB   10240
#define STAGEB 40960
#define GEMM_SMEM (2 * STAGEB)

__global__ __launch_bounds__(256, 2) void gemm_hmma(
    const __nv_bfloat16* __restrict__ Ah, const __nv_bfloat16* __restrict__ Al,
    const __nv_bfloat16* __restrict__ Bh, const __nv_bfloat16* __restrict__ Bl,
    const float* __restrict__ bias, float* __restrict__ C,
    int M, int Ntot)
{
    extern __shared__ char dsm[];
    const uint32_t sb = smem_to_u32(dsm);

    const int t    = threadIdx.x;
    const int lane = t & 31;
    const int wid  = t >> 5;
    const int wm   = wid >> 2;
    const int wn   = wid & 3;
    const int bm   = blockIdx.y << 7;
    const int bn   = blockIdx.x << 7;

    const int row0 = t >> 2;
    const int ch0  = t & 3;
    uint32_t soff[8];
    const __nv_bfloat16* gp[8];
    {
        const __nv_bfloat16* bases[4] = {Ah, Al, Bh, Bl};
        const int rb[4] = {bm, bm, bn, bn};
#pragma unroll
        for (int m = 0; m < 4; m++)
#pragma unroll
            for (int h = 0; h < 2; h++) {
                const int r = row0 + h * 64;
                soff[m * 2 + h] = (uint32_t)(m * MATB + r * 80 + ch0 * 16);
                gp[m * 2 + h]   = bases[m] + (size_t)(rb[m] + r) * KDIM + ch0 * 8;
            }
    }

    const uint32_t a_base = (uint32_t)((wm * 64 + (lane & 15)) * 80 + (lane >> 4) * 16);
    const uint32_t b_base = (uint32_t)(2 * MATB +
        (wn * 32 + (lane & 7) + ((lane >> 4) << 3)) * 80 + ((lane >> 3) & 1) * 16);

    float acc[4][4][4];
#pragma unroll
    for (int mi = 0; mi < 4; mi++)
#pragma unroll
        for (int ni = 0; ni < 4; ni++)
#pragma unroll
            for (int e = 0; e < 4; e++) acc[mi][ni][e] = 0.0f;

    const int NT = KDIM / 32;

    // prologue: stage 0
    {
#pragma unroll
        for (int i = 0; i < 8; i++) CP_ASYNC16(sb + soff[i], gp[i]);
        CP_COMMIT();
    }

#pragma unroll 1
    for (int kt = 0; kt < NT; kt++) {
        // issue next stage (buffer freed by the end-of-loop barrier)
        if (kt + 1 < NT) {
            const uint32_t st = sb + (uint32_t)((kt + 1) & 1) * STAGEB;
            const int ko = (kt + 1) * 32;
#pragma unroll
            for (int i = 0; i < 8; i++) CP_ASYNC16(st + soff[i], gp[i] + ko);
        }
        CP_COMMIT();
        CP_WAIT(1);
        __syncthreads();

        const uint32_t stg = sb + (uint32_t)(kt & 1) * STAGEB;
#pragma unroll
        for (int ks = 0; ks < 2; ks++) {
            const uint32_t ko = (uint32_t)(ks * 32);
            uint32_t ah[4][4], al[4][4];
#pragma unroll
            for (int mi = 0; mi < 4; mi++) {
                LDSM_X4(ah[mi][0], ah[mi][1], ah[mi][2], ah[mi][3],
                        stg + a_base + (uint32_t)(mi * 1280) + ko);
                LDSM_X4(al[mi][0], al[mi][1], al[mi][2], al[mi][3],
                        stg + MATB + a_base + (uint32_t)(mi * 1280) + ko);
            }
            uint32_t rbh[2][4], rbl[2][4];
#pragma unroll
            for (int g = 0; g < 2; g++) {
                LDSM_X4(rbh[g][0], rbh[g][1], rbh[g][2], rbh[g][3],
                        stg + b_base + (uint32_t)(g * 1280) + ko);
                LDSM_X4(rbl[g][0], rbl[g][1], rbl[g][2], rbl[g][3],
                        stg + MATB + b_base + (uint32_t)(g * 1280) + ko);
            }
#pragma unroll
            for (int mi = 0; mi < 4; mi++)
#pragma unroll
                for (int ni = 0; ni < 4; ni++) {
                    const int g = ni >> 1, u = (ni & 1) * 2;
                    MMA16816(acc[mi][ni], ah[mi], rbh[g][u], rbh[g][u + 1]);
                    MMA16816(acc[mi][ni], ah[mi], rbl[g][u], rbl[g][u + 1]);
                    MMA16816(acc[mi][ni], al[mi], rbh[g][u], rbh[g][u + 1]);
                }
        }
        __syncthreads();   // readers done before next-iter overwrite
    }

    const int er = bm + wm * 64 + (lane >> 2);
    const int ec = bn + wn * 32 + (lane & 3) * 2;
#pragma unroll
    for (int ni = 0; ni < 4; ni++) {
        const int col = ec + ni * 8;
        const float2 bv = *reinterpret_cast<const float2*>(bias + col);
#pragma unroll
        for (int mi = 0; mi < 4; mi++) {
            const int r0 = er + mi * 16;
            float2 o0, o1;
            o0.x = acc[mi][ni][0] + bv.x;
            o0.y = acc[mi][ni][1] + bv.y;
            o1.x = acc[mi][ni][2] + bv.x;
            o1.y = acc[mi][ni][3] + bv.y;
            *reinterpret_cast<float2*>(C + (size_t)r0 * Ntot + col) = o0;
            *reinterpret_cast<float2*>(C + (size_t)(r0 + 8) * Ntot + col) = o1;
        }
    }
}

// ---------------------------------------------------------------------------
// HMMA flash attention, split-bf16 3-product for S=QK^T and O=PV.
// Grid (4, B*H), 2 passes: q-tiles {7-bx, bx} (BQ=128). 8 warps x 16 rows.
// smem (144B row stride, conflict-free ldmatrix):
//   Qh[128], Ql[128], Kh[64], Kl[64], Vth[64](=[dh][key]), Vtl[64], msk[64]f
// ---------------------------------------------------------------------------
#define ASTR 144
#define QH_OFF 0
#define QL_OFF 18432
#define KH_OFF 36864
#define KL_OFF 46080
#define VTH_OFF 55296
#define VTL_OFF 64512
#define MSK_OFF 73728
#define ATTN_SMEM (73728 + 256)

__global__ __launch_bounds__(256, 2) void attn_hmma(
    const float* __restrict__ qkv, const int* __restrict__ mask,
    float* __restrict__ out)
{
    extern __shared__ char smc[];
    const uint32_t sb = smem_to_u32(smc);

    const int t    = threadIdx.x;
    const int lane = t & 31;
    const int w    = t >> 5;
    const int bh   = blockIdx.y;
    const int b    = bh >> 4;
    const int h    = bh & 15;
    const float* qb = qkv + (size_t)b * TSEQ * QKV_N;
    float* msk_s = (float*)(smc + MSK_OFF);

    // warp-invariant ldsm bases
    const uint32_t aq_base = sb + QH_OFF +
        (uint32_t)((16 * w + (lane & 15)) * ASTR + (lane >> 4) * 16);
    const uint32_t bk_base = sb + KH_OFF +
        (uint32_t)(((lane & 7) + ((lane >> 4) << 3)) * ASTR + ((lane >> 3) & 1) * 16);
    const uint32_t bv_base = sb + VTH_OFF +
        (uint32_t)(((lane & 7) + ((lane >> 4) << 3)) * ASTR + ((lane >> 3) & 1) * 16);

#pragma unroll 1
    for (int pass = 0; pass < 2; pass++) {
        const int qt = pass ? (int)blockIdx.x : 7 - (int)blockIdx.x;
        __syncthreads();   // previous pass readers of Q done

        // ---- load Q tile 128x64 fp32 -> hi/lo bf16, pre-scaled ----
#pragma unroll
        for (int p = 0; p < 8; p++) {
            const int idx = t + (p << 8);
            const int row = idx >> 4;
            const int c4  = idx & 15;
            float4 v = *reinterpret_cast<const float4*>(
                qb + (size_t)(qt * 128 + row) * QKV_N + h * DHEAD + c4 * 4);
            v.x *= 0.125f; v.y *= 0.125f; v.z *= 0.125f; v.w *= 0.125f;
            const float hx = __bfloat162float(__float2bfloat16(v.x));
            const float hy = __bfloat162float(__float2bfloat16(v.y));
            const float hz = __bfloat162float(__float2bfloat16(v.z));
            const float hw = __bfloat162float(__float2bfloat16(v.w));
            uint2 uh, ul;
            uh.x = packbf(v.x, v.y);       uh.y = packbf(v.z, v.w);
            ul.x = packbf(v.x - hx, v.y - hy); ul.y = packbf(v.z - hz, v.w - hw);
            const int o = row * ASTR + c4 * 8;
            *reinterpret_cast<uint2*>(smc + QH_OFF + o) = uh;
            *reinterpret_cast<uint2*>(smc + QL_OFF + o) = ul;
        }

        float m0 = -1e30f, m1 = -1e30f, l0 = 0.0f, l1 = 0.0f;
        float of[8][4];
#pragma unroll
        for (int j = 0; j < 8; j++)
#pragma unroll
            for (int e = 0; e < 4; e++) of[j][e] = 0.0f;

        const int qrow_w = qt * 128 + 16 * w;
        const int r0g = qrow_w + (lane >> 2);

        const int kmax = 2 * qt + 1;
#pragma unroll 1
        for (int kt = 0; kt <= kmax; kt++) {
            __syncthreads();   // previous compute done; Q stores visible later

            // ---- load K and V tiles (64x64 fp32 each) ----
#pragma unroll
            for (int p = 0; p < 4; p++) {
                const int idx = t + (p << 8);
                const int row = idx >> 4;
                const int c4  = idx & 15;
                const size_t gro = (size_t)(kt * 64 + row) * QKV_N + h * DHEAD + c4 * 4;
                // K -> [key][dh] hi/lo
                const float4 kv = *reinterpret_cast<const float4*>(qb + DMODEL + gro);
                const float khx = __bfloat162float(__float2bfloat16(kv.x));
                const float khy = __bfloat162float(__float2bfloat16(kv.y));
                const float khz = __bfloat162float(__float2bfloat16(kv.z));
                const float khw = __bfloat162float(__float2bfloat16(kv.w));
                uint2 uh, ul;
                uh.x = packbf(kv.x, kv.y);          uh.y = packbf(kv.z, kv.w);
                ul.x = packbf(kv.x - khx, kv.y - khy); ul.y = packbf(kv.z - khz, kv.w - khw);
                const int o = row * ASTR + c4 * 8;
                *reinterpret_cast<uint2*>(smc + KH_OFF + o) = uh;
                *reinterpret_cast<uint2*>(smc + KL_OFF + o) = ul;
                // V -> transposed [dh][key] hi/lo (scalar bf16 stores)
                const float4 vv = *reinterpret_cast<const float4*>(qb + 2 * DMODEL + gro);
                const float ve[4] = {vv.x, vv.y, vv.z, vv.w};
#pragma unroll
                for (int e = 0; e < 4; e++) {
                    const int dh = c4 * 4 + e;
                    const __nv_bfloat16 vh = __float2bfloat16(ve[e]);
                    *reinterpret_cast<__nv_bfloat16*>(smc + VTH_OFF + dh * ASTR + row * 2) = vh;
                    *reinterpret_cast<__nv_bfloat16*>(smc + VTL_OFF + dh * ASTR + row * 2) =
                        __float2bfloat16(ve[e] - __bfloat162float(vh));
                }
            }
            if (t < 64)
                msk_s[t] = (mask[b * TSEQ + kt * 64 + t] != 0) ? 0.0f : -1e30f;
            __syncthreads();

            // ---- S = Q @ K^T (split-bf16, 3-product) ----
            float s[8][4];
#pragma unroll
            for (int j = 0; j < 8; j++)
#pragma unroll
                for (int e = 0; e < 4; e++) s[j][e] = 0.0f;

#pragma unroll
            for (int ks = 0; ks < 4; ks++) {
                uint32_t aqh[4], aql[4];
                LDSM_X4(aqh[0], aqh[1], aqh[2], aqh[3], aq_base + ks * 32);
                LDSM_X4(aql[0], aql[1], aql[2], aql[3],
                        aq_base + (QL_OFF - QH_OFF) + ks * 32);
#pragma unroll
                for (int g = 0; g < 4; g++) {
                    uint32_t bkh[4], bkl[4];
                    LDSM_X4(bkh[0], bkh[1], bkh[2], bkh[3],
                            bk_base + g * (16 * ASTR) + ks * 32);
                    LDSM_X4(bkl[0], bkl[1], bkl[2], bkl[3],
                            bk_base + (KL_OFF - KH_OFF) + g * (16 * ASTR) + ks * 32);
                    MMA16816(s[2 * g],     aqh, bkh[0], bkh[1]);
                    MMA16816(s[2 * g],     aqh, bkl[0], bkl[1]);
                    MMA16816(s[2 * g],     aql, bkh[0], bkh[1]);
                    MMA16816(s[2 * g + 1], aqh, bkh[2], bkh[3]);
                    MMA16816(s[2 * g + 1], aqh, bkl[2], bkl[3]);
                    MMA16816(s[2 * g + 1], aql, bkh[2], bkh[3]);
                }
            }

            // ---- mask + causal ----
            const int lc = 2 * (lane & 3);
#pragma unroll
            for (int j = 0; j < 8; j++) {
                const float mj0 = msk_s[j * 8 + lc];
                const float mj1 = msk_s[j * 8 + lc + 1];
                s[j][0] += mj0; s[j][1] += mj1;
                s[j][2] += mj0; s[j][3] += mj1;
            }
            if (kt * 64 + 63 > qrow_w) {
                const int r1g = r0g + 8;
#pragma unroll
                for (int j = 0; j < 8; j++) {
                    const int c0 = kt * 64 + j * 8 + lc;
                    if (c0     > r0g) s[j][0] = -1e30f;
                    if (c0 + 1 > r0g) s[j][1] = -1e30f;
                    if (c0     > r1g) s[j][2] = -1e30f;
                    if (c0 + 1 > r1g) s[j][3] = -1e30f;
                }
            }

            // ---- online softmax (rows are warp-local: lanes xor 1,2) ----
            float rm0 = -1e30f, rm1 = -1e30f;
#pragma unroll
            for (int j = 0; j < 8; j++) {
                rm0 = fmaxf(rm0, fmaxf(s[j][0], s[j][1]));
                rm1 = fmaxf(rm1, fmaxf(s[j][2], s[j][3]));
            }
            rm0 = fmaxf(rm0, __shfl_xor_sync(0xffffffffu, rm0, 1));
            rm0 = fmaxf(rm0, __shfl_xor_sync(0xffffffffu, rm0, 2));
            rm1 = fmaxf(rm1, __shfl_xor_sync(0xffffffffu, rm1, 1));
            rm1 = fmaxf(rm1, __shfl_xor_sync(0xffffffffu, rm1, 2));
            const float mn0 = fmaxf(m0, rm0), mn1 = fmaxf(m1, rm1);
            const float al0 = __expf(m0 - mn0), al1 = __expf(m1 - mn1);
            m0 = mn0; m1 = mn1;
            float ls0 = 0.0f, ls1 = 0.0f;
#pragma unroll
            for (int j = 0; j < 8; j++) {
                s[j][0] = __expf(s[j][0] - mn0); ls0 += s[j][0];
                s[j][1] = __expf(s[j][1] - mn0); ls0 += s[j][1];
                s[j][2] = __expf(s[j][2] - mn1); ls1 += s[j][2];
                s[j][3] = __expf(s[j][3] - mn1); ls1 += s[j][3];
            }
            ls0 += __shfl_xor_sync(0xffffffffu, ls0, 1);
            ls0 += __shfl_xor_sync(0xffffffffu, ls0, 2);
            ls1 += __shfl_xor_sync(0xffffffffu, ls1, 1);
            ls1 += __shfl_xor_sync(0xffffffffu, ls1, 2);
            l0 = l0 * al0 + ls0;
            l1 = l1 * al1 + ls1;
#pragma unroll
            for (int j = 0; j < 8; j++) {
                of[j][0] *= al0; of[j][1] *= al0;
                of[j][2] *= al1; of[j][3] *= al1;
            }

            // ---- O += P @ V (P split hi/lo from C-frags, V split hi/lo) ----
#pragma unroll
            for (int kt2 = 0; kt2 < 4; kt2++) {
                uint32_t aph[4], apl[4];
                {
                    const float* p0 = s[2 * kt2];
                    const float* p1 = s[2 * kt2 + 1];
                    float hl[8];
#pragma unroll
                    for (int e = 0; e < 4; e++) {
                        hl[e]     = p0[e] - __bfloat162float(__float2bfloat16(p0[e]));
                        hl[4 + e] = p1[e] - __bfloat162float(__float2bfloat16(p1[e]));
                    }
                    aph[0] = packbf(p0[0], p0[1]); aph[1] = packbf(p0[2], p0[3]);
                    aph[2] = packbf(p1[0], p1[1]); aph[3] = packbf(p1[2], p1[3]);
                    apl[0] = packbf(hl[0], hl[1]); apl[1] = packbf(hl[2], hl[3]);
                    apl[2] = packbf(hl[4], hl[5]); apl[3] = packbf(hl[6], hl[7]);
                }
#pragma unroll
                for (int g = 0; g < 4; g++) {
                    uint32_t bvh[4], bvl[4];
                    LDSM_X4(bvh[0], bvh[1], bvh[2], bvh[3],
                            bv_base + g * (16 * ASTR) + kt2 * 32);
                    LDSM_X4(bvl[0], bvl[1], bvl[2], bvl[3],
                            bv_base + (VTL_OFF - VTH_OFF) + g * (16 * ASTR) + kt2 * 32);
                    MMA16816(of[2 * g],     aph, bvh[0], bvh[1]);
                    MMA16816(of[2 * g],     aph, bvl[0], bvl[1]);
                    MMA16816(of[2 * g],     apl, bvh[0], bvh[1]);
                    MMA16816(of[2 * g + 1], aph, bvh[2], bvh[3]);
                    MMA16816(of[2 * g + 1], aph, bvl[2], bvl[3]);
                    MMA16816(of[2 * g + 1], apl, bvh[2], bvh[3]);
                }
            }
        }

        // ---- normalize + store to [B*T, D], col = h*64+dh ----
        const float inv0 = 1.0f / l0, inv1 = 1.0f / l1;
        float* ob = out + ((size_t)(b * TSEQ) + r0g) * DMODEL + h * DHEAD + 2 * (lane & 3);
#pragma unroll
        for (int j = 0; j < 8; j++) {
            float2 v0, v1;
            v0.x = of[j][0] * inv0; v0.y = of[j][1] * inv0;
            v1.x = of[j][2] * inv1; v1.y = of[j][3] * inv1;
            *reinterpret_cast<float2*>(ob + j * 8) = v0;
            *reinterpret_cast<float2*>(ob + (size_t)8 * DMODEL + j * 8) = v1;
        }
    }
}

// ---------------------------------------------------------------------------
// fp32 -> (bf16 hi, bf16 lo) elementwise split, 4 elems/thread
// ---------------------------------------------------------------------------
__global__ __launch_bounds__(256) void convert_split(
    const float* __restrict__ A, __nv_bfloat16* __restrict__ H,
    __nv_bfloat16* __restrict__ L)
{
    const int i = blockIdx.x * blockDim.x + threadIdx.x;
    const float4 v = reinterpret_cast<const float4*>(A)[i];
    __nv_bfloat16 h0 = __float2bfloat16(v.x), h1 = __float2bfloat16(v.y);
    __nv_bfloat16 h2 = __float2bfloat16(v.z), h3 = __float2bfloat16(v.w);
    __nv_bfloat16 l0 = __float2bfloat16(v.x - __bfloat162float(h0));
    __nv_bfloat16 l1 = __float2bfloat16(v.y - __bfloat162float(h1));
    __nv_bfloat16 l2 = __float2bfloat16(v.z - __bfloat162float(h2));
    __nv_bfloat16 l3 = __float2bfloat16(v.w - __bfloat162float(h3));
    reinterpret_cast<__nv_bfloat162*>(H)[2 * i + 0] = __halves2bfloat162(h0, h1);
    reinterpret_cast<__nv_bfloat162*>(H)[2 * i + 1] = __halves2bfloat162(h2, h3);
    reinterpret_cast<__nv_bfloat162*>(L)[2 * i + 0] = __halves2bfloat162(l0, l1);
    reinterpret_cast<__nv_bfloat162*>(L)[2 * i + 1] = __halves2bfloat162(l2, l3);
}

// ---------------------------------------------------------------------------
// W[K][N] fp32 -> Wt_hi/lo[N][K] bf16 (transpose + split), block (32,8)
// ---------------------------------------------------------------------------
__global__ __launch_bounds__(256) void convert_transpose(
    const float* __restrict__ W, __nv_bfloat16* __restrict__ Th,
    __nv_bfloat16* __restrict__ Tl, int K, int N)
{
    __shared__ float tile[32][33];
    const int tx = threadIdx.x, ty = threadIdx.y;
    const int n0 = blockIdx.x * 32, k0 = blockIdx.y * 32;
#pragma unroll
    for (int i = 0; i < 4; i++)
        tile[ty + i * 8][tx] = W[(size_t)(k0 + ty + i * 8) * N + n0 + tx];
    __syncthreads();
#pragma unroll
    for (int i = 0; i < 4; i++) {
        const float v = tile[tx][ty + i * 8];
        const __nv_bfloat16 h = __float2bfloat16(v);
        const __nv_bfloat16 l = __float2bfloat16(v - __bfloat162float(h));
        const size_t o = (size_t)(n0 + ty + i * 8) * K + k0 + tx;
        Th[o] = h;
        Tl[o] = l;
    }
}

// ---------------------------------------------------------------------------
extern "C" void kernel_launch(void* const* d_in, const int* in_sizes, int n_in,
                              void* d_out, int out_size)
{
    const float* x     = (const float*)d_in[0];
    const float* Wqkv  = (const float*)d_in[1];
    const float* bqkv  = (const float*)d_in[2];
    const float* Wproj = (const float*)d_in[3];
    const float* bproj = (const float*)d_in[4];
    const int*   mask  = (const int*)d_in[5];
    float* out = (float*)d_out;

    float *qkv = nullptr, *attn = nullptr;
    __nv_bfloat16 *xh, *xl, *ah, *al, *wqh, *wql, *wph, *wpl;
    cudaGetSymbolAddress((void**)&qkv,  g_qkv);
    cudaGetSymbolAddress((void**)&attn, g_attn);
    cudaGetSymbolAddress((void**)&xh, g_xh);   cudaGetSymbolAddress((void**)&xl, g_xl);
    cudaGetSymbolAddress((void**)&ah, g_ah);   cudaGetSymbolAddress((void**)&al, g_al);
    cudaGetSymbolAddress((void**)&wqh, g_wqh); cudaGetSymbolAddress((void**)&wql, g_wql);
    cudaGetSymbolAddress((void**)&wph, g_wph); cudaGetSymbolAddress((void**)&wpl, g_wpl);

    cudaFuncSetAttribute(attn_hmma,
                         cudaFuncAttributeMaxDynamicSharedMemorySize, ATTN_SMEM);
    cudaFuncSetAttribute(gemm_hmma,
                         cudaFuncAttributeMaxDynamicSharedMemorySize, GEMM_SMEM);

    // Split-convert inputs and weights (weights transposed to [N][K])
    convert_split<<<(MROWS * DMODEL) / 1024, 256>>>(x, xh, xl);
    convert_transpose<<<dim3(QKV_N / 32, DMODEL / 32), dim3(32, 8)>>>(
        Wqkv, wqh, wql, DMODEL, QKV_N);
    convert_transpose<<<dim3(DMODEL / 32, DMODEL / 32), dim3(32, 8)>>>(
        Wproj, wph, wpl, DMODEL, DMODEL);

    // 1) QKV = x @ Wqkv + bqkv  (HMMA split-bf16)
    gemm_hmma<<<dim3(QKV_N / 128, MROWS / 128), 256, GEMM_SMEM>>>(
        xh, xl, wqh, wql, bqkv, qkv, MROWS, QKV_N);

    // 2) Fused causal attention (HMMA split-bf16)
    attn_hmma<<<dim3(4, BATCH * NH), 256, ATTN_SMEM>>>(qkv, mask, attn);

    // 3) out = attn @ Wproj + bproj
    convert_split<<<(MROWS * DMODEL) / 1024, 256>>>(attn, ah, al);
    gemm_hmma<<<dim3(DMODEL / 128, MROWS / 128), 256, GEMM_SMEM>>>(
        ah, al, wph, wpl, bproj, out, MROWS, DMODEL);
}

// round 5
// speedup vs baseline: 2.3143x; 1.0421x over previous
#include <cuda_runtime.h>
#include <cuda_bf16.h>
#include <math.h>
#include <cstdint>

// Problem constants
#define BATCH 4
#define TSEQ  1024
#define DMODEL 1024
#define NH 16
#define DHEAD 64
#define QKV_N 3072   // 3*DMODEL
#define MROWS 4096   // BATCH*TSEQ
#define KDIM 1024    // K is 1024 for both GEMMs

// ---------------------------------------------------------------------------
// Scratch (device globals: allocation-free)
// ---------------------------------------------------------------------------
__device__ float g_qkv[(size_t)MROWS * QKV_N];    // [B*T, 3D] fp32
__device__ __nv_bfloat16 g_xh[(size_t)MROWS * DMODEL];
__device__ __nv_bfloat16 g_xl[(size_t)MROWS * DMODEL];
__device__ __nv_bfloat16 g_ah[(size_t)MROWS * DMODEL];   // attention out hi
__device__ __nv_bfloat16 g_al[(size_t)MROWS * DMODEL];   // attention out lo
__device__ __nv_bfloat16 g_wqh[(size_t)QKV_N * DMODEL];  // Wqkv^T [3072][1024]
__device__ __nv_bfloat16 g_wql[(size_t)QKV_N * DMODEL];
__device__ __nv_bfloat16 g_wph[(size_t)DMODEL * DMODEL]; // Wproj^T [1024][1024]
__device__ __nv_bfloat16 g_wpl[(size_t)DMODEL * DMODEL];

// ---------------------------------------------------------------------------
// PTX helpers (base ISA only — compute_103 virtual arch, no tcgen05)
// ---------------------------------------------------------------------------
__device__ __forceinline__ uint32_t smem_to_u32(const void* p) {
    uint32_t a;
    asm("{ .reg .u64 t; cvta.to.shared.u64 t, %1; cvt.u32.u64 %0, t; }"
        : "=r"(a) : "l"(p));
    return a;
}

#define CP_ASYNC16(smem, gptr) \
    asm volatile("cp.async.cg.shared.global [%0], [%1], 16;" \
        :: "r"(smem), "l"(gptr) : "memory")
#define CP_COMMIT() asm volatile("cp.async.commit_group;" ::: "memory")
#define CP_WAIT(n)  asm volatile("cp.async.wait_group %0;" :: "n"(n) : "memory")

#define LDSM_X4(r0, r1, r2, r3, addr) \
    asm volatile("ldmatrix.sync.aligned.m8n8.x4.shared.b16 {%0,%1,%2,%3}, [%4];" \
        : "=r"(r0), "=r"(r1), "=r"(r2), "=r"(r3) : "r"(addr))

#define MMA16816(c, a, b0, b1) \
    asm volatile("mma.sync.aligned.m16n8k16.row.col.f32.bf16.bf16.f32 " \
        "{%0,%1,%2,%3}, {%4,%5,%6,%7}, {%8,%9}, {%0,%1,%2,%3};" \
        : "+f"((c)[0]), "+f"((c)[1]), "+f"((c)[2]), "+f"((c)[3]) \
        : "r"((a)[0]), "r"((a)[1]), "r"((a)[2]), "r"((a)[3]), \
          "r"(b0), "r"(b1))

// pack two floats to bf16x2 (lo addr half = first arg)
__device__ __forceinline__ uint32_t packbf(float lo, float hi) {
    uint32_t r;
    asm("cvt.rn.bf16x2.f32 %0, %1, %2;" : "=r"(r) : "f"(hi), "f"(lo));
    return r;
}

// ---------------------------------------------------------------------------
// Split-bf16 HMMA GEMM v3: C = (Ah+Al)[M,K] @ ((Bh+Bl)[N,K])^T + bias
// CTA 128x128, K-tile 32, 2-stage cp.async, 2 CTAs/SM.
// 128 threads = 4 warps in 2x2 grid, warp tile 64x64 (high MMA:LDSM ratio).
// smem per matrix per stage: 128 rows x 80B = 10240B.
// ---------------------------------------------------------------------------
#define MATB   10240
#define STAGEB 40960
#define GEMM_SMEM (2 * STAGEB)

__global__ __launch_bounds__(128, 2) void gemm_hmma(
    const __nv_bfloat16* __restrict__ Ah, const __nv_bfloat16* __restrict__ Al,
    const __nv_bfloat16* __restrict__ Bh, const __nv_bfloat16* __restrict__ Bl,
    const float* __restrict__ bias, float* __restrict__ C,
    int M, int Ntot)
{
    extern __shared__ char dsm[];
    const uint32_t sb = smem_to_u32(dsm);

    const int t    = threadIdx.x;
    const int lane = t & 31;
    const int wid  = t >> 5;
    const int wm   = wid >> 1;          // 0..1 (64-row slab)
    const int wn   = wid & 1;           // 0..1 (64-col slab)
    const int bm   = blockIdx.y << 7;
    const int bn   = blockIdx.x << 7;

    // ---- cp.async plan: 4 matrices x 512 chunks(16B) / 128 thr = 16/thread
    const int rbase = t >> 2;       // 0..31
    const int ch0   = t & 3;        // 0..3 (16B chunk in 64B k-slab)
    uint32_t soff[16];
    const __nv_bfloat16* gp[16];
    {
        const __nv_bfloat16* bases[4] = {Ah, Al, Bh, Bl};
        const int rb[4] = {bm, bm, bn, bn};
#pragma unroll
        for (int m = 0; m < 4; m++)
#pragma unroll
            for (int hh = 0; hh < 4; hh++) {
                const int r = rbase + hh * 32;
                soff[m * 4 + hh] = (uint32_t)(m * MATB + r * 80 + ch0 * 16);
                gp[m * 4 + hh]   = bases[m] + (size_t)(rb[m] + r) * KDIM + ch0 * 8;
            }
    }

    const uint32_t a_base = (uint32_t)((wm * 64 + (lane & 15)) * 80 + (lane >> 4) * 16);
    const uint32_t b_base = (uint32_t)(2 * MATB +
        (wn * 64 + (lane & 7) + ((lane >> 4) << 3)) * 80 + ((lane >> 3) & 1) * 16);

    float acc[4][8][4];
#pragma unroll
    for (int mi = 0; mi < 4; mi++)
#pragma unroll
        for (int ni = 0; ni < 8; ni++)
#pragma unroll
            for (int e = 0; e < 4; e++) acc[mi][ni][e] = 0.0f;

    const int NT = KDIM / 32;

    // prologue: stage 0
#pragma unroll
    for (int i = 0; i < 16; i++) CP_ASYNC16(sb + soff[i], gp[i]);
    CP_COMMIT();

#pragma unroll 1
    for (int kt = 0; kt < NT; kt++) {
        if (kt + 1 < NT) {
            const uint32_t st = sb + (uint32_t)((kt + 1) & 1) * STAGEB;
            const int ko = (kt + 1) * 32;
#pragma unroll
            for (int i = 0; i < 16; i++) CP_ASYNC16(st + soff[i], gp[i] + ko);
        }
        CP_COMMIT();
        CP_WAIT(1);
        __syncthreads();

        const uint32_t stg = sb + (uint32_t)(kt & 1) * STAGEB;
#pragma unroll
        for (int ks = 0; ks < 2; ks++) {
            const uint32_t ko = (uint32_t)(ks * 32);
            uint32_t ah[4][4], al[4][4];
#pragma unroll
            for (int mi = 0; mi < 4; mi++) {
                LDSM_X4(ah[mi][0], ah[mi][1], ah[mi][2], ah[mi][3],
                        stg + a_base + (uint32_t)(mi * 1280) + ko);
                LDSM_X4(al[mi][0], al[mi][1], al[mi][2], al[mi][3],
                        stg + MATB + a_base + (uint32_t)(mi * 1280) + ko);
            }
            uint32_t rbh[4][4], rbl[4][4];
#pragma unroll
            for (int g = 0; g < 4; g++) {
                LDSM_X4(rbh[g][0], rbh[g][1], rbh[g][2], rbh[g][3],
                        stg + b_base + (uint32_t)(g * 1280) + ko);
                LDSM_X4(rbl[g][0], rbl[g][1], rbl[g][2], rbl[g][3],
                        stg + MATB + b_base + (uint32_t)(g * 1280) + ko);
            }
#pragma unroll
            for (int mi = 0; mi < 4; mi++)
#pragma unroll
                for (int ni = 0; ni < 8; ni++) {
                    const int g = ni >> 1, u = (ni & 1) * 2;
                    MMA16816(acc[mi][ni], ah[mi], rbh[g][u], rbh[g][u + 1]);
                    MMA16816(acc[mi][ni], ah[mi], rbl[g][u], rbl[g][u + 1]);
                    MMA16816(acc[mi][ni], al[mi], rbh[g][u], rbh[g][u + 1]);
                }
        }
        __syncthreads();
    }

    // ---- epilogue: add bias, store fp32 ----
    const int er = bm + wm * 64 + (lane >> 2);
    const int ec = bn + wn * 64 + (lane & 3) * 2;
#pragma unroll
    for (int ni = 0; ni < 8; ni++) {
        const int col = ec + ni * 8;
        const float2 bv = *reinterpret_cast<const float2*>(bias + col);
#pragma unroll
        for (int mi = 0; mi < 4; mi++) {
            const int r0 = er + mi * 16;
            float2 o0, o1;
            o0.x = acc[mi][ni][0] + bv.x;
            o0.y = acc[mi][ni][1] + bv.y;
            o1.x = acc[mi][ni][2] + bv.x;
            o1.y = acc[mi][ni][3] + bv.y;
            *reinterpret_cast<float2*>(C + (size_t)r0 * Ntot + col) = o0;
            *reinterpret_cast<float2*>(C + (size_t)(r0 + 8) * Ntot + col) = o1;
        }
    }
}

// ---------------------------------------------------------------------------
// HMMA flash attention, split-bf16 3-product for S=QK^T and O=PV.
// Grid (4, B*H), 2 passes: q-tiles {7-bx, bx} (BQ=128). 8 warps x 16 rows.
// Output written directly as bf16 hi/lo (feeds proj GEMM, no convert pass).
// ---------------------------------------------------------------------------
#define ASTR 144
#define QH_OFF 0
#define QL_OFF 18432
#define KH_OFF 36864
#define KL_OFF 46080
#define VTH_OFF 55296
#define VTL_OFF 64512
#define MSK_OFF 73728
#define ATTN_SMEM (73728 + 256)

__global__ __launch_bounds__(256, 2) void attn_hmma(
    const float* __restrict__ qkv, const int* __restrict__ mask,
    __nv_bfloat16* __restrict__ outh, __nv_bfloat16* __restrict__ outl)
{
    extern __shared__ char smc[];
    const uint32_t sb = smem_to_u32(smc);

    const int t    = threadIdx.x;
    const int lane = t & 31;
    const int w    = t >> 5;
    const int bh   = blockIdx.y;
    const int b    = bh >> 4;
    const int h    = bh & 15;
    const float* qb = qkv + (size_t)b * TSEQ * QKV_N;
    float* msk_s = (float*)(smc + MSK_OFF);

    const uint32_t aq_base = sb + QH_OFF +
        (uint32_t)((16 * w + (lane & 15)) * ASTR + (lane >> 4) * 16);
    const uint32_t bk_base = sb + KH_OFF +
        (uint32_t)(((lane & 7) + ((lane >> 4) << 3)) * ASTR + ((lane >> 3) & 1) * 16);
    const uint32_t bv_base = sb + VTH_OFF +
        (uint32_t)(((lane & 7) + ((lane >> 4) << 3)) * ASTR + ((lane >> 3) & 1) * 16);

#pragma unroll 1
    for (int pass = 0; pass < 2; pass++) {
        const int qt = pass ? (int)blockIdx.x : 7 - (int)blockIdx.x;
        __syncthreads();

        // ---- load Q tile 128x64 fp32 -> hi/lo bf16, pre-scaled ----
#pragma unroll
        for (int p = 0; p < 8; p++) {
            const int idx = t + (p << 8);
            const int row = idx >> 4;
            const int c4  = idx & 15;
            float4 v = *reinterpret_cast<const float4*>(
                qb + (size_t)(qt * 128 + row) * QKV_N + h * DHEAD + c4 * 4);
            v.x *= 0.125f; v.y *= 0.125f; v.z *= 0.125f; v.w *= 0.125f;
            const float hx = __bfloat162float(__float2bfloat16(v.x));
            const float hy = __bfloat162float(__float2bfloat16(v.y));
            const float hz = __bfloat162float(__float2bfloat16(v.z));
            const float hw = __bfloat162float(__float2bfloat16(v.w));
            uint2 uh, ul;
            uh.x = packbf(v.x, v.y);       uh.y = packbf(v.z, v.w);
            ul.x = packbf(v.x - hx, v.y - hy); ul.y = packbf(v.z - hz, v.w - hw);
            const int o = row * ASTR + c4 * 8;
            *reinterpret_cast<uint2*>(smc + QH_OFF + o) = uh;
            *reinterpret_cast<uint2*>(smc + QL_OFF + o) = ul;
        }

        float m0 = -1e30f, m1 = -1e30f, l0 = 0.0f, l1 = 0.0f;
        float of[8][4];
#pragma unroll
        for (int j = 0; j < 8; j++)
#pragma unroll
            for (int e = 0; e < 4; e++) of[j][e] = 0.0f;

        const int qrow_w = qt * 128 + 16 * w;
        const int r0g = qrow_w + (lane >> 2);

        const int kmax = 2 * qt + 1;
#pragma unroll 1
        for (int kt = 0; kt <= kmax; kt++) {
            __syncthreads();

            // ---- load K and V tiles (64x64 fp32 each) ----
#pragma unroll
            for (int p = 0; p < 4; p++) {
                const int idx = t + (p << 8);
                const int row = idx >> 4;
                const int c4  = idx & 15;
                const size_t gro = (size_t)(kt * 64 + row) * QKV_N + h * DHEAD + c4 * 4;
                const float4 kv = *reinterpret_cast<const float4*>(qb + DMODEL + gro);
                const float khx = __bfloat162float(__float2bfloat16(kv.x));
                const float khy = __bfloat162float(__float2bfloat16(kv.y));
                const float khz = __bfloat162float(__float2bfloat16(kv.z));
                const float khw = __bfloat162float(__float2bfloat16(kv.w));
                uint2 uh, ul;
                uh.x = packbf(kv.x, kv.y);             uh.y = packbf(kv.z, kv.w);
                ul.x = packbf(kv.x - khx, kv.y - khy); ul.y = packbf(kv.z - khz, kv.w - khw);
                const int o = row * ASTR + c4 * 8;
                *reinterpret_cast<uint2*>(smc + KH_OFF + o) = uh;
                *reinterpret_cast<uint2*>(smc + KL_OFF + o) = ul;
                const float4 vv = *reinterpret_cast<const float4*>(qb + 2 * DMODEL + gro);
                const float ve[4] = {vv.x, vv.y, vv.z, vv.w};
#pragma unroll
                for (int e = 0; e < 4; e++) {
                    const int dh = c4 * 4 + e;
                    const __nv_bfloat16 vh = __float2bfloat16(ve[e]);
                    *reinterpret_cast<__nv_bfloat16*>(smc + VTH_OFF + dh * ASTR + row * 2) = vh;
                    *reinterpret_cast<__nv_bfloat16*>(smc + VTL_OFF + dh * ASTR + row * 2) =
                        __float2bfloat16(ve[e] - __bfloat162float(vh));
                }
            }
            if (t < 64)
                msk_s[t] = (mask[b * TSEQ + kt * 64 + t] != 0) ? 0.0f : -1e30f;
            __syncthreads();

            // ---- S = Q @ K^T ----
            float s[8][4];
#pragma unroll
            for (int j = 0; j < 8; j++)
#pragma unroll
                for (int e = 0; e < 4; e++) s[j][e] = 0.0f;

#pragma unroll
            for (int ks = 0; ks < 4; ks++) {
                uint32_t aqh[4], aql[4];
                LDSM_X4(aqh[0], aqh[1], aqh[2], aqh[3], aq_base + ks * 32);
                LDSM_X4(aql[0], aql[1], aql[2], aql[3],
                        aq_base + (QL_OFF - QH_OFF) + ks * 32);
#pragma unroll
                for (int g = 0; g < 4; g++) {
                    uint32_t bkh[4], bkl[4];
                    LDSM_X4(bkh[0], bkh[1], bkh[2], bkh[3],
                            bk_base + g * (16 * ASTR) + ks * 32);
                    LDSM_X4(bkl[0], bkl[1], bkl[2], bkl[3],
                            bk_base + (KL_OFF - KH_OFF) + g * (16 * ASTR) + ks * 32);
                    MMA16816(s[2 * g],     aqh, bkh[0], bkh[1]);
                    MMA16816(s[2 * g],     aqh, bkl[0], bkl[1]);
                    MMA16816(s[2 * g],     aql, bkh[0], bkh[1]);
                    MMA16816(s[2 * g + 1], aqh, bkh[2], bkh[3]);
                    MMA16816(s[2 * g + 1], aqh, bkl[2], bkl[3]);
                    MMA16816(s[2 * g + 1], aql, bkh[2], bkh[3]);
                }
            }

            // ---- mask + causal ----
            const int lc = 2 * (lane & 3);
#pragma unroll
            for (int j = 0; j < 8; j++) {
                const float mj0 = msk_s[j * 8 + lc];
                const float mj1 = msk_s[j * 8 + lc + 1];
                s[j][0] += mj0; s[j][1] += mj1;
                s[j][2] += mj0; s[j][3] += mj1;
            }
            if (kt * 64 + 63 > qrow_w) {
                const int r1g = r0g + 8;
#pragma unroll
                for (int j = 0; j < 8; j++) {
                    const int c0 = kt * 64 + j * 8 + lc;
                    if (c0     > r0g) s[j][0] = -1e30f;
                    if (c0 + 1 > r0g) s[j][1] = -1e30f;
                    if (c0     > r1g) s[j][2] = -1e30f;
                    if (c0 + 1 > r1g) s[j][3] = -1e30f;
                }
            }

            // ---- online softmax ----
            float rm0 = -1e30f, rm1 = -1e30f;
#pragma unroll
            for (int j = 0; j < 8; j++) {
                rm0 = fmaxf(rm0, fmaxf(s[j][0], s[j][1]));
                rm1 = fmaxf(rm1, fmaxf(s[j][2], s[j][3]));
            }
            rm0 = fmaxf(rm0, __shfl_xor_sync(0xffffffffu, rm0, 1));
            rm0 = fmaxf(rm0, __shfl_xor_sync(0xffffffffu, rm0, 2));
            rm1 = fmaxf(rm1, __shfl_xor_sync(0xffffffffu, rm1, 1));
            rm1 = fmaxf(rm1, __shfl_xor_sync(0xffffffffu, rm1, 2));
            const float mn0 = fmaxf(m0, rm0), mn1 = fmaxf(m1, rm1);
            const float al0 = __expf(m0 - mn0), al1 = __expf(m1 - mn1);
            m0 = mn0; m1 = mn1;
            float ls0 = 0.0f, ls1 = 0.0f;
#pragma unroll
            for (int j = 0; j < 8; j++) {
                s[j][0] = __expf(s[j][0] - mn0); ls0 += s[j][0];
                s[j][1] = __expf(s[j][1] - mn0); ls0 += s[j][1];
                s[j][2] = __expf(s[j][2] - mn1); ls1 += s[j][2];
                s[j][3] = __expf(s[j][3] - mn1); ls1 += s[j][3];
            }
            ls0 += __shfl_xor_sync(0xffffffffu, ls0, 1);
            ls0 += __shfl_xor_sync(0xffffffffu, ls0, 2);
            ls1 += __shfl_xor_sync(0xffffffffu, ls1, 1);
            ls1 += __shfl_xor_sync(0xffffffffu, ls1, 2);
            l0 = l0 * al0 + ls0;
            l1 = l1 * al1 + ls1;
#pragma unroll
            for (int j = 0; j < 8; j++) {
                of[j][0] *= al0; of[j][1] *= al0;
                of[j][2] *= al1; of[j][3] *= al1;
            }

            // ---- O += P @ V ----
#pragma unroll
            for (int kt2 = 0; kt2 < 4; kt2++) {
                uint32_t aph[4], apl[4];
                {
                    const float* p0 = s[2 * kt2];
                    const float* p1 = s[2 * kt2 + 1];
                    float hl[8];
#pragma unroll
                    for (int e = 0; e < 4; e++) {
                        hl[e]     = p0[e] - __bfloat162float(__float2bfloat16(p0[e]));
                        hl[4 + e] = p1[e] - __bfloat162float(__float2bfloat16(p1[e]));
                    }
                    aph[0] = packbf(p0[0], p0[1]); aph[1] = packbf(p0[2], p0[3]);
                    aph[2] = packbf(p1[0], p1[1]); aph[3] = packbf(p1[2], p1[3]);
                    apl[0] = packbf(hl[0], hl[1]); apl[1] = packbf(hl[2], hl[3]);
                    apl[2] = packbf(hl[4], hl[5]); apl[3] = packbf(hl[6], hl[7]);
                }
#pragma unroll
                for (int g = 0; g < 4; g++) {
                    uint32_t bvh[4], bvl[4];
                    LDSM_X4(bvh[0], bvh[1], bvh[2], bvh[3],
                            bv_base + g * (16 * ASTR) + kt2 * 32);
                    LDSM_X4(bvl[0], bvl[1], bvl[2], bvl[3],
                            bv_base + (VTL_OFF - VTH_OFF) + g * (16 * ASTR) + kt2 * 32);
                    MMA16816(of[2 * g],     aph, bvh[0], bvh[1]);
                    MMA16816(of[2 * g],     aph, bvl[0], bvl[1]);
                    MMA16816(of[2 * g],     apl, bvh[0], bvh[1]);
                    MMA16816(of[2 * g + 1], aph, bvh[2], bvh[3]);
                    MMA16816(of[2 * g + 1], aph, bvl[2], bvl[3]);
                    MMA16816(of[2 * g + 1], apl, bvh[2], bvh[3]);
                }
            }
        }

        // ---- normalize + split-store bf16 hi/lo to [B*T, D] ----
        const float inv0 = 1.0f / l0, inv1 = 1.0f / l1;
        const size_t obase = ((size_t)(b * TSEQ) + r0g) * DMODEL + h * DHEAD + 2 * (lane & 3);
#pragma unroll
        for (int j = 0; j < 8; j++) {
            const float v00 = of[j][0] * inv0, v01 = of[j][1] * inv0;
            const float v10 = of[j][2] * inv1, v11 = of[j][3] * inv1;
            const float h00 = __bfloat162float(__float2bfloat16(v00));
            const float h01 = __bfloat162float(__float2bfloat16(v01));
            const float h10 = __bfloat162float(__float2bfloat16(v10));
            const float h11 = __bfloat162float(__float2bfloat16(v11));
            *reinterpret_cast<uint32_t*>(outh + obase + j * 8) = packbf(v00, v01);
            *reinterpret_cast<uint32_t*>(outl + obase + j * 8) = packbf(v00 - h00, v01 - h01);
            *reinterpret_cast<uint32_t*>(outh + obase + (size_t)8 * DMODEL + j * 8) = packbf(v10, v11);
            *reinterpret_cast<uint32_t*>(outl + obase + (size_t)8 * DMODEL + j * 8) = packbf(v10 - h10, v11 - h11);
        }
    }
}

// ---------------------------------------------------------------------------
// fp32 -> (bf16 hi, bf16 lo) elementwise split, 4 elems/thread
// ---------------------------------------------------------------------------
__global__ __launch_bounds__(256) void convert_split(
    const float* __restrict__ A, __nv_bfloat16* __restrict__ H,
    __nv_bfloat16* __restrict__ L)
{
    const int i = blockIdx.x * blockDim.x + threadIdx.x;
    const float4 v = reinterpret_cast<const float4*>(A)[i];
    __nv_bfloat16 h0 = __float2bfloat16(v.x), h1 = __float2bfloat16(v.y);
    __nv_bfloat16 h2 = __float2bfloat16(v.z), h3 = __float2bfloat16(v.w);
    __nv_bfloat16 l0 = __float2bfloat16(v.x - __bfloat162float(h0));
    __nv_bfloat16 l1 = __float2bfloat16(v.y - __bfloat162float(h1));
    __nv_bfloat16 l2 = __float2bfloat16(v.z - __bfloat162float(h2));
    __nv_bfloat16 l3 = __float2bfloat16(v.w - __bfloat162float(h3));
    reinterpret_cast<__nv_bfloat162*>(H)[2 * i + 0] = __halves2bfloat162(h0, h1);
    reinterpret_cast<__nv_bfloat162*>(H)[2 * i + 1] = __halves2bfloat162(h2, h3);
    reinterpret_cast<__nv_bfloat162*>(L)[2 * i + 0] = __halves2bfloat162(l0, l1);
    reinterpret_cast<__nv_bfloat162*>(L)[2 * i + 1] = __halves2bfloat162(l2, l3);
}

// ---------------------------------------------------------------------------
// W[K][N] fp32 -> Wt_hi/lo[N][K] bf16 (transpose + split), block (32,8)
// ---------------------------------------------------------------------------
__global__ __launch_bounds__(256) void convert_transpose(
    const float* __restrict__ W, __nv_bfloat16* __restrict__ Th,
    __nv_bfloat16* __restrict__ Tl, int K, int N)
{
    __shared__ float tile[32][33];
    const int tx = threadIdx.x, ty = threadIdx.y;
    const int n0 = blockIdx.x * 32, k0 = blockIdx.y * 32;
#pragma unroll
    for (int i = 0; i < 4; i++)
        tile[ty + i * 8][tx] = W[(size_t)(k0 + ty + i * 8) * N + n0 + tx];
    __syncthreads();
#pragma unroll
    for (int i = 0; i < 4; i++) {
        const float v = tile[tx][ty + i * 8];
        const __nv_bfloat16 h = __float2bfloat16(v);
        const __nv_bfloat16 l = __float2bfloat16(v - __bfloat162float(h));
        const size_t o = (size_t)(n0 + ty + i * 8) * K + k0 + tx;
        Th[o] = h;
        Tl[o] = l;
    }
}

// ---------------------------------------------------------------------------
extern "C" void kernel_launch(void* const* d_in, const int* in_sizes, int n_in,
                              void* d_out, int out_size)
{
    const float* x     = (const float*)d_in[0];
    const float* Wqkv  = (const float*)d_in[1];
    const float* bqkv  = (const float*)d_in[2];
    const float* Wproj = (const float*)d_in[3];
    const float* bproj = (const float*)d_in[4];
    const int*   mask  = (const int*)d_in[5];
    float* out = (float*)d_out;

    float *qkv = nullptr;
    __nv_bfloat16 *xh, *xl, *ah, *al, *wqh, *wql, *wph, *wpl;
    cudaGetSymbolAddress((void**)&qkv,  g_qkv);
    cudaGetSymbolAddress((void**)&xh, g_xh);   cudaGetSymbolAddress((void**)&xl, g_xl);
    cudaGetSymbolAddress((void**)&ah, g_ah);   cudaGetSymbolAddress((void**)&al, g_al);
    cudaGetSymbolAddress((void**)&wqh, g_wqh); cudaGetSymbolAddress((void**)&wql, g_wql);
    cudaGetSymbolAddress((void**)&wph, g_wph); cudaGetSymbolAddress((void**)&wpl, g_wpl);

    cudaFuncSetAttribute(attn_hmma,
                         cudaFuncAttributeMaxDynamicSharedMemorySize, ATTN_SMEM);
    cudaFuncSetAttribute(gemm_hmma,
                         cudaFuncAttributeMaxDynamicSharedMemorySize, GEMM_SMEM);

    // Split-convert input and weights (weights transposed to [N][K])
    convert_split<<<(MROWS * DMODEL) / 1024, 256>>>(x, xh, xl);
    convert_transpose<<<dim3(QKV_N / 32, DMODEL / 32), dim3(32, 8)>>>(
        Wqkv, wqh, wql, DMODEL, QKV_N);
    convert_transpose<<<dim3(DMODEL / 32, DMODEL / 32), dim3(32, 8)>>>(
        Wproj, wph, wpl, DMODEL, DMODEL);

    // 1) QKV = x @ Wqkv + bqkv  (HMMA split-bf16)
    gemm_hmma<<<dim3(QKV_N / 128, MROWS / 128), 128, GEMM_SMEM>>>(
        xh, xl, wqh, wql, bqkv, qkv, MROWS, QKV_N);

    // 2) Fused causal attention (HMMA split-bf16), writes bf16 hi/lo
    attn_hmma<<<dim3(4, BATCH * NH), 256, ATTN_SMEM>>>(qkv, mask, ah, al);

    // 3) out = attn @ Wproj + bproj
    gemm_hmma<<<dim3(DMODEL / 128, MROWS / 128), 128, GEMM_SMEM>>>(
        ah, al, wph, wpl, bproj, out, MROWS, DMODEL);
}

// round 6
// speedup vs baseline: 2.4305x; 1.0502x over previous
#include <cuda_runtime.h>
#include <cuda_bf16.h>
#include <math.h>
#include <cstdint>

// Problem constants
#define BATCH 4
#define TSEQ  1024
#define DMODEL 1024
#define NH 16
#define DHEAD 64
#define QKV_N 3072   // 3*DMODEL
#define MROWS 4096   // BATCH*TSEQ
#define KDIM 1024    // K is 1024 for both GEMMs

// ---------------------------------------------------------------------------
// Scratch (device globals: allocation-free)
// ---------------------------------------------------------------------------
__device__ __nv_bfloat16 g_xh[(size_t)MROWS * DMODEL];
__device__ __nv_bfloat16 g_xl[(size_t)MROWS * DMODEL];
__device__ __nv_bfloat16 g_qh[(size_t)MROWS * DMODEL];   // Q scaled, split
__device__ __nv_bfloat16 g_ql[(size_t)MROWS * DMODEL];
__device__ __nv_bfloat16 g_kh[(size_t)MROWS * DMODEL];
__device__ __nv_bfloat16 g_kl[(size_t)MROWS * DMODEL];
__device__ __nv_bfloat16 g_vh[(size_t)MROWS * DMODEL];   // V [row][h*64+dh]
__device__ __nv_bfloat16 g_vl[(size_t)MROWS * DMODEL];
__device__ __nv_bfloat16 g_vth[(size_t)MROWS * DMODEL];  // V^T [bh][dh][t]
__device__ __nv_bfloat16 g_vtl[(size_t)MROWS * DMODEL];
__device__ __nv_bfloat16 g_ah[(size_t)MROWS * DMODEL];   // attention out hi
__device__ __nv_bfloat16 g_al[(size_t)MROWS * DMODEL];   // attention out lo
__device__ __nv_bfloat16 g_wqh[(size_t)QKV_N * DMODEL];  // Wqkv^T [3072][1024]
__device__ __nv_bfloat16 g_wql[(size_t)QKV_N * DMODEL];
__device__ __nv_bfloat16 g_wph[(size_t)DMODEL * DMODEL]; // Wproj^T [1024][1024]
__device__ __nv_bfloat16 g_wpl[(size_t)DMODEL * DMODEL];

// ---------------------------------------------------------------------------
// PTX helpers (base ISA only — compute_103 virtual arch, no tcgen05)
// ---------------------------------------------------------------------------
__device__ __forceinline__ uint32_t smem_to_u32(const void* p) {
    uint32_t a;
    asm("{ .reg .u64 t; cvta.to.shared.u64 t, %1; cvt.u32.u64 %0, t; }"
        : "=r"(a) : "l"(p));
    return a;
}

#define CP_ASYNC16(smem, gptr) \
    asm volatile("cp.async.cg.shared.global [%0], [%1], 16;" \
        :: "r"(smem), "l"(gptr) : "memory")
#define CP_COMMIT() asm volatile("cp.async.commit_group;" ::: "memory")
#define CP_WAIT(n)  asm volatile("cp.async.wait_group %0;" :: "n"(n) : "memory")

#define LDSM_X4(r0, r1, r2, r3, addr) \
    asm volatile("ldmatrix.sync.aligned.m8n8.x4.shared.b16 {%0,%1,%2,%3}, [%4];" \
        : "=r"(r0), "=r"(r1), "=r"(r2), "=r"(r3) : "r"(addr))

#define MMA16816(c, a, b0, b1) \
    asm volatile("mma.sync.aligned.m16n8k16.row.col.f32.bf16.bf16.f32 " \
        "{%0,%1,%2,%3}, {%4,%5,%6,%7}, {%8,%9}, {%0,%1,%2,%3};" \
        : "+f"((c)[0]), "+f"((c)[1]), "+f"((c)[2]), "+f"((c)[3]) \
        : "r"((a)[0]), "r"((a)[1]), "r"((a)[2]), "r"((a)[3]), \
          "r"(b0), "r"(b1))

// pack two floats to bf16x2 (lo addr half = first arg)
__device__ __forceinline__ uint32_t packbf(float lo, float hi) {
    uint32_t r;
    asm("cvt.rn.bf16x2.f32 %0, %1, %2;" : "=r"(r) : "f"(hi), "f"(lo));
    return r;
}

// ---------------------------------------------------------------------------
// Split-bf16 HMMA GEMM: C = (Ah+Al)[M,K] @ ((Bh+Bl)[N,K])^T + bias
// CTA 128x128, K-tile 32, 2-stage cp.async, 2 CTAs/SM, 4 warps (2x2), 64x64.
// MODE 0: fp32 C out.  MODE 1: QKV epilogue -> split-bf16 q(scaled)/k/v.
// ---------------------------------------------------------------------------
#define MATB   10240
#define STAGEB 40960
#define GEMM_SMEM (2 * STAGEB)

template <int MODE>
__global__ __launch_bounds__(128, 2) void gemm_hmma(
    const __nv_bfloat16* __restrict__ Ah, const __nv_bfloat16* __restrict__ Al,
    const __nv_bfloat16* __restrict__ Bh, const __nv_bfloat16* __restrict__ Bl,
    const float* __restrict__ bias, float* __restrict__ C,
    __nv_bfloat16* __restrict__ qh, __nv_bfloat16* __restrict__ ql,
    __nv_bfloat16* __restrict__ kh, __nv_bfloat16* __restrict__ kl,
    __nv_bfloat16* __restrict__ vh, __nv_bfloat16* __restrict__ vl,
    int M, int Ntot)
{
    extern __shared__ char dsm[];
    const uint32_t sb = smem_to_u32(dsm);

    const int t    = threadIdx.x;
    const int lane = t & 31;
    const int wid  = t >> 5;
    const int wm   = wid >> 1;
    const int wn   = wid & 1;
    const int bm   = blockIdx.y << 7;
    const int bn   = blockIdx.x << 7;

    const int rbase = t >> 2;
    const int ch0   = t & 3;
    uint32_t soff[16];
    const __nv_bfloat16* gp[16];
    {
        const __nv_bfloat16* bases[4] = {Ah, Al, Bh, Bl};
        const int rb[4] = {bm, bm, bn, bn};
#pragma unroll
        for (int m = 0; m < 4; m++)
#pragma unroll
            for (int hh = 0; hh < 4; hh++) {
                const int r = rbase + hh * 32;
                soff[m * 4 + hh] = (uint32_t)(m * MATB + r * 80 + ch0 * 16);
                gp[m * 4 + hh]   = bases[m] + (size_t)(rb[m] + r) * KDIM + ch0 * 8;
            }
    }

    const uint32_t a_base = (uint32_t)((wm * 64 + (lane & 15)) * 80 + (lane >> 4) * 16);
    const uint32_t b_base = (uint32_t)(2 * MATB +
        (wn * 64 + (lane & 7) + ((lane >> 4) << 3)) * 80 + ((lane >> 3) & 1) * 16);

    float acc[4][8][4];
#pragma unroll
    for (int mi = 0; mi < 4; mi++)
#pragma unroll
        for (int ni = 0; ni < 8; ni++)
#pragma unroll
            for (int e = 0; e < 4; e++) acc[mi][ni][e] = 0.0f;

    const int NT = KDIM / 32;

#pragma unroll
    for (int i = 0; i < 16; i++) CP_ASYNC16(sb + soff[i], gp[i]);
    CP_COMMIT();

#pragma unroll 1
    for (int kt = 0; kt < NT; kt++) {
        if (kt + 1 < NT) {
            const uint32_t st = sb + (uint32_t)((kt + 1) & 1) * STAGEB;
            const int ko = (kt + 1) * 32;
#pragma unroll
            for (int i = 0; i < 16; i++) CP_ASYNC16(st + soff[i], gp[i] + ko);
        }
        CP_COMMIT();
        CP_WAIT(1);
        __syncthreads();

        const uint32_t stg = sb + (uint32_t)(kt & 1) * STAGEB;
#pragma unroll
        for (int ks = 0; ks < 2; ks++) {
            const uint32_t ko = (uint32_t)(ks * 32);
            uint32_t ah[4][4], al[4][4];
#pragma unroll
            for (int mi = 0; mi < 4; mi++) {
                LDSM_X4(ah[mi][0], ah[mi][1], ah[mi][2], ah[mi][3],
                        stg + a_base + (uint32_t)(mi * 1280) + ko);
                LDSM_X4(al[mi][0], al[mi][1], al[mi][2], al[mi][3],
                        stg + MATB + a_base + (uint32_t)(mi * 1280) + ko);
            }
            uint32_t rbh[4][4], rbl[4][4];
#pragma unroll
            for (int g = 0; g < 4; g++) {
                LDSM_X4(rbh[g][0], rbh[g][1], rbh[g][2], rbh[g][3],
                        stg + b_base + (uint32_t)(g * 1280) + ko);
                LDSM_X4(rbl[g][0], rbl[g][1], rbl[g][2], rbl[g][3],
                        stg + MATB + b_base + (uint32_t)(g * 1280) + ko);
            }
#pragma unroll
            for (int mi = 0; mi < 4; mi++)
#pragma unroll
                for (int ni = 0; ni < 8; ni++) {
                    const int g = ni >> 1, u = (ni & 1) * 2;
                    MMA16816(acc[mi][ni], ah[mi], rbh[g][u], rbh[g][u + 1]);
                    MMA16816(acc[mi][ni], ah[mi], rbl[g][u], rbl[g][u + 1]);
                    MMA16816(acc[mi][ni], al[mi], rbh[g][u], rbh[g][u + 1]);
                }
        }
        __syncthreads();
    }

    // ---- epilogue ----
    const int er = bm + wm * 64 + (lane >> 2);
    const int ec = bn + wn * 64 + (lane & 3) * 2;

    if (MODE == 0) {
#pragma unroll
        for (int ni = 0; ni < 8; ni++) {
            const int col = ec + ni * 8;
            const float2 bv = *reinterpret_cast<const float2*>(bias + col);
#pragma unroll
            for (int mi = 0; mi < 4; mi++) {
                const int r0 = er + mi * 16;
                float2 o0, o1;
                o0.x = acc[mi][ni][0] + bv.x;
                o0.y = acc[mi][ni][1] + bv.y;
                o1.x = acc[mi][ni][2] + bv.x;
                o1.y = acc[mi][ni][3] + bv.y;
                *reinterpret_cast<float2*>(C + (size_t)r0 * Ntot + col) = o0;
                *reinterpret_cast<float2*>(C + (size_t)(r0 + 8) * Ntot + col) = o1;
            }
        }
    } else {
        // QKV epilogue: seg 0=Q(scale 0.125), 1=K, 2=V -> split-bf16 [row][cloc]
        const int seg = bn >> 10;
        __nv_bfloat16 *H, *L;
        float scale = 1.0f;
        if (seg == 0)      { H = qh; L = ql; scale = 0.125f; }
        else if (seg == 1) { H = kh; L = kl; }
        else               { H = vh; L = vl; }
        const int ecl = ec & 1023;   // column within the 1024-wide segment
#pragma unroll
        for (int ni = 0; ni < 8; ni++) {
            const int col = ec + ni * 8;
            const float2 bv = *reinterpret_cast<const float2*>(bias + col);
            const int cl = ecl + ni * 8;
#pragma unroll
            for (int mi = 0; mi < 4; mi++) {
                const int r0 = er + mi * 16;
                const float v00 = (acc[mi][ni][0] + bv.x) * scale;
                const float v01 = (acc[mi][ni][1] + bv.y) * scale;
                const float v10 = (acc[mi][ni][2] + bv.x) * scale;
                const float v11 = (acc[mi][ni][3] + bv.y) * scale;
                const float h00 = __bfloat162float(__float2bfloat16(v00));
                const float h01 = __bfloat162float(__float2bfloat16(v01));
                const float h10 = __bfloat162float(__float2bfloat16(v10));
                const float h11 = __bfloat162float(__float2bfloat16(v11));
                *reinterpret_cast<uint32_t*>(H + (size_t)r0 * 1024 + cl) = packbf(v00, v01);
                *reinterpret_cast<uint32_t*>(L + (size_t)r0 * 1024 + cl) = packbf(v00 - h00, v01 - h01);
                *reinterpret_cast<uint32_t*>(H + (size_t)(r0 + 8) * 1024 + cl) = packbf(v10, v11);
                *reinterpret_cast<uint32_t*>(L + (size_t)(r0 + 8) * 1024 + cl) = packbf(v10 - h10, v11 - h11);
            }
        }
    }
}

// ---------------------------------------------------------------------------
// V transpose: vh/vl [B*T][1024] -> vth/vtl [(b*16+h)*64+dh][1024] (col = t)
// ---------------------------------------------------------------------------
__global__ __launch_bounds__(256) void transpose_v(
    const __nv_bfloat16* __restrict__ vh, const __nv_bfloat16* __restrict__ vl,
    __nv_bfloat16* __restrict__ vth, __nv_bfloat16* __restrict__ vtl)
{
    __shared__ __nv_bfloat16 th[32][33], tl[32][33];
    const int tx = threadIdx.x, ty = threadIdx.y;
    const int c0 = blockIdx.x * 32;   // V column (h*64+dh)
    const int r0 = blockIdx.y * 32;   // token row
#pragma unroll
    for (int i = 0; i < 4; i++) {
        const size_t src = (size_t)(r0 + ty + i * 8) * 1024 + c0 + tx;
        th[ty + i * 8][tx] = vh[src];
        tl[ty + i * 8][tx] = vl[src];
    }
    __syncthreads();
    const int b = r0 >> 10;
    const int tbase = (r0 & 1023) + tx;
#pragma unroll
    for (int i = 0; i < 4; i++) {
        const int cp = c0 + ty + i * 8;
        const int hh = cp >> 6, dh = cp & 63;
        const size_t dst = (size_t)(((b * 16 + hh) * 64) + dh) * 1024 + tbase;
        vth[dst] = th[tx][ty + i * 8];
        vtl[dst] = tl[tx][ty + i * 8];
    }
}

// ---------------------------------------------------------------------------
// HMMA flash attention, split-bf16 3-product; all operands pre-split bf16,
// loaded straight into smem with cp.async (no conversion in the hot loop).
// Grid (4, B*H), 2 passes: q-tiles {7-bx, bx} (BQ=128). 8 warps x 16 rows.
// ---------------------------------------------------------------------------
#define ASTR 144
#define QH_OFF 0
#define QL_OFF 18432
#define KH_OFF 36864
#define KL_OFF 46080
#define VTH_OFF 55296
#define VTL_OFF 64512
#define MSK_OFF 73728
#define ATTN_SMEM (73728 + 256)

__global__ __launch_bounds__(256, 2) void attn_hmma(
    const __nv_bfloat16* __restrict__ qh, const __nv_bfloat16* __restrict__ ql,
    const __nv_bfloat16* __restrict__ kh, const __nv_bfloat16* __restrict__ kl,
    const __nv_bfloat16* __restrict__ vth, const __nv_bfloat16* __restrict__ vtl,
    const int* __restrict__ mask,
    __nv_bfloat16* __restrict__ outh, __nv_bfloat16* __restrict__ outl)
{
    extern __shared__ char smc[];
    const uint32_t sb = smem_to_u32(smc);

    const int t    = threadIdx.x;
    const int lane = t & 31;
    const int w    = t >> 5;
    const int bh   = blockIdx.y;
    const int b    = bh >> 4;
    const int h    = bh & 15;
    float* msk_s = (float*)(smc + MSK_OFF);

    // cp.async plans (thread-invariant parts)
    const int qrow = t >> 1;                 // Q: 2 chunk-slots/thread/row-pass
    const int qch  = (t & 1) * 4;            // chunks 0-3 / 4-7 alt? use 8/thread below
    (void)qrow; (void)qch;

    const uint32_t aq_base = sb + QH_OFF +
        (uint32_t)((16 * w + (lane & 15)) * ASTR + (lane >> 4) * 16);
    const uint32_t bk_base = sb + KH_OFF +
        (uint32_t)(((lane & 7) + ((lane >> 4) << 3)) * ASTR + ((lane >> 3) & 1) * 16);
    const uint32_t bv_base = sb + VTH_OFF +
        (uint32_t)(((lane & 7) + ((lane >> 4) << 3)) * ASTR + ((lane >> 3) & 1) * 16);

#pragma unroll 1
    for (int pass = 0; pass < 2; pass++) {
        const int qt = pass ? (int)blockIdx.x : 7 - (int)blockIdx.x;
        __syncthreads();   // previous pass readers of Q done

        // ---- Q tile: 128 rows x 64 bf16 (hi+lo) = 2048 16B chunks ----
#pragma unroll
        for (int p = 0; p < 8; p++) {
            const int c   = t + (p << 8);        // 0..2047
            const int m   = c >> 10;             // 0=hi 1=lo
            const int idx = c & 1023;
            const int row = idx >> 3;
            const int ch  = idx & 7;
            const __nv_bfloat16* src = (m ? ql : qh) +
                (size_t)(b * 1024 + qt * 128 + row) * 1024 + h * 64 + ch * 8;
            CP_ASYNC16(sb + (m ? QL_OFF : QH_OFF) + row * ASTR + ch * 16, src);
        }
        CP_COMMIT();

        float m0 = -1e30f, m1 = -1e30f, l0 = 0.0f, l1 = 0.0f;
        float of[8][4];
#pragma unroll
        for (int j = 0; j < 8; j++)
#pragma unroll
            for (int e = 0; e < 4; e++) of[j][e] = 0.0f;

        const int qrow_w = qt * 128 + 16 * w;
        const int r0g = qrow_w + (lane >> 2);

        const int kmax = 2 * qt + 1;
#pragma unroll 1
        for (int kt = 0; kt <= kmax; kt++) {
            __syncthreads();   // previous compute done (K/V smem reusable)

            // ---- K (64x64) + V^T (64x64) hi/lo: 2048 chunks ----
#pragma unroll
            for (int p = 0; p < 8; p++) {
                const int c   = t + (p << 8);    // 0..2047
                const int m   = c >> 9;          // 0=Kh 1=Kl 2=Vth 3=Vtl
                const int idx = c & 511;
                const int row = idx >> 3;
                const int ch  = idx & 7;
                const __nv_bfloat16* src;
                uint32_t dst;
                if (m == 0) {
                    src = kh + (size_t)(b * 1024 + kt * 64 + row) * 1024 + h * 64 + ch * 8;
                    dst = sb + KH_OFF + row * ASTR + ch * 16;
                } else if (m == 1) {
                    src = kl + (size_t)(b * 1024 + kt * 64 + row) * 1024 + h * 64 + ch * 8;
                    dst = sb + KL_OFF + row * ASTR + ch * 16;
                } else if (m == 2) {
                    src = vth + (size_t)(bh * 64 + row) * 1024 + kt * 64 + ch * 8;
                    dst = sb + VTH_OFF + row * ASTR + ch * 16;
                } else {
                    src = vtl + (size_t)(bh * 64 + row) * 1024 + kt * 64 + ch * 8;
                    dst = sb + VTL_OFF + row * ASTR + ch * 16;
                }
                CP_ASYNC16(dst, src);
            }
            if (t < 64)
                msk_s[t] = (mask[b * TSEQ + kt * 64 + t] != 0) ? 0.0f : -1e30f;
            CP_COMMIT();
            CP_WAIT(0);
            __syncthreads();

            // ---- S = Q @ K^T ----
            float s[8][4];
#pragma unroll
            for (int j = 0; j < 8; j++)
#pragma unroll
                for (int e = 0; e < 4; e++) s[j][e] = 0.0f;

#pragma unroll
            for (int ks = 0; ks < 4; ks++) {
                uint32_t aqh[4], aql[4];
                LDSM_X4(aqh[0], aqh[1], aqh[2], aqh[3], aq_base + ks * 32);
                LDSM_X4(aql[0], aql[1], aql[2], aql[3],
                        aq_base + (QL_OFF - QH_OFF) + ks * 32);
#pragma unroll
                for (int g = 0; g < 4; g++) {
                    uint32_t bkh[4], bkl[4];
                    LDSM_X4(bkh[0], bkh[1], bkh[2], bkh[3],
                            bk_base + g * (16 * ASTR) + ks * 32);
                    LDSM_X4(bkl[0], bkl[1], bkl[2], bkl[3],
                            bk_base + (KL_OFF - KH_OFF) + g * (16 * ASTR) + ks * 32);
                    MMA16816(s[2 * g],     aqh, bkh[0], bkh[1]);
                    MMA16816(s[2 * g],     aqh, bkl[0], bkl[1]);
                    MMA16816(s[2 * g],     aql, bkh[0], bkh[1]);
                    MMA16816(s[2 * g + 1], aqh, bkh[2], bkh[3]);
                    MMA16816(s[2 * g + 1], aqh, bkl[2], bkl[3]);
                    MMA16816(s[2 * g + 1], aql, bkh[2], bkh[3]);
                }
            }

            // ---- mask + causal ----
            const int lc = 2 * (lane & 3);
#pragma unroll
            for (int j = 0; j < 8; j++) {
                const float mj0 = msk_s[j * 8 + lc];
                const float mj1 = msk_s[j * 8 + lc + 1];
                s[j][0] += mj0; s[j][1] += mj1;
                s[j][2] += mj0; s[j][3] += mj1;
            }
            if (kt * 64 + 63 > qrow_w) {
                const int r1g = r0g + 8;
#pragma unroll
                for (int j = 0; j < 8; j++) {
                    const int c0 = kt * 64 + j * 8 + lc;
                    if (c0     > r0g) s[j][0] = -1e30f;
                    if (c0 + 1 > r0g) s[j][1] = -1e30f;
                    if (c0     > r1g) s[j][2] = -1e30f;
                    if (c0 + 1 > r1g) s[j][3] = -1e30f;
                }
            }

            // ---- online softmax ----
            float rm0 = -1e30f, rm1 = -1e30f;
#pragma unroll
            for (int j = 0; j < 8; j++) {
                rm0 = fmaxf(rm0, fmaxf(s[j][0], s[j][1]));
                rm1 = fmaxf(rm1, fmaxf(s[j][2], s[j][3]));
            }
            rm0 = fmaxf(rm0, __shfl_xor_sync(0xffffffffu, rm0, 1));
            rm0 = fmaxf(rm0, __shfl_xor_sync(0xffffffffu, rm0, 2));
            rm1 = fmaxf(rm1, __shfl_xor_sync(0xffffffffu, rm1, 1));
            rm1 = fmaxf(rm1, __shfl_xor_sync(0xffffffffu, rm1, 2));
            const float mn0 = fmaxf(m0, rm0), mn1 = fmaxf(m1, rm1);
            const float al0 = __expf(m0 - mn0), al1 = __expf(m1 - mn1);
            m0 = mn0; m1 = mn1;
            float ls0 = 0.0f, ls1 = 0.0f;
#pragma unroll
            for (int j = 0; j < 8; j++) {
                s[j][0] = __expf(s[j][0] - mn0); ls0 += s[j][0];
                s[j][1] = __expf(s[j][1] - mn0); ls0 += s[j][1];
                s[j][2] = __expf(s[j][2] - mn1); ls1 += s[j][2];
                s[j][3] = __expf(s[j][3] - mn1); ls1 += s[j][3];
            }
            ls0 += __shfl_xor_sync(0xffffffffu, ls0, 1);
            ls0 += __shfl_xor_sync(0xffffffffu, ls0, 2);
            ls1 += __shfl_xor_sync(0xffffffffu, ls1, 1);
            ls1 += __shfl_xor_sync(0xffffffffu, ls1, 2);
            l0 = l0 * al0 + ls0;
            l1 = l1 * al1 + ls1;
#pragma unroll
            for (int j = 0; j < 8; j++) {
                of[j][0] *= al0; of[j][1] *= al0;
                of[j][2] *= al1; of[j][3] *= al1;
            }

            // ---- O += P @ V ----
#pragma unroll
            for (int kt2 = 0; kt2 < 4; kt2++) {
                uint32_t aph[4], apl[4];
                {
                    const float* p0 = s[2 * kt2];
                    const float* p1 = s[2 * kt2 + 1];
                    float hl[8];
#pragma unroll
                    for (int e = 0; e < 4; e++) {
                        hl[e]     = p0[e] - __bfloat162float(__float2bfloat16(p0[e]));
                        hl[4 + e] = p1[e] - __bfloat162float(__float2bfloat16(p1[e]));
                    }
                    aph[0] = packbf(p0[0], p0[1]); aph[1] = packbf(p0[2], p0[3]);
                    aph[2] = packbf(p1[0], p1[1]); aph[3] = packbf(p1[2], p1[3]);
                    apl[0] = packbf(hl[0], hl[1]); apl[1] = packbf(hl[2], hl[3]);
                    apl[2] = packbf(hl[4], hl[5]); apl[3] = packbf(hl[6], hl[7]);
                }
#pragma unroll
                for (int g = 0; g < 4; g++) {
                    uint32_t bvh[4], bvl[4];
                    LDSM_X4(bvh[0], bvh[1], bvh[2], bvh[3],
                            bv_base + g * (16 * ASTR) + kt2 * 32);
                    LDSM_X4(bvl[0], bvl[1], bvl[2], bvl[3],
                            bv_base + (VTL_OFF - VTH_OFF) + g * (16 * ASTR) + kt2 * 32);
                    MMA16816(of[2 * g],     aph, bvh[0], bvh[1]);
                    MMA16816(of[2 * g],     aph, bvl[0], bvl[1]);
                    MMA16816(of[2 * g],     apl, bvh[0], bvh[1]);
                    MMA16816(of[2 * g + 1], aph, bvh[2], bvh[3]);
                    MMA16816(of[2 * g + 1], aph, bvl[2], bvl[3]);
                    MMA16816(of[2 * g + 1], apl, bvh[2], bvh[3]);
                }
            }
        }

        // ---- normalize + split-store bf16 hi/lo to [B*T, D] ----
        const float inv0 = 1.0f / l0, inv1 = 1.0f / l1;
        const size_t obase = ((size_t)(b * TSEQ) + r0g) * DMODEL + h * DHEAD + 2 * (lane & 3);
#pragma unroll
        for (int j = 0; j < 8; j++) {
            const float v00 = of[j][0] * inv0, v01 = of[j][1] * inv0;
            const float v10 = of[j][2] * inv1, v11 = of[j][3] * inv1;
            const float h00 = __bfloat162float(__float2bfloat16(v00));
            const float h01 = __bfloat162float(__float2bfloat16(v01));
            const float h10 = __bfloat162float(__float2bfloat16(v10));
            const float h11 = __bfloat162float(__float2bfloat16(v11));
            *reinterpret_cast<uint32_t*>(outh + obase + j * 8) = packbf(v00, v01);
            *reinterpret_cast<uint32_t*>(outl + obase + j * 8) = packbf(v00 - h00, v01 - h01);
            *reinterpret_cast<uint32_t*>(outh + obase + (size_t)8 * DMODEL + j * 8) = packbf(v10, v11);
            *reinterpret_cast<uint32_t*>(outl + obase + (size_t)8 * DMODEL + j * 8) = packbf(v10 - h10, v11 - h11);
        }
    }
}

// ---------------------------------------------------------------------------
// fp32 -> (bf16 hi, bf16 lo) elementwise split, 4 elems/thread
// ---------------------------------------------------------------------------
__global__ __launch_bounds__(256) void convert_split(
    const float* __restrict__ A, __nv_bfloat16* __restrict__ H,
    __nv_bfloat16* __restrict__ L)
{
    const int i = blockIdx.x * blockDim.x + threadIdx.x;
    const float4 v = reinterpret_cast<const float4*>(A)[i];
    __nv_bfloat16 h0 = __float2bfloat16(v.x), h1 = __float2bfloat16(v.y);
    __nv_bfloat16 h2 = __float2bfloat16(v.z), h3 = __float2bfloat16(v.w);
    __nv_bfloat16 l0 = __float2bfloat16(v.x - __bfloat162float(h0));
    __nv_bfloat16 l1 = __float2bfloat16(v.y - __bfloat162float(h1));
    __nv_bfloat16 l2 = __float2bfloat16(v.z - __bfloat162float(h2));
    __nv_bfloat16 l3 = __float2bfloat16(v.w - __bfloat162float(h3));
    reinterpret_cast<__nv_bfloat162*>(H)[2 * i + 0] = __halves2bfloat162(h0, h1);
    reinterpret_cast<__nv_bfloat162*>(H)[2 * i + 1] = __halves2bfloat162(h2, h3);
    reinterpret_cast<__nv_bfloat162*>(L)[2 * i + 0] = __halves2bfloat162(l0, l1);
    reinterpret_cast<__nv_bfloat162*>(L)[2 * i + 1] = __halves2bfloat162(l2, l3);
}

// ---------------------------------------------------------------------------
// W[K][N] fp32 -> Wt_hi/lo[N][K] bf16 (transpose + split), block (32,8)
// ---------------------------------------------------------------------------
__global__ __launch_bounds__(256) void convert_transpose(
    const float* __restrict__ W, __nv_bfloat16* __restrict__ Th,
    __nv_bfloat16* __restrict__ Tl, int K, int N)
{
    __shared__ float tile[32][33];
    const int tx = threadIdx.x, ty = threadIdx.y;
    const int n0 = blockIdx.x * 32, k0 = blockIdx.y * 32;
#pragma unroll
    for (int i = 0; i < 4; i++)
        tile[ty + i * 8][tx] = W[(size_t)(k0 + ty + i * 8) * N + n0 + tx];
    __syncthreads();
#pragma unroll
    for (int i = 0; i < 4; i++) {
        const float v = tile[tx][ty + i * 8];
        const __nv_bfloat16 h = __float2bfloat16(v);
        const __nv_bfloat16 l = __float2bfloat16(v - __bfloat162float(h));
        const size_t o = (size_t)(n0 + ty + i * 8) * K + k0 + tx;
        Th[o] = h;
        Tl[o] = l;
    }
}

// ---------------------------------------------------------------------------
extern "C" void kernel_launch(void* const* d_in, const int* in_sizes, int n_in,
                              void* d_out, int out_size)
{
    const float* x     = (const float*)d_in[0];
    const float* Wqkv  = (const float*)d_in[1];
    const float* bqkv  = (const float*)d_in[2];
    const float* Wproj = (const float*)d_in[3];
    const float* bproj = (const float*)d_in[4];
    const int*   mask  = (const int*)d_in[5];
    float* out = (float*)d_out;

    __nv_bfloat16 *xh, *xl, *qh, *ql, *kh, *kl, *vh, *vl, *vth, *vtl;
    __nv_bfloat16 *ah, *al, *wqh, *wql, *wph, *wpl;
    cudaGetSymbolAddress((void**)&xh, g_xh);   cudaGetSymbolAddress((void**)&xl, g_xl);
    cudaGetSymbolAddress((void**)&qh, g_qh);   cudaGetSymbolAddress((void**)&ql, g_ql);
    cudaGetSymbolAddress((void**)&kh, g_kh);   cudaGetSymbolAddress((void**)&kl, g_kl);
    cudaGetSymbolAddress((void**)&vh, g_vh);   cudaGetSymbolAddress((void**)&vl, g_vl);
    cudaGetSymbolAddress((void**)&vth, g_vth); cudaGetSymbolAddress((void**)&vtl, g_vtl);
    cudaGetSymbolAddress((void**)&ah, g_ah);   cudaGetSymbolAddress((void**)&al, g_al);
    cudaGetSymbolAddress((void**)&wqh, g_wqh); cudaGetSymbolAddress((void**)&wql, g_wql);
    cudaGetSymbolAddress((void**)&wph, g_wph); cudaGetSymbolAddress((void**)&wpl, g_wpl);

    cudaFuncSetAttribute(attn_hmma,
                         cudaFuncAttributeMaxDynamicSharedMemorySize, ATTN_SMEM);
    cudaFuncSetAttribute(gemm_hmma<0>,
                         cudaFuncAttributeMaxDynamicSharedMemorySize, GEMM_SMEM);
    cudaFuncSetAttribute(gemm_hmma<1>,
                         cudaFuncAttributeMaxDynamicSharedMemorySize, GEMM_SMEM);

    // Split-convert input and weights (weights transposed to [N][K])
    convert_split<<<(MROWS * DMODEL) / 1024, 256>>>(x, xh, xl);
    convert_transpose<<<dim3(QKV_N / 32, DMODEL / 32), dim3(32, 8)>>>(
        Wqkv, wqh, wql, DMODEL, QKV_N);
    convert_transpose<<<dim3(DMODEL / 32, DMODEL / 32), dim3(32, 8)>>>(
        Wproj, wph, wpl, DMODEL, DMODEL);

    // 1) QKV GEMM -> split-bf16 Q(scaled)/K/V directly
    gemm_hmma<1><<<dim3(QKV_N / 128, MROWS / 128), 128, GEMM_SMEM>>>(
        xh, xl, wqh, wql, bqkv, nullptr,
        qh, ql, kh, kl, vh, vl, MROWS, QKV_N);

    // 2) V transpose (coalesced, once)
    transpose_v<<<dim3(32, 128), dim3(32, 8)>>>(vh, vl, vth, vtl);

    // 3) Fused causal attention (HMMA split-bf16, cp.async loads)
    attn_hmma<<<dim3(4, BATCH * NH), 256, ATTN_SMEM>>>(
        qh, ql, kh, kl, vth, vtl, mask, ah, al);

    // 4) out = attn @ Wproj + bproj
    gemm_hmma<0><<<dim3(DMODEL / 128, MROWS / 128), 128, GEMM_SMEM>>>(
        ah, al, wph, wpl, bproj, out,
        nullptr, nullptr, nullptr, nullptr, nullptr, nullptr, MROWS, DMODEL);
}

// round 7
// speedup vs baseline: 2.7426x; 1.1284x over previous
#include <cuda_runtime.h>
#include <cuda_bf16.h>
#include <math.h>
#include <cstdint>

// Problem constants
#define BATCH 4
#define TSEQ  1024
#define DMODEL 1024
#define NH 16
#define DHEAD 64
#define QKV_N 3072   // 3*DMODEL
#define MROWS 4096   // BATCH*TSEQ
#define KDIM 1024    // K is 1024 for both GEMMs

// ---------------------------------------------------------------------------
// Scratch (device globals: allocation-free)
// ---------------------------------------------------------------------------
__device__ __nv_bfloat16 g_xh[(size_t)MROWS * DMODEL];
__device__ __nv_bfloat16 g_xl[(size_t)MROWS * DMODEL];
__device__ __nv_bfloat16 g_qh[(size_t)MROWS * DMODEL];   // Q scaled, split
__device__ __nv_bfloat16 g_ql[(size_t)MROWS * DMODEL];
__device__ __nv_bfloat16 g_kh[(size_t)MROWS * DMODEL];
__device__ __nv_bfloat16 g_kl[(size_t)MROWS * DMODEL];
__device__ __nv_bfloat16 g_vh[(size_t)MROWS * DMODEL];   // V [row][h*64+dh]
__device__ __nv_bfloat16 g_vl[(size_t)MROWS * DMODEL];
__device__ __nv_bfloat16 g_vth[(size_t)MROWS * DMODEL];  // V^T [bh][dh][t]
__device__ __nv_bfloat16 g_vtl[(size_t)MROWS * DMODEL];
__device__ __nv_bfloat16 g_ah[(size_t)MROWS * DMODEL];   // attention out hi
__device__ __nv_bfloat16 g_al[(size_t)MROWS * DMODEL];   // attention out lo
__device__ __nv_bfloat16 g_wqh[(size_t)QKV_N * DMODEL];  // Wqkv^T [3072][1024]
__device__ __nv_bfloat16 g_wql[(size_t)QKV_N * DMODEL];
__device__ __nv_bfloat16 g_wph[(size_t)DMODEL * DMODEL]; // Wproj^T [1024][1024]
__device__ __nv_bfloat16 g_wpl[(size_t)DMODEL * DMODEL];

// ---------------------------------------------------------------------------
// PTX helpers (base ISA only — compute_103 virtual arch, no tcgen05)
// ---------------------------------------------------------------------------
__device__ __forceinline__ uint32_t smem_to_u32(const void* p) {
    uint32_t a;
    asm("{ .reg .u64 t; cvta.to.shared.u64 t, %1; cvt.u32.u64 %0, t; }"
        : "=r"(a) : "l"(p));
    return a;
}

#define CP_ASYNC16(smem, gptr) \
    asm volatile("cp.async.cg.shared.global [%0], [%1], 16;" \
        :: "r"(smem), "l"(gptr) : "memory")
#define CP_COMMIT() asm volatile("cp.async.commit_group;" ::: "memory")
#define CP_WAIT(n)  asm volatile("cp.async.wait_group %0;" :: "n"(n) : "memory")

#define LDSM_X4(r0, r1, r2, r3, addr) \
    asm volatile("ldmatrix.sync.aligned.m8n8.x4.shared.b16 {%0,%1,%2,%3}, [%4];" \
        : "=r"(r0), "=r"(r1), "=r"(r2), "=r"(r3) : "r"(addr))

#define MMA16816(c, a, b0, b1) \
    asm volatile("mma.sync.aligned.m16n8k16.row.col.f32.bf16.bf16.f32 " \
        "{%0,%1,%2,%3}, {%4,%5,%6,%7}, {%8,%9}, {%0,%1,%2,%3};" \
        : "+f"((c)[0]), "+f"((c)[1]), "+f"((c)[2]), "+f"((c)[3]) \
        : "r"((a)[0]), "r"((a)[1]), "r"((a)[2]), "r"((a)[3]), \
          "r"(b0), "r"(b1))

// pack two floats to bf16x2 (lo addr half = first arg)
__device__ __forceinline__ uint32_t packbf(float lo, float hi) {
    uint32_t r;
    asm("cvt.rn.bf16x2.f32 %0, %1, %2;" : "=r"(r) : "f"(hi), "f"(lo));
    return r;
}

// Swizzled byte offset within one 8KB matrix tile (128 rows x 32 bf16):
// row-pair lines of 128B, chunk3 = (r&1)*4 + ch (ch = 16B k-chunk 0..3),
// swizzled with XOR (r>>1)&7.
__device__ __forceinline__ uint32_t sw_off(int r, int ch) {
    const uint32_t chunk3 = (uint32_t)(((r & 1) << 2) | ch);
    return (uint32_t)((r >> 1) * 128) + ((chunk3 ^ ((uint32_t)(r >> 1) & 7u)) << 4);
}

// ---------------------------------------------------------------------------
// Split-bf16 HMMA GEMM: C = (Ah+Al)[M,K] @ ((Bh+Bl)[N,K])^T + bias
// CTA 128x128, K-tile 32, 3-stage cp.async (swizzled smem, 32KB/stage),
// 2 CTAs/SM, 4 warps (2x2), warp tile 64x64.
// MODE 0: fp32 C out.  MODE 1: QKV epilogue -> split-bf16 q(scaled)/k/v.
// ---------------------------------------------------------------------------
#define MATB   8192
#define STAGEB 32768
#define GEMM_SMEM (3 * STAGEB)

template <int MODE>
__global__ __launch_bounds__(128, 2) void gemm_hmma(
    const __nv_bfloat16* __restrict__ Ah, const __nv_bfloat16* __restrict__ Al,
    const __nv_bfloat16* __restrict__ Bh, const __nv_bfloat16* __restrict__ Bl,
    const float* __restrict__ bias, float* __restrict__ C,
    __nv_bfloat16* __restrict__ qh, __nv_bfloat16* __restrict__ ql,
    __nv_bfloat16* __restrict__ kh, __nv_bfloat16* __restrict__ kl,
    __nv_bfloat16* __restrict__ vh, __nv_bfloat16* __restrict__ vl,
    int M, int Ntot)
{
    extern __shared__ char dsm[];
    const uint32_t sb = smem_to_u32(dsm);

    const int t    = threadIdx.x;
    const int lane = t & 31;
    const int wid  = t >> 5;
    const int wm   = wid >> 1;
    const int wn   = wid & 1;
    const int bm   = blockIdx.y << 7;
    const int bn   = blockIdx.x << 7;

    // cp.async plan: 4 matrices x 512 chunks(16B) / 128 thr = 16/thread
    const int rbase = t >> 2;       // 0..31
    const int ch0   = t & 3;        // k-chunk 0..3
    uint32_t soff[16];
    const __nv_bfloat16* gp[16];
    {
        const __nv_bfloat16* bases[4] = {Ah, Al, Bh, Bl};
        const int rb[4] = {bm, bm, bn, bn};
#pragma unroll
        for (int m = 0; m < 4; m++)
#pragma unroll
            for (int hh = 0; hh < 4; hh++) {
                const int r = rbase + hh * 32;
                soff[m * 4 + hh] = (uint32_t)(m * MATB) + sw_off(r, ch0);
                gp[m * 4 + hh]   = bases[m] + (size_t)(rb[m] + r) * KDIM + ch0 * 8;
            }
    }

    // ldsm bases (swizzled, ks=0); ks toggles byte bit5 via XOR, mi/g add 1024B
    const uint32_t a_base = sw_off(wm * 64 + (lane & 15), lane >> 4);
    const uint32_t b_base = (uint32_t)(2 * MATB) +
        sw_off(wn * 64 + (lane & 7) + ((lane >> 4) << 3), (lane >> 3) & 1);

    float acc[4][8][4];
#pragma unroll
    for (int mi = 0; mi < 4; mi++)
#pragma unroll
        for (int ni = 0; ni < 8; ni++)
#pragma unroll
            for (int e = 0; e < 4; e++) acc[mi][ni][e] = 0.0f;

    const int NT = KDIM / 32;

    // prologue: stages 0 and 1
#pragma unroll
    for (int s = 0; s < 2; s++) {
        const uint32_t st = sb + (uint32_t)s * STAGEB;
        const int ko = s * 32;
#pragma unroll
        for (int i = 0; i < 16; i++) CP_ASYNC16(st + soff[i], gp[i] + ko);
        CP_COMMIT();
    }

    int buf = 0, nbuf = 2;
#pragma unroll 1
    for (int kt = 0; kt < NT; kt++) {
        CP_WAIT(1);
        __syncthreads();

        // issue stage kt+2 into nbuf (its last reader finished at kt-1,
        // ordered by the barrier above)
        if (kt + 2 < NT) {
            const uint32_t st = sb + (uint32_t)nbuf * STAGEB;
            const int ko = (kt + 2) * 32;
#pragma unroll
            for (int i = 0; i < 16; i++) CP_ASYNC16(st + soff[i], gp[i] + ko);
        }
        CP_COMMIT();

        const uint32_t stg = sb + (uint32_t)buf * STAGEB;
        buf = (buf == 2) ? 0 : buf + 1;
        nbuf = (nbuf == 2) ? 0 : nbuf + 1;

#pragma unroll
        for (int ks = 0; ks < 2; ks++) {
            const uint32_t ksx = (uint32_t)(ks << 5);
            uint32_t ah[4][4], al[4][4];
#pragma unroll
            for (int mi = 0; mi < 4; mi++) {
                const uint32_t ao = (a_base + (uint32_t)(mi * 1024)) ^ ksx;
                LDSM_X4(ah[mi][0], ah[mi][1], ah[mi][2], ah[mi][3], stg + ao);
                LDSM_X4(al[mi][0], al[mi][1], al[mi][2], al[mi][3], stg + MATB + ao);
            }
            uint32_t rbh[4][4], rbl[4][4];
#pragma unroll
            for (int g = 0; g < 4; g++) {
                const uint32_t bo = (b_base + (uint32_t)(g * 1024)) ^ ksx;
                LDSM_X4(rbh[g][0], rbh[g][1], rbh[g][2], rbh[g][3], stg + bo);
                LDSM_X4(rbl[g][0], rbl[g][1], rbl[g][2], rbl[g][3], stg + MATB + bo);
            }
#pragma unroll
            for (int mi = 0; mi < 4; mi++)
#pragma unroll
                for (int ni = 0; ni < 8; ni++) {
                    const int g = ni >> 1, u = (ni & 1) * 2;
                    MMA16816(acc[mi][ni], ah[mi], rbh[g][u], rbh[g][u + 1]);
                    MMA16816(acc[mi][ni], ah[mi], rbl[g][u], rbl[g][u + 1]);
                    MMA16816(acc[mi][ni], al[mi], rbh[g][u], rbh[g][u + 1]);
                }
        }
    }

    // ---- epilogue ----
    const int er = bm + wm * 64 + (lane >> 2);
    const int ec = bn + wn * 64 + (lane & 3) * 2;

    if (MODE == 0) {
#pragma unroll
        for (int ni = 0; ni < 8; ni++) {
            const int col = ec + ni * 8;
            const float2 bv = *reinterpret_cast<const float2*>(bias + col);
#pragma unroll
            for (int mi = 0; mi < 4; mi++) {
                const int r0 = er + mi * 16;
                float2 o0, o1;
                o0.x = acc[mi][ni][0] + bv.x;
                o0.y = acc[mi][ni][1] + bv.y;
                o1.x = acc[mi][ni][2] + bv.x;
                o1.y = acc[mi][ni][3] + bv.y;
                *reinterpret_cast<float2*>(C + (size_t)r0 * Ntot + col) = o0;
                *reinterpret_cast<float2*>(C + (size_t)(r0 + 8) * Ntot + col) = o1;
            }
        }
    } else {
        // QKV epilogue: seg 0=Q(scale 0.125), 1=K, 2=V -> split-bf16
        const int seg = bn >> 10;
        __nv_bfloat16 *H, *L;
        float scale = 1.0f;
        if (seg == 0)      { H = qh; L = ql; scale = 0.125f; }
        else if (seg == 1) { H = kh; L = kl; }
        else               { H = vh; L = vl; }
        const int ecl = ec & 1023;
#pragma unroll
        for (int ni = 0; ni < 8; ni++) {
            const int col = ec + ni * 8;
            const float2 bv = *reinterpret_cast<const float2*>(bias + col);
            const int cl = ecl + ni * 8;
#pragma unroll
            for (int mi = 0; mi < 4; mi++) {
                const int r0 = er + mi * 16;
                const float v00 = (acc[mi][ni][0] + bv.x) * scale;
                const float v01 = (acc[mi][ni][1] + bv.y) * scale;
                const float v10 = (acc[mi][ni][2] + bv.x) * scale;
                const float v11 = (acc[mi][ni][3] + bv.y) * scale;
                const float h00 = __bfloat162float(__float2bfloat16(v00));
                const float h01 = __bfloat162float(__float2bfloat16(v01));
                const float h10 = __bfloat162float(__float2bfloat16(v10));
                const float h11 = __bfloat162float(__float2bfloat16(v11));
                *reinterpret_cast<uint32_t*>(H + (size_t)r0 * 1024 + cl) = packbf(v00, v01);
                *reinterpret_cast<uint32_t*>(L + (size_t)r0 * 1024 + cl) = packbf(v00 - h00, v01 - h01);
                *reinterpret_cast<uint32_t*>(H + (size_t)(r0 + 8) * 1024 + cl) = packbf(v10, v11);
                *reinterpret_cast<uint32_t*>(L + (size_t)(r0 + 8) * 1024 + cl) = packbf(v10 - h10, v11 - h11);
            }
        }
    }
}

// ---------------------------------------------------------------------------
// V transpose: vh/vl [B*T][1024] -> vth/vtl [(b*16+h)*64+dh][1024] (col = t)
// ---------------------------------------------------------------------------
__global__ __launch_bounds__(256) void transpose_v(
    const __nv_bfloat16* __restrict__ vh, const __nv_bfloat16* __restrict__ vl,
    __nv_bfloat16* __restrict__ vth, __nv_bfloat16* __restrict__ vtl)
{
    __shared__ __nv_bfloat16 th[32][33], tl[32][33];
    const int tx = threadIdx.x, ty = threadIdx.y;
    const int c0 = blockIdx.x * 32;   // V column (h*64+dh)
    const int r0 = blockIdx.y * 32;   // token row
#pragma unroll
    for (int i = 0; i < 4; i++) {
        const size_t src = (size_t)(r0 + ty + i * 8) * 1024 + c0 + tx;
        th[ty + i * 8][tx] = vh[src];
        tl[ty + i * 8][tx] = vl[src];
    }
    __syncthreads();
    const int b = r0 >> 10;
    const int tbase = (r0 & 1023) + tx;
#pragma unroll
    for (int i = 0; i < 4; i++) {
        const int cp = c0 + ty + i * 8;
        const int hh = cp >> 6, dh = cp & 63;
        const size_t dst = (size_t)(((b * 16 + hh) * 64) + dh) * 1024 + tbase;
        vth[dst] = th[tx][ty + i * 8];
        vtl[dst] = tl[tx][ty + i * 8];
    }
}

// ---------------------------------------------------------------------------
// HMMA flash attention, split-bf16 3-product; all operands pre-split bf16,
// loaded straight into smem with cp.async (no conversion in the hot loop).
// Grid (4, B*H), 2 passes: q-tiles {7-bx, bx} (BQ=128). 8 warps x 16 rows.
// ---------------------------------------------------------------------------
#define ASTR 144
#define QH_OFF 0
#define QL_OFF 18432
#define KH_OFF 36864
#define KL_OFF 46080
#define VTH_OFF 55296
#define VTL_OFF 64512
#define MSK_OFF 73728
#define ATTN_SMEM (73728 + 256)

__global__ __launch_bounds__(256, 2) void attn_hmma(
    const __nv_bfloat16* __restrict__ qh, const __nv_bfloat16* __restrict__ ql,
    const __nv_bfloat16* __restrict__ kh, const __nv_bfloat16* __restrict__ kl,
    const __nv_bfloat16* __restrict__ vth, const __nv_bfloat16* __restrict__ vtl,
    const int* __restrict__ mask,
    __nv_bfloat16* __restrict__ outh, __nv_bfloat16* __restrict__ outl)
{
    extern __shared__ char smc[];
    const uint32_t sb = smem_to_u32(smc);

    const int t    = threadIdx.x;
    const int lane = t & 31;
    const int w    = t >> 5;
    const int bh   = blockIdx.y;
    const int b    = bh >> 4;
    const int h    = bh & 15;
    float* msk_s = (float*)(smc + MSK_OFF);

    const uint32_t aq_base = sb + QH_OFF +
        (uint32_t)((16 * w + (lane & 15)) * ASTR + (lane >> 4) * 16);
    const uint32_t bk_base = sb + KH_OFF +
        (uint32_t)(((lane & 7) + ((lane >> 4) << 3)) * ASTR + ((lane >> 3) & 1) * 16);
    const uint32_t bv_base = sb + VTH_OFF +
        (uint32_t)(((lane & 7) + ((lane >> 4) << 3)) * ASTR + ((lane >> 3) & 1) * 16);

#pragma unroll 1
    for (int pass = 0; pass < 2; pass++) {
        const int qt = pass ? (int)blockIdx.x : 7 - (int)blockIdx.x;
        __syncthreads();   // previous pass readers of Q done

        // ---- Q tile: 128 rows x 64 bf16 (hi+lo) = 2048 16B chunks ----
#pragma unroll
        for (int p = 0; p < 8; p++) {
            const int c   = t + (p << 8);        // 0..2047
            const int m   = c >> 10;             // 0=hi 1=lo
            const int idx = c & 1023;
            const int row = idx >> 3;
            const int ch  = idx & 7;
            const __nv_bfloat16* src = (m ? ql : qh) +
                (size_t)(b * 1024 + qt * 128 + row) * 1024 + h * 64 + ch * 8;
            CP_ASYNC16(sb + (m ? QL_OFF : QH_OFF) + row * ASTR + ch * 16, src);
        }
        CP_COMMIT();

        float m0 = -1e30f, m1 = -1e30f, l0 = 0.0f, l1 = 0.0f;
        float of[8][4];
#pragma unroll
        for (int j = 0; j < 8; j++)
#pragma unroll
            for (int e = 0; e < 4; e++) of[j][e] = 0.0f;

        const int qrow_w = qt * 128 + 16 * w;
        const int r0g = qrow_w + (lane >> 2);

        const int kmax = 2 * qt + 1;
#pragma unroll 1
        for (int kt = 0; kt <= kmax; kt++) {
            __syncthreads();   // previous compute done (K/V smem reusable)

            // ---- K (64x64) + V^T (64x64) hi/lo: 2048 chunks ----
#pragma unroll
            for (int p = 0; p < 8; p++) {
                const int c   = t + (p << 8);    // 0..2047
                const int m   = c >> 9;          // 0=Kh 1=Kl 2=Vth 3=Vtl
                const int idx = c & 511;
                const int row = idx >> 3;
                const int ch  = idx & 7;
                const __nv_bfloat16* src;
                uint32_t dst;
                if (m == 0) {
                    src = kh + (size_t)(b * 1024 + kt * 64 + row) * 1024 + h * 64 + ch * 8;
                    dst = sb + KH_OFF + row * ASTR + ch * 16;
                } else if (m == 1) {
                    src = kl + (size_t)(b * 1024 + kt * 64 + row) * 1024 + h * 64 + ch * 8;
                    dst = sb + KL_OFF + row * ASTR + ch * 16;
                } else if (m == 2) {
                    src = vth + (size_t)(bh * 64 + row) * 1024 + kt * 64 + ch * 8;
                    dst = sb + VTH_OFF + row * ASTR + ch * 16;
                } else {
                    src = vtl + (size_t)(bh * 64 + row) * 1024 + kt * 64 + ch * 8;
                    dst = sb + VTL_OFF + row * ASTR + ch * 16;
                }
                CP_ASYNC16(dst, src);
            }
            if (t < 64)
                msk_s[t] = (mask[b * TSEQ + kt * 64 + t] != 0) ? 0.0f : -1e30f;
            CP_COMMIT();
            CP_WAIT(0);
            __syncthreads();

            // ---- S = Q @ K^T ----
            float s[8][4];
#pragma unroll
            for (int j = 0; j < 8; j++)
#pragma unroll
                for (int e = 0; e < 4; e++) s[j][e] = 0.0f;

#pragma unroll
            for (int ks = 0; ks < 4; ks++) {
                uint32_t aqh[4], aql[4];
                LDSM_X4(aqh[0], aqh[1], aqh[2], aqh[3], aq_base + ks * 32);
                LDSM_X4(aql[0], aql[1], aql[2], aql[3],
                        aq_base + (QL_OFF - QH_OFF) + ks * 32);
#pragma unroll
                for (int g = 0; g < 4; g++) {
                    uint32_t bkh[4], bkl[4];
                    LDSM_X4(bkh[0], bkh[1], bkh[2], bkh[3],
                            bk_base + g * (16 * ASTR) + ks * 32);
                    LDSM_X4(bkl[0], bkl[1], bkl[2], bkl[3],
                            bk_base + (KL_OFF - KH_OFF) + g * (16 * ASTR) + ks * 32);
                    MMA16816(s[2 * g],     aqh, bkh[0], bkh[1]);
                    MMA16816(s[2 * g],     aqh, bkl[0], bkl[1]);
                    MMA16816(s[2 * g],     aql, bkh[0], bkh[1]);
                    MMA16816(s[2 * g + 1], aqh, bkh[2], bkh[3]);
                    MMA16816(s[2 * g + 1], aqh, bkl[2], bkl[3]);
                    MMA16816(s[2 * g + 1], aql, bkh[2], bkh[3]);
                }
            }

            // ---- mask + causal ----
            const int lc = 2 * (lane & 3);
#pragma unroll
            for (int j = 0; j < 8; j++) {
                const float mj0 = msk_s[j * 8 + lc];
                const float mj1 = msk_s[j * 8 + lc + 1];
                s[j][0] += mj0; s[j][1] += mj1;
                s[j][2] += mj0; s[j][3] += mj1;
            }
            if (kt * 64 + 63 > qrow_w) {
                const int r1g = r0g + 8;
#pragma unroll
                for (int j = 0; j < 8; j++) {
                    const int c0 = kt * 64 + j * 8 + lc;
                    if (c0     > r0g) s[j][0] = -1e30f;
                    if (c0 + 1 > r0g) s[j][1] = -1e30f;
                    if (c0     > r1g) s[j][2] = -1e30f;
                    if (c0 + 1 > r1g) s[j][3] = -1e30f;
                }
            }

            // ---- online softmax ----
            float rm0 = -1e30f, rm1 = -1e30f;
#pragma unroll
            for (int j = 0; j < 8; j++) {
                rm0 = fmaxf(rm0, fmaxf(s[j][0], s[j][1]));
                rm1 = fmaxf(rm1, fmaxf(s[j][2], s[j][3]));
            }
            rm0 = fmaxf(rm0, __shfl_xor_sync(0xffffffffu, rm0, 1));
            rm0 = fmaxf(rm0, __shfl_xor_sync(0xffffffffu, rm0, 2));
            rm1 = fmaxf(rm1, __shfl_xor_sync(0xffffffffu, rm1, 1));
            rm1 = fmaxf(rm1, __shfl_xor_sync(0xffffffffu, rm1, 2));
            const float mn0 = fmaxf(m0, rm0), mn1 = fmaxf(m1, rm1);
            const float al0 = __expf(m0 - mn0), al1 = __expf(m1 - mn1);
            m0 = mn0; m1 = mn1;
            float ls0 = 0.0f, ls1 = 0.0f;
#pragma unroll
            for (int j = 0; j < 8; j++) {
                s[j][0] = __expf(s[j][0] - mn0); ls0 += s[j][0];
                s[j][1] = __expf(s[j][1] - mn0); ls0 += s[j][1];
                s[j][2] = __expf(s[j][2] - mn1); ls1 += s[j][2];
                s[j][3] = __expf(s[j][3] - mn1); ls1 += s[j][3];
            }
            ls0 += __shfl_xor_sync(0xffffffffu, ls0, 1);
            ls0 += __shfl_xor_sync(0xffffffffu, ls0, 2);
            ls1 += __shfl_xor_sync(0xffffffffu, ls1, 1);
            ls1 += __shfl_xor_sync(0xffffffffu, ls1, 2);
            l0 = l0 * al0 + ls0;
            l1 = l1 * al1 + ls1;
#pragma unroll
            for (int j = 0; j < 8; j++) {
                of[j][0] *= al0; of[j][1] *= al0;
                of[j][2] *= al1; of[j][3] *= al1;
            }

            // ---- O += P @ V ----
#pragma unroll
            for (int kt2 = 0; kt2 < 4; kt2++) {
                uint32_t aph[4], apl[4];
                {
                    const float* p0 = s[2 * kt2];
                    const float* p1 = s[2 * kt2 + 1];
                    float hl[8];
#pragma unroll
                    for (int e = 0; e < 4; e++) {
                        hl[e]     = p0[e] - __bfloat162float(__float2bfloat16(p0[e]));
                        hl[4 + e] = p1[e] - __bfloat162float(__float2bfloat16(p1[e]));
                    }
                    aph[0] = packbf(p0[0], p0[1]); aph[1] = packbf(p0[2], p0[3]);
                    aph[2] = packbf(p1[0], p1[1]); aph[3] = packbf(p1[2], p1[3]);
                    apl[0] = packbf(hl[0], hl[1]); apl[1] = packbf(hl[2], hl[3]);
                    apl[2] = packbf(hl[4], hl[5]); apl[3] = packbf(hl[6], hl[7]);
                }
#pragma unroll
                for (int g = 0; g < 4; g++) {
                    uint32_t bvh[4], bvl[4];
                    LDSM_X4(bvh[0], bvh[1], bvh[2], bvh[3],
                            bv_base + g * (16 * ASTR) + kt2 * 32);
                    LDSM_X4(bvl[0], bvl[1], bvl[2], bvl[3],
                            bv_base + (VTL_OFF - VTH_OFF) + g * (16 * ASTR) + kt2 * 32);
                    MMA16816(of[2 * g],     aph, bvh[0], bvh[1]);
                    MMA16816(of[2 * g],     aph, bvl[0], bvl[1]);
                    MMA16816(of[2 * g],     apl, bvh[0], bvh[1]);
                    MMA16816(of[2 * g + 1], aph, bvh[2], bvh[3]);
                    MMA16816(of[2 * g + 1], aph, bvl[2], bvl[3]);
                    MMA16816(of[2 * g + 1], apl, bvh[2], bvh[3]);
                }
            }
        }

        // ---- normalize + split-store bf16 hi/lo to [B*T, D] ----
        const float inv0 = 1.0f / l0, inv1 = 1.0f / l1;
        const size_t obase = ((size_t)(b * TSEQ) + r0g) * DMODEL + h * DHEAD + 2 * (lane & 3);
#pragma unroll
        for (int j = 0; j < 8; j++) {
            const float v00 = of[j][0] * inv0, v01 = of[j][1] * inv0;
            const float v10 = of[j][2] * inv1, v11 = of[j][3] * inv1;
            const float h00 = __bfloat162float(__float2bfloat16(v00));
            const float h01 = __bfloat162float(__float2bfloat16(v01));
            const float h10 = __bfloat162float(__float2bfloat16(v10));
            const float h11 = __bfloat162float(__float2bfloat16(v11));
            *reinterpret_cast<uint32_t*>(outh + obase + j * 8) = packbf(v00, v01);
            *reinterpret_cast<uint32_t*>(outl + obase + j * 8) = packbf(v00 - h00, v01 - h01);
            *reinterpret_cast<uint32_t*>(outh + obase + (size_t)8 * DMODEL + j * 8) = packbf(v10, v11);
            *reinterpret_cast<uint32_t*>(outl + obase + (size_t)8 * DMODEL + j * 8) = packbf(v10 - h10, v11 - h11);
        }
    }
}

// ---------------------------------------------------------------------------
// fp32 -> (bf16 hi, bf16 lo) elementwise split, 4 elems/thread
// ---------------------------------------------------------------------------
__global__ __launch_bounds__(256) void convert_split(
    const float* __restrict__ A, __nv_bfloat16* __restrict__ H,
    __nv_bfloat16* __restrict__ L)
{
    const int i = blockIdx.x * blockDim.x + threadIdx.x;
    const float4 v = reinterpret_cast<const float4*>(A)[i];
    __nv_bfloat16 h0 = __float2bfloat16(v.x), h1 = __float2bfloat16(v.y);
    __nv_bfloat16 h2 = __float2bfloat16(v.z), h3 = __float2bfloat16(v.w);
    __nv_bfloat16 l0 = __float2bfloat16(v.x - __bfloat162float(h0));
    __nv_bfloat16 l1 = __float2bfloat16(v.y - __bfloat162float(h1));
    __nv_bfloat16 l2 = __float2bfloat16(v.z - __bfloat162float(h2));
    __nv_bfloat16 l3 = __float2bfloat16(v.w - __bfloat162float(h3));
    reinterpret_cast<__nv_bfloat162*>(H)[2 * i + 0] = __halves2bfloat162(h0, h1);
    reinterpret_cast<__nv_bfloat162*>(H)[2 * i + 1] = __halves2bfloat162(h2, h3);
    reinterpret_cast<__nv_bfloat162*>(L)[2 * i + 0] = __halves2bfloat162(l0, l1);
    reinterpret_cast<__nv_bfloat162*>(L)[2 * i + 1] = __halves2bfloat162(l2, l3);
}

// ---------------------------------------------------------------------------
// W[K][N] fp32 -> Wt_hi/lo[N][K] bf16 (transpose + split), block (32,8)
// ---------------------------------------------------------------------------
__global__ __launch_bounds__(256) void convert_transpose(
    const float* __restrict__ W, __nv_bfloat16* __restrict__ Th,
    __nv_bfloat16* __restrict__ Tl, int K, int N)
{
    __shared__ float tile[32][33];
    const int tx = threadIdx.x, ty = threadIdx.y;
    const int n0 = blockIdx.x * 32, k0 = blockIdx.y * 32;
#pragma unroll
    for (int i = 0; i < 4; i++)
        tile[ty + i * 8][tx] = W[(size_t)(k0 + ty + i * 8) * N + n0 + tx];
    __syncthreads();
#pragma unroll
    for (int i = 0; i < 4; i++) {
        const float v = tile[tx][ty + i * 8];
        const __nv_bfloat16 h = __float2bfloat16(v);
        const __nv_bfloat16 l = __float2bfloat16(v - __bfloat162float(h));
        const size_t o = (size_t)(n0 + ty + i * 8) * K + k0 + tx;
        Th[o] = h;
        Tl[o] = l;
    }
}

// ---------------------------------------------------------------------------
extern "C" void kernel_launch(void* const* d_in, const int* in_sizes, int n_in,
                              void* d_out, int out_size)
{
    const float* x     = (const float*)d_in[0];
    const float* Wqkv  = (const float*)d_in[1];
    const float* bqkv  = (const float*)d_in[2];
    const float* Wproj = (const float*)d_in[3];
    const float* bproj = (const float*)d_in[4];
    const int*   mask  = (const int*)d_in[5];
    float* out = (float*)d_out;

    __nv_bfloat16 *xh, *xl, *qh, *ql, *kh, *kl, *vh, *vl, *vth, *vtl;
    __nv_bfloat16 *ah, *al, *wqh, *wql, *wph, *wpl;
    cudaGetSymbolAddress((void**)&xh, g_xh);   cudaGetSymbolAddress((void**)&xl, g_xl);
    cudaGetSymbolAddress((void**)&qh, g_qh);   cudaGetSymbolAddress((void**)&ql, g_ql);
    cudaGetSymbolAddress((void**)&kh, g_kh);   cudaGetSymbolAddress((void**)&kl, g_kl);
    cudaGetSymbolAddress((void**)&vh, g_vh);   cudaGetSymbolAddress((void**)&vl, g_vl);
    cudaGetSymbolAddress((void**)&vth, g_vth); cudaGetSymbolAddress((void**)&vtl, g_vtl);
    cudaGetSymbolAddress((void**)&ah, g_ah);   cudaGetSymbolAddress((void**)&al, g_al);
    cudaGetSymbolAddress((void**)&wqh, g_wqh); cudaGetSymbolAddress((void**)&wql, g_wql);
    cudaGetSymbolAddress((void**)&wph, g_wph); cudaGetSymbolAddress((void**)&wpl, g_wpl);

    cudaFuncSetAttribute(attn_hmma,
                         cudaFuncAttributeMaxDynamicSharedMemorySize, ATTN_SMEM);
    cudaFuncSetAttribute(gemm_hmma<0>,
                         cudaFuncAttributeMaxDynamicSharedMemorySize, GEMM_SMEM);
    cudaFuncSetAttribute(gemm_hmma<1>,
                         cudaFuncAttributeMaxDynamicSharedMemorySize, GEMM_SMEM);

    // Split-convert input and weights (weights transposed to [N][K])
    convert_split<<<(MROWS * DMODEL) / 1024, 256>>>(x, xh, xl);
    convert_transpose<<<dim3(QKV_N / 32, DMODEL / 32), dim3(32, 8)>>>(
        Wqkv, wqh, wql, DMODEL, QKV_N);
    convert_transpose<<<dim3(DMODEL / 32, DMODEL / 32), dim3(32, 8)>>>(
        Wproj, wph, wpl, DMODEL, DMODEL);

    // 1) QKV GEMM -> split-bf16 Q(scaled)/K/V directly
    gemm_hmma<1><<<dim3(QKV_N / 128, MROWS / 128), 128, GEMM_SMEM>>>(
        xh, xl, wqh, wql, bqkv, nullptr,
        qh, ql, kh, kl, vh, vl, MROWS, QKV_N);

    // 2) V transpose (coalesced, once)
    transpose_v<<<dim3(32, 128), dim3(32, 8)>>>(vh, vl, vth, vtl);

    // 3) Fused causal attention (HMMA split-bf16, cp.async loads)
    attn_hmma<<<dim3(4, BATCH * NH), 256, ATTN_SMEM>>>(
        qh, ql, kh, kl, vth, vtl, mask, ah, al);

    // 4) out = attn @ Wproj + bproj
    gemm_hmma<0><<<dim3(DMODEL / 128, MROWS / 128), 128, GEMM_SMEM>>>(
        ah, al, wph, wpl, bproj, out,
        nullptr, nullptr, nullptr, nullptr, nullptr, nullptr, MROWS, DMODEL);
}

// round 8
// speedup vs baseline: 2.7673x; 1.0090x over previous
#include <cuda_runtime.h>
#include <cuda_bf16.h>
#include <math.h>
#include <cstdint>

// Problem constants
#define BATCH 4
#define TSEQ  1024
#define DMODEL 1024
#define NH 16
#define DHEAD 64
#define QKV_N 3072   // 3*DMODEL
#define MROWS 4096   // BATCH*TSEQ
#define KDIM 1024    // K is 1024 for both GEMMs

// ---------------------------------------------------------------------------
// Scratch (device globals: allocation-free)
// ---------------------------------------------------------------------------
__device__ __nv_bfloat16 g_xh[(size_t)MROWS * DMODEL];
__device__ __nv_bfloat16 g_xl[(size_t)MROWS * DMODEL];
__device__ __nv_bfloat16 g_qh[(size_t)MROWS * DMODEL];   // Q scaled, split
__device__ __nv_bfloat16 g_ql[(size_t)MROWS * DMODEL];
__device__ __nv_bfloat16 g_kh[(size_t)MROWS * DMODEL];
__device__ __nv_bfloat16 g_kl[(size_t)MROWS * DMODEL];
__device__ __nv_bfloat16 g_vh[(size_t)MROWS * DMODEL];   // V [row][h*64+dh]
__device__ __nv_bfloat16 g_vl[(size_t)MROWS * DMODEL];
__device__ __nv_bfloat16 g_vth[(size_t)MROWS * DMODEL];  // V^T [bh][dh][t]
__device__ __nv_bfloat16 g_vtl[(size_t)MROWS * DMODEL];
__device__ __nv_bfloat16 g_ah[(size_t)MROWS * DMODEL];   // attention out hi
__device__ __nv_bfloat16 g_al[(size_t)MROWS * DMODEL];   // attention out lo
__device__ __nv_bfloat16 g_wqh[(size_t)QKV_N * DMODEL];  // Wqkv^T [3072][1024]
__device__ __nv_bfloat16 g_wql[(size_t)QKV_N * DMODEL];
__device__ __nv_bfloat16 g_wph[(size_t)DMODEL * DMODEL]; // Wproj^T [1024][1024]
__device__ __nv_bfloat16 g_wpl[(size_t)DMODEL * DMODEL];

// ---------------------------------------------------------------------------
// PTX helpers (base ISA only — compute_103 virtual arch, no tcgen05)
// ---------------------------------------------------------------------------
__device__ __forceinline__ uint32_t smem_to_u32(const void* p) {
    uint32_t a;
    asm("{ .reg .u64 t; cvta.to.shared.u64 t, %1; cvt.u32.u64 %0, t; }"
        : "=r"(a) : "l"(p));
    return a;
}

#define CP_ASYNC16(smem, gptr) \
    asm volatile("cp.async.cg.shared.global [%0], [%1], 16;" \
        :: "r"(smem), "l"(gptr) : "memory")
#define CP_COMMIT() asm volatile("cp.async.commit_group;" ::: "memory")
#define CP_WAIT(n)  asm volatile("cp.async.wait_group %0;" :: "n"(n) : "memory")

#define LDSM_X4(r0, r1, r2, r3, addr) \
    asm volatile("ldmatrix.sync.aligned.m8n8.x4.shared.b16 {%0,%1,%2,%3}, [%4];" \
        : "=r"(r0), "=r"(r1), "=r"(r2), "=r"(r3) : "r"(addr))

#define MMA16816(c, a, b0, b1) \
    asm volatile("mma.sync.aligned.m16n8k16.row.col.f32.bf16.bf16.f32 " \
        "{%0,%1,%2,%3}, {%4,%5,%6,%7}, {%8,%9}, {%0,%1,%2,%3};" \
        : "+f"((c)[0]), "+f"((c)[1]), "+f"((c)[2]), "+f"((c)[3]) \
        : "r"((a)[0]), "r"((a)[1]), "r"((a)[2]), "r"((a)[3]), \
          "r"(b0), "r"(b1))

// pack two floats to bf16x2 (lo addr half = first arg)
__device__ __forceinline__ uint32_t packbf(float lo, float hi) {
    uint32_t r;
    asm("cvt.rn.bf16x2.f32 %0, %1, %2;" : "=r"(r) : "f"(hi), "f"(lo));
    return r;
}

// Swizzled byte offset within one 8KB matrix tile (128 rows x 32 bf16):
// row-pair lines of 128B, chunk3 = (r&1)*4 + ch (ch = 16B k-chunk 0..3),
// swizzled with XOR (r>>1)&7.
__device__ __forceinline__ uint32_t sw_off(int r, int ch) {
    const uint32_t chunk3 = (uint32_t)(((r & 1) << 2) | ch);
    return (uint32_t)((r >> 1) * 128) + ((chunk3 ^ ((uint32_t)(r >> 1) & 7u)) << 4);
}

// ---------------------------------------------------------------------------
// Split-bf16 HMMA GEMM: C = (Ah+Al)[M,K] @ ((Bh+Bl)[N,K])^T + bias
// CTA 128x128, K-tile 32, 3-stage cp.async (swizzled smem, 32KB/stage),
// 2 CTAs/SM, 4 warps (2x2), warp tile 64x64.
// MODE 0: fp32 C out.  MODE 1: QKV epilogue -> split-bf16 q(scaled)/k/v.
// ---------------------------------------------------------------------------
#define MATB   8192
#define STAGEB 32768
#define GEMM_SMEM (3 * STAGEB)

template <int MODE>
__global__ __launch_bounds__(128, 2) void gemm_hmma(
    const __nv_bfloat16* __restrict__ Ah, const __nv_bfloat16* __restrict__ Al,
    const __nv_bfloat16* __restrict__ Bh, const __nv_bfloat16* __restrict__ Bl,
    const float* __restrict__ bias, float* __restrict__ C,
    __nv_bfloat16* __restrict__ qh, __nv_bfloat16* __restrict__ ql,
    __nv_bfloat16* __restrict__ kh, __nv_bfloat16* __restrict__ kl,
    __nv_bfloat16* __restrict__ vh, __nv_bfloat16* __restrict__ vl,
    int M, int Ntot)
{
    extern __shared__ char dsm[];
    const uint32_t sb = smem_to_u32(dsm);

    const int t    = threadIdx.x;
    const int lane = t & 31;
    const int wid  = t >> 5;
    const int wm   = wid >> 1;
    const int wn   = wid & 1;
    const int bm   = blockIdx.y << 7;
    const int bn   = blockIdx.x << 7;

    // cp.async plan: 4 matrices x 512 chunks(16B) / 128 thr = 16/thread
    const int rbase = t >> 2;       // 0..31
    const int ch0   = t & 3;        // k-chunk 0..3
    uint32_t soff[16];
    const __nv_bfloat16* gp[16];
    {
        const __nv_bfloat16* bases[4] = {Ah, Al, Bh, Bl};
        const int rb[4] = {bm, bm, bn, bn};
#pragma unroll
        for (int m = 0; m < 4; m++)
#pragma unroll
            for (int hh = 0; hh < 4; hh++) {
                const int r = rbase + hh * 32;
                soff[m * 4 + hh] = (uint32_t)(m * MATB) + sw_off(r, ch0);
                gp[m * 4 + hh]   = bases[m] + (size_t)(rb[m] + r) * KDIM + ch0 * 8;
            }
    }

    // ldsm bases (swizzled, ks=0); ks toggles byte bit5 via XOR, mi/g add 1024B
    const uint32_t a_base = sw_off(wm * 64 + (lane & 15), lane >> 4);
    const uint32_t b_base = (uint32_t)(2 * MATB) +
        sw_off(wn * 64 + (lane & 7) + ((lane >> 4) << 3), (lane >> 3) & 1);

    float acc[4][8][4];
#pragma unroll
    for (int mi = 0; mi < 4; mi++)
#pragma unroll
        for (int ni = 0; ni < 8; ni++)
#pragma unroll
            for (int e = 0; e < 4; e++) acc[mi][ni][e] = 0.0f;

    const int NT = KDIM / 32;

    // prologue: stages 0 and 1
#pragma unroll
    for (int s = 0; s < 2; s++) {
        const uint32_t st = sb + (uint32_t)s * STAGEB;
        const int ko = s * 32;
#pragma unroll
        for (int i = 0; i < 16; i++) CP_ASYNC16(st + soff[i], gp[i] + ko);
        CP_COMMIT();
    }

    int buf = 0, nbuf = 2;
#pragma unroll 1
    for (int kt = 0; kt < NT; kt++) {
        CP_WAIT(1);
        __syncthreads();

        // issue stage kt+2 into nbuf (its last reader finished at kt-1,
        // ordered by the barrier above)
        if (kt + 2 < NT) {
            const uint32_t st = sb + (uint32_t)nbuf * STAGEB;
            const int ko = (kt + 2) * 32;
#pragma unroll
            for (int i = 0; i < 16; i++) CP_ASYNC16(st + soff[i], gp[i] + ko);
        }
        CP_COMMIT();

        const uint32_t stg = sb + (uint32_t)buf * STAGEB;
        buf = (buf == 2) ? 0 : buf + 1;
        nbuf = (nbuf == 2) ? 0 : nbuf + 1;

#pragma unroll
        for (int ks = 0; ks < 2; ks++) {
            const uint32_t ksx = (uint32_t)(ks << 5);
            uint32_t ah[4][4], al[4][4];
#pragma unroll
            for (int mi = 0; mi < 4; mi++) {
                const uint32_t ao = (a_base + (uint32_t)(mi * 1024)) ^ ksx;
                LDSM_X4(ah[mi][0], ah[mi][1], ah[mi][2], ah[mi][3], stg + ao);
                LDSM_X4(al[mi][0], al[mi][1], al[mi][2], al[mi][3], stg + MATB + ao);
            }
            uint32_t rbh[4][4], rbl[4][4];
#pragma unroll
            for (int g = 0; g < 4; g++) {
                const uint32_t bo = (b_base + (uint32_t)(g * 1024)) ^ ksx;
                LDSM_X4(rbh[g][0], rbh[g][1], rbh[g][2], rbh[g][3], stg + bo);
                LDSM_X4(rbl[g][0], rbl[g][1], rbl[g][2], rbl[g][3], stg + MATB + bo);
            }
#pragma unroll
            for (int mi = 0; mi < 4; mi++)
#pragma unroll
                for (int ni = 0; ni < 8; ni++) {
                    const int g = ni >> 1, u = (ni & 1) * 2;
                    MMA16816(acc[mi][ni], ah[mi], rbh[g][u], rbh[g][u + 1]);
                    MMA16816(acc[mi][ni], ah[mi], rbl[g][u], rbl[g][u + 1]);
                    MMA16816(acc[mi][ni], al[mi], rbh[g][u], rbh[g][u + 1]);
                }
        }
    }

    // ---- epilogue ----
    const int er = bm + wm * 64 + (lane >> 2);
    const int ec = bn + wn * 64 + (lane & 3) * 2;

    if (MODE == 0) {
#pragma unroll
        for (int ni = 0; ni < 8; ni++) {
            const int col = ec + ni * 8;
            const float2 bv = *reinterpret_cast<const float2*>(bias + col);
#pragma unroll
            for (int mi = 0; mi < 4; mi++) {
                const int r0 = er + mi * 16;
                float2 o0, o1;
                o0.x = acc[mi][ni][0] + bv.x;
                o0.y = acc[mi][ni][1] + bv.y;
                o1.x = acc[mi][ni][2] + bv.x;
                o1.y = acc[mi][ni][3] + bv.y;
                *reinterpret_cast<float2*>(C + (size_t)r0 * Ntot + col) = o0;
                *reinterpret_cast<float2*>(C + (size_t)(r0 + 8) * Ntot + col) = o1;
            }
        }
    } else {
        // QKV epilogue: seg 0=Q(scale 0.125), 1=K, 2=V -> split-bf16
        const int seg = bn >> 10;
        __nv_bfloat16 *H, *L;
        float scale = 1.0f;
        if (seg == 0)      { H = qh; L = ql; scale = 0.125f; }
        else if (seg == 1) { H = kh; L = kl; }
        else               { H = vh; L = vl; }
        const int ecl = ec & 1023;
#pragma unroll
        for (int ni = 0; ni < 8; ni++) {
            const int col = ec + ni * 8;
            const float2 bv = *reinterpret_cast<const float2*>(bias + col);
            const int cl = ecl + ni * 8;
#pragma unroll
            for (int mi = 0; mi < 4; mi++) {
                const int r0 = er + mi * 16;
                const float v00 = (acc[mi][ni][0] + bv.x) * scale;
                const float v01 = (acc[mi][ni][1] + bv.y) * scale;
                const float v10 = (acc[mi][ni][2] + bv.x) * scale;
                const float v11 = (acc[mi][ni][3] + bv.y) * scale;
                const float h00 = __bfloat162float(__float2bfloat16(v00));
                const float h01 = __bfloat162float(__float2bfloat16(v01));
                const float h10 = __bfloat162float(__float2bfloat16(v10));
                const float h11 = __bfloat162float(__float2bfloat16(v11));
                *reinterpret_cast<uint32_t*>(H + (size_t)r0 * 1024 + cl) = packbf(v00, v01);
                *reinterpret_cast<uint32_t*>(L + (size_t)r0 * 1024 + cl) = packbf(v00 - h00, v01 - h01);
                *reinterpret_cast<uint32_t*>(H + (size_t)(r0 + 8) * 1024 + cl) = packbf(v10, v11);
                *reinterpret_cast<uint32_t*>(L + (size_t)(r0 + 8) * 1024 + cl) = packbf(v10 - h10, v11 - h11);
            }
        }
    }
}

// ---------------------------------------------------------------------------
// V transpose: vh/vl [B*T][1024] -> vth/vtl [(b*16+h)*64+dh][1024] (col = t)
// ---------------------------------------------------------------------------
__global__ __launch_bounds__(256) void transpose_v(
    const __nv_bfloat16* __restrict__ vh, const __nv_bfloat16* __restrict__ vl,
    __nv_bfloat16* __restrict__ vth, __nv_bfloat16* __restrict__ vtl)
{
    __shared__ __nv_bfloat16 th[32][33], tl[32][33];
    const int tx = threadIdx.x, ty = threadIdx.y;
    const int c0 = blockIdx.x * 32;   // V column (h*64+dh)
    const int r0 = blockIdx.y * 32;   // token row
#pragma unroll
    for (int i = 0; i < 4; i++) {
        const size_t src = (size_t)(r0 + ty + i * 8) * 1024 + c0 + tx;
        th[ty + i * 8][tx] = vh[src];
        tl[ty + i * 8][tx] = vl[src];
    }
    __syncthreads();
    const int b = r0 >> 10;
    const int tbase = (r0 & 1023) + tx;
#pragma unroll
    for (int i = 0; i < 4; i++) {
        const int cp = c0 + ty + i * 8;
        const int hh = cp >> 6, dh = cp & 63;
        const size_t dst = (size_t)(((b * 16 + hh) * 64) + dh) * 1024 + tbase;
        vth[dst] = th[tx][ty + i * 8];
        vtl[dst] = tl[tx][ty + i * 8];
    }
}

// ---------------------------------------------------------------------------
// HMMA flash attention, split-bf16 3-product; all operands pre-split bf16.
// K/V (and mask) double-buffered: loads for kt+1 overlap compute of kt.
// Grid (4, B*H), 2 passes: q-tiles {7-bx, bx} (BQ=128). 8 warps x 16 rows.
// ---------------------------------------------------------------------------
#define ASTR 144
#define QH_OFF 0
#define QL_OFF 18432
#define K_OFF  36864            // 2 buffers x (Kh 9216 + Kl 9216)
#define V_OFF  73728            // 2 buffers x (Vth 9216 + Vtl 9216)
#define KVBUF  18432            // buffer stride
#define MSK_OFF 110592          // 2 x 64 floats
#define ATTN_SMEM (110592 + 512)

__global__ __launch_bounds__(256, 2) void attn_hmma(
    const __nv_bfloat16* __restrict__ qh, const __nv_bfloat16* __restrict__ ql,
    const __nv_bfloat16* __restrict__ kh, const __nv_bfloat16* __restrict__ kl,
    const __nv_bfloat16* __restrict__ vth, const __nv_bfloat16* __restrict__ vtl,
    const int* __restrict__ mask,
    __nv_bfloat16* __restrict__ outh, __nv_bfloat16* __restrict__ outl)
{
    extern __shared__ char smc[];
    const uint32_t sb = smem_to_u32(smc);

    const int t    = threadIdx.x;
    const int lane = t & 31;
    const int w    = t >> 5;
    const int bh   = blockIdx.y;
    const int b    = bh >> 4;
    const int h    = bh & 15;
    float* msk_s = (float*)(smc + MSK_OFF);

    const uint32_t aq_base = sb + QH_OFF +
        (uint32_t)((16 * w + (lane & 15)) * ASTR + (lane >> 4) * 16);
    const uint32_t bk_base = sb + K_OFF +
        (uint32_t)(((lane & 7) + ((lane >> 4) << 3)) * ASTR + ((lane >> 3) & 1) * 16);
    const uint32_t bv_base = sb + V_OFF +
        (uint32_t)(((lane & 7) + ((lane >> 4) << 3)) * ASTR + ((lane >> 3) & 1) * 16);

    // per-thread K/V load plan pieces (row/chunk fixed across iterations)
    const int kv_m   = 0;  (void)kv_m;

#pragma unroll 1
    for (int pass = 0; pass < 2; pass++) {
        const int qt = pass ? (int)blockIdx.x : 7 - (int)blockIdx.x;
        __syncthreads();   // previous pass readers of Q / buf0 done

        // ---- Q tile: 128 rows x 64 bf16 (hi+lo) = 2048 16B chunks ----
#pragma unroll
        for (int p = 0; p < 8; p++) {
            const int c   = t + (p << 8);        // 0..2047
            const int m   = c >> 10;             // 0=hi 1=lo
            const int idx = c & 1023;
            const int row = idx >> 3;
            const int ch  = idx & 7;
            const __nv_bfloat16* src = (m ? ql : qh) +
                (size_t)(b * 1024 + qt * 128 + row) * 1024 + h * 64 + ch * 8;
            CP_ASYNC16(sb + (m ? QL_OFF : QH_OFF) + row * ASTR + ch * 16, src);
        }
        CP_COMMIT();

        const int kmax = 2 * qt + 1;

        // ---- prologue: K/V for kt=0 into buffer 0, mask[0] ----
#pragma unroll
        for (int p = 0; p < 8; p++) {
            const int c   = t + (p << 8);    // 0..2047
            const int m   = c >> 9;          // 0=Kh 1=Kl 2=Vth 3=Vtl
            const int idx = c & 511;
            const int row = idx >> 3;
            const int ch  = idx & 7;
            const __nv_bfloat16* src;
            uint32_t dst;
            if (m == 0) {
                src = kh + (size_t)(b * 1024 + row) * 1024 + h * 64 + ch * 8;
                dst = sb + K_OFF + row * ASTR + ch * 16;
            } else if (m == 1) {
                src = kl + (size_t)(b * 1024 + row) * 1024 + h * 64 + ch * 8;
                dst = sb + K_OFF + 9216 + row * ASTR + ch * 16;
            } else if (m == 2) {
                src = vth + (size_t)(bh * 64 + row) * 1024 + ch * 8;
                dst = sb + V_OFF + row * ASTR + ch * 16;
            } else {
                src = vtl + (size_t)(bh * 64 + row) * 1024 + ch * 8;
                dst = sb + V_OFF + 9216 + row * ASTR + ch * 16;
            }
            CP_ASYNC16(dst, src);
        }
        if (t < 64)
            msk_s[t] = (mask[b * TSEQ + t] != 0) ? 0.0f : -1e30f;
        CP_COMMIT();

        float m0 = -1e30f, m1 = -1e30f, l0 = 0.0f, l1 = 0.0f;
        float of[8][4];
#pragma unroll
        for (int j = 0; j < 8; j++)
#pragma unroll
            for (int e = 0; e < 4; e++) of[j][e] = 0.0f;

        const int qrow_w = qt * 128 + 16 * w;
        const int r0g = qrow_w + (lane >> 2);

#pragma unroll 1
        for (int kt = 0; kt <= kmax; kt++) {
            CP_WAIT(0);
            __syncthreads();   // kt data visible to all; kt-1 compute done

            // ---- prefetch kt+1 into the alternate buffer (overlaps compute)
            if (kt < kmax) {
                const uint32_t kb = (uint32_t)(((kt + 1) & 1) * KVBUF);
#pragma unroll
                for (int p = 0; p < 8; p++) {
                    const int c   = t + (p << 8);
                    const int m   = c >> 9;
                    const int idx = c & 511;
                    const int row = idx >> 3;
                    const int ch  = idx & 7;
                    const __nv_bfloat16* src;
                    uint32_t dst;
                    if (m == 0) {
                        src = kh + (size_t)(b * 1024 + (kt + 1) * 64 + row) * 1024 + h * 64 + ch * 8;
                        dst = sb + K_OFF + kb + row * ASTR + ch * 16;
                    } else if (m == 1) {
                        src = kl + (size_t)(b * 1024 + (kt + 1) * 64 + row) * 1024 + h * 64 + ch * 8;
                        dst = sb + K_OFF + kb + 9216 + row * ASTR + ch * 16;
                    } else if (m == 2) {
                        src = vth + (size_t)(bh * 64 + row) * 1024 + (kt + 1) * 64 + ch * 8;
                        dst = sb + V_OFF + kb + row * ASTR + ch * 16;
                    } else {
                        src = vtl + (size_t)(bh * 64 + row) * 1024 + (kt + 1) * 64 + ch * 8;
                        dst = sb + V_OFF + kb + 9216 + row * ASTR + ch * 16;
                    }
                    CP_ASYNC16(dst, src);
                }
                if (t < 64)
                    msk_s[((kt + 1) & 1) * 64 + t] =
                        (mask[b * TSEQ + (kt + 1) * 64 + t] != 0) ? 0.0f : -1e30f;
            }
            CP_COMMIT();

            const uint32_t kb = (uint32_t)((kt & 1) * KVBUF);
            const float* msk = msk_s + (kt & 1) * 64;

            // ---- S = Q @ K^T ----
            float s[8][4];
#pragma unroll
            for (int j = 0; j < 8; j++)
#pragma unroll
                for (int e = 0; e < 4; e++) s[j][e] = 0.0f;

#pragma unroll
            for (int ks = 0; ks < 4; ks++) {
                uint32_t aqh[4], aql[4];
                LDSM_X4(aqh[0], aqh[1], aqh[2], aqh[3], aq_base + ks * 32);
                LDSM_X4(aql[0], aql[1], aql[2], aql[3],
                        aq_base + (QL_OFF - QH_OFF) + ks * 32);
#pragma unroll
                for (int g = 0; g < 4; g++) {
                    uint32_t bkh[4], bkl[4];
                    LDSM_X4(bkh[0], bkh[1], bkh[2], bkh[3],
                            bk_base + kb + g * (16 * ASTR) + ks * 32);
                    LDSM_X4(bkl[0], bkl[1], bkl[2], bkl[3],
                            bk_base + kb + 9216 + g * (16 * ASTR) + ks * 32);
                    MMA16816(s[2 * g],     aqh, bkh[0], bkh[1]);
                    MMA16816(s[2 * g],     aqh, bkl[0], bkl[1]);
                    MMA16816(s[2 * g],     aql, bkh[0], bkh[1]);
                    MMA16816(s[2 * g + 1], aqh, bkh[2], bkh[3]);
                    MMA16816(s[2 * g + 1], aqh, bkl[2], bkl[3]);
                    MMA16816(s[2 * g + 1], aql, bkh[2], bkh[3]);
                }
            }

            // ---- mask + causal ----
            const int lc = 2 * (lane & 3);
#pragma unroll
            for (int j = 0; j < 8; j++) {
                const float mj0 = msk[j * 8 + lc];
                const float mj1 = msk[j * 8 + lc + 1];
                s[j][0] += mj0; s[j][1] += mj1;
                s[j][2] += mj0; s[j][3] += mj1;
            }
            if (kt * 64 + 63 > qrow_w) {
                const int r1g = r0g + 8;
#pragma unroll
                for (int j = 0; j < 8; j++) {
                    const int c0 = kt * 64 + j * 8 + lc;
                    if (c0     > r0g) s[j][0] = -1e30f;
                    if (c0 + 1 > r0g) s[j][1] = -1e30f;
                    if (c0     > r1g) s[j][2] = -1e30f;
                    if (c0 + 1 > r1g) s[j][3] = -1e30f;
                }
            }

            // ---- online softmax ----
            float rm0 = -1e30f, rm1 = -1e30f;
#pragma unroll
            for (int j = 0; j < 8; j++) {
                rm0 = fmaxf(rm0, fmaxf(s[j][0], s[j][1]));
                rm1 = fmaxf(rm1, fmaxf(s[j][2], s[j][3]));
            }
            rm0 = fmaxf(rm0, __shfl_xor_sync(0xffffffffu, rm0, 1));
            rm0 = fmaxf(rm0, __shfl_xor_sync(0xffffffffu, rm0, 2));
            rm1 = fmaxf(rm1, __shfl_xor_sync(0xffffffffu, rm1, 1));
            rm1 = fmaxf(rm1, __shfl_xor_sync(0xffffffffu, rm1, 2));
            const float mn0 = fmaxf(m0, rm0), mn1 = fmaxf(m1, rm1);
            const float al0 = __expf(m0 - mn0), al1 = __expf(m1 - mn1);
            m0 = mn0; m1 = mn1;
            float ls0 = 0.0f, ls1 = 0.0f;
#pragma unroll
            for (int j = 0; j < 8; j++) {
                s[j][0] = __expf(s[j][0] - mn0); ls0 += s[j][0];
                s[j][1] = __expf(s[j][1] - mn0); ls0 += s[j][1];
                s[j][2] = __expf(s[j][2] - mn1); ls1 += s[j][2];
                s[j][3] = __expf(s[j][3] - mn1); ls1 += s[j][3];
            }
            ls0 += __shfl_xor_sync(0xffffffffu, ls0, 1);
            ls0 += __shfl_xor_sync(0xffffffffu, ls0, 2);
            ls1 += __shfl_xor_sync(0xffffffffu, ls1, 1);
            ls1 += __shfl_xor_sync(0xffffffffu, ls1, 2);
            l0 = l0 * al0 + ls0;
            l1 = l1 * al1 + ls1;
#pragma unroll
            for (int j = 0; j < 8; j++) {
                of[j][0] *= al0; of[j][1] *= al0;
                of[j][2] *= al1; of[j][3] *= al1;
            }

            // ---- O += P @ V ----
#pragma unroll
            for (int kt2 = 0; kt2 < 4; kt2++) {
                uint32_t aph[4], apl[4];
                {
                    const float* p0 = s[2 * kt2];
                    const float* p1 = s[2 * kt2 + 1];
                    float hl[8];
#pragma unroll
                    for (int e = 0; e < 4; e++) {
                        hl[e]     = p0[e] - __bfloat162float(__float2bfloat16(p0[e]));
                        hl[4 + e] = p1[e] - __bfloat162float(__float2bfloat16(p1[e]));
                    }
                    aph[0] = packbf(p0[0], p0[1]); aph[1] = packbf(p0[2], p0[3]);
                    aph[2] = packbf(p1[0], p1[1]); aph[3] = packbf(p1[2], p1[3]);
                    apl[0] = packbf(hl[0], hl[1]); apl[1] = packbf(hl[2], hl[3]);
                    apl[2] = packbf(hl[4], hl[5]); apl[3] = packbf(hl[6], hl[7]);
                }
#pragma unroll
                for (int g = 0; g < 4; g++) {
                    uint32_t bvh[4], bvl[4];
                    LDSM_X4(bvh[0], bvh[1], bvh[2], bvh[3],
                            bv_base + kb + g * (16 * ASTR) + kt2 * 32);
                    LDSM_X4(bvl[0], bvl[1], bvl[2], bvl[3],
                            bv_base + kb + 9216 + g * (16 * ASTR) + kt2 * 32);
                    MMA16816(of[2 * g],     aph, bvh[0], bvh[1]);
                    MMA16816(of[2 * g],     aph, bvl[0], bvl[1]);
                    MMA16816(of[2 * g],     apl, bvh[0], bvh[1]);
                    MMA16816(of[2 * g + 1], aph, bvh[2], bvh[3]);
                    MMA16816(of[2 * g + 1], aph, bvl[2], bvl[3]);
                    MMA16816(of[2 * g + 1], apl, bvh[2], bvh[3]);
                }
            }
        }

        // ---- normalize + split-store bf16 hi/lo to [B*T, D] ----
        const float inv0 = 1.0f / l0, inv1 = 1.0f / l1;
        const size_t obase = ((size_t)(b * TSEQ) + r0g) * DMODEL + h * DHEAD + 2 * (lane & 3);
#pragma unroll
        for (int j = 0; j < 8; j++) {
            const float v00 = of[j][0] * inv0, v01 = of[j][1] * inv0;
            const float v10 = of[j][2] * inv1, v11 = of[j][3] * inv1;
            const float h00 = __bfloat162float(__float2bfloat16(v00));
            const float h01 = __bfloat162float(__float2bfloat16(v01));
            const float h10 = __bfloat162float(__float2bfloat16(v10));
            const float h11 = __bfloat162float(__float2bfloat16(v11));
            *reinterpret_cast<uint32_t*>(outh + obase + j * 8) = packbf(v00, v01);
            *reinterpret_cast<uint32_t*>(outl + obase + j * 8) = packbf(v00 - h00, v01 - h01);
            *reinterpret_cast<uint32_t*>(outh + obase + (size_t)8 * DMODEL + j * 8) = packbf(v10, v11);
            *reinterpret_cast<uint32_t*>(outl + obase + (size_t)8 * DMODEL + j * 8) = packbf(v10 - h10, v11 - h11);
        }
    }
}

// ---------------------------------------------------------------------------
// fp32 -> (bf16 hi, bf16 lo) elementwise split, 4 elems/thread
// ---------------------------------------------------------------------------
__global__ __launch_bounds__(256) void convert_split(
    const float* __restrict__ A, __nv_bfloat16* __restrict__ H,
    __nv_bfloat16* __restrict__ L)
{
    const int i = blockIdx.x * blockDim.x + threadIdx.x;
    const float4 v = reinterpret_cast<const float4*>(A)[i];
    __nv_bfloat16 h0 = __float2bfloat16(v.x), h1 = __float2bfloat16(v.y);
    __nv_bfloat16 h2 = __float2bfloat16(v.z), h3 = __float2bfloat16(v.w);
    __nv_bfloat16 l0 = __float2bfloat16(v.x - __bfloat162float(h0));
    __nv_bfloat16 l1 = __float2bfloat16(v.y - __bfloat162float(h1));
    __nv_bfloat16 l2 = __float2bfloat16(v.z - __bfloat162float(h2));
    __nv_bfloat16 l3 = __float2bfloat16(v.w - __bfloat162float(h3));
    reinterpret_cast<__nv_bfloat162*>(H)[2 * i + 0] = __halves2bfloat162(h0, h1);
    reinterpret_cast<__nv_bfloat162*>(H)[2 * i + 1] = __halves2bfloat162(h2, h3);
    reinterpret_cast<__nv_bfloat162*>(L)[2 * i + 0] = __halves2bfloat162(l0, l1);
    reinterpret_cast<__nv_bfloat162*>(L)[2 * i + 1] = __halves2bfloat162(l2, l3);
}

// ---------------------------------------------------------------------------
// W[K][N] fp32 -> Wt_hi/lo[N][K] bf16 (transpose + split), block (32,8)
// ---------------------------------------------------------------------------
__global__ __launch_bounds__(256) void convert_transpose(
    const float* __restrict__ W, __nv_bfloat16* __restrict__ Th,
    __nv_bfloat16* __restrict__ Tl, int K, int N)
{
    __shared__ float tile[32][33];
    const int tx = threadIdx.x, ty = threadIdx.y;
    const int n0 = blockIdx.x * 32, k0 = blockIdx.y * 32;
#pragma unroll
    for (int i = 0; i < 4; i++)
        tile[ty + i * 8][tx] = W[(size_t)(k0 + ty + i * 8) * N + n0 + tx];
    __syncthreads();
#pragma unroll
    for (int i = 0; i < 4; i++) {
        const float v = tile[tx][ty + i * 8];
        const __nv_bfloat16 h = __float2bfloat16(v);
        const __nv_bfloat16 l = __float2bfloat16(v - __bfloat162float(h));
        const size_t o = (size_t)(n0 + ty + i * 8) * K + k0 + tx;
        Th[o] = h;
        Tl[o] = l;
    }
}

// ---------------------------------------------------------------------------
extern "C" void kernel_launch(void* const* d_in, const int* in_sizes, int n_in,
                              void* d_out, int out_size)
{
    const float* x     = (const float*)d_in[0];
    const float* Wqkv  = (const float*)d_in[1];
    const float* bqkv  = (const float*)d_in[2];
    const float* Wproj = (const float*)d_in[3];
    const float* bproj = (const float*)d_in[4];
    const int*   mask  = (const int*)d_in[5];
    float* out = (float*)d_out;

    __nv_bfloat16 *xh, *xl, *qh, *ql, *kh, *kl, *vh, *vl, *vth, *vtl;
    __nv_bfloat16 *ah, *al, *wqh, *wql, *wph, *wpl;
    cudaGetSymbolAddress((void**)&xh, g_xh);   cudaGetSymbolAddress((void**)&xl, g_xl);
    cudaGetSymbolAddress((void**)&qh, g_qh);   cudaGetSymbolAddress((void**)&ql, g_ql);
    cudaGetSymbolAddress((void**)&kh, g_kh);   cudaGetSymbolAddress((void**)&kl, g_kl);
    cudaGetSymbolAddress((void**)&vh, g_vh);   cudaGetSymbolAddress((void**)&vl, g_vl);
    cudaGetSymbolAddress((void**)&vth, g_vth); cudaGetSymbolAddress((void**)&vtl, g_vtl);
    cudaGetSymbolAddress((void**)&ah, g_ah);   cudaGetSymbolAddress((void**)&al, g_al);
    cudaGetSymbolAddress((void**)&wqh, g_wqh); cudaGetSymbolAddress((void**)&wql, g_wql);
    cudaGetSymbolAddress((void**)&wph, g_wph); cudaGetSymbolAddress((void**)&wpl, g_wpl);

    cudaFuncSetAttribute(attn_hmma,
                         cudaFuncAttributeMaxDynamicSharedMemorySize, ATTN_SMEM);
    cudaFuncSetAttribute(gemm_hmma<0>,
                         cudaFuncAttributeMaxDynamicSharedMemorySize, GEMM_SMEM);
    cudaFuncSetAttribute(gemm_hmma<1>,
                         cudaFuncAttributeMaxDynamicSharedMemorySize, GEMM_SMEM);

    // Split-convert input and weights (weights transposed to [N][K])
    convert_split<<<(MROWS * DMODEL) / 1024, 256>>>(x, xh, xl);
    convert_transpose<<<dim3(QKV_N / 32, DMODEL / 32), dim3(32, 8)>>>(
        Wqkv, wqh, wql, DMODEL, QKV_N);
    convert_transpose<<<dim3(DMODEL / 32, DMODEL / 32), dim3(32, 8)>>>(
        Wproj, wph, wpl, DMODEL, DMODEL);

    // 1) QKV GEMM -> split-bf16 Q(scaled)/K/V directly
    gemm_hmma<1><<<dim3(QKV_N / 128, MROWS / 128), 128, GEMM_SMEM>>>(
        xh, xl, wqh, wql, bqkv, nullptr,
        qh, ql, kh, kl, vh, vl, MROWS, QKV_N);

    // 2) V transpose (coalesced, once)
    transpose_v<<<dim3(32, 128), dim3(32, 8)>>>(vh, vl, vth, vtl);

    // 3) Fused causal attention (HMMA split-bf16, double-buffered K/V)
    attn_hmma<<<dim3(4, BATCH * NH), 256, ATTN_SMEM>>>(
        qh, ql, kh, kl, vth, vtl, mask, ah, al);

    // 4) out = attn @ Wproj + bproj
    gemm_hmma<0><<<dim3(DMODEL / 128, MROWS / 128), 128, GEMM_SMEM>>>(
        ah, al, wph, wpl, bproj, out,
        nullptr, nullptr, nullptr, nullptr, nullptr, nullptr, MROWS, DMODEL);
}

// round 9
// speedup vs baseline: 3.3569x; 1.2130x over previous
#include <cuda_runtime.h>
#include <cuda_bf16.h>
#include <math.h>
#include <cstdint>

// Problem constants
#define BATCH 4
#define TSEQ  1024
#define DMODEL 1024
#define NH 16
#define DHEAD 64
#define QKV_N 3072   // 3*DMODEL
#define MROWS 4096   // BATCH*TSEQ
#define KDIM 1024    // K is 1024 for both GEMMs
#define NTK  32      // k-tiles (KDIM/32)

// ---------------------------------------------------------------------------
// Scratch (device globals: allocation-free)
// ---------------------------------------------------------------------------
__device__ float g_xp[(size_t)MROWS * KDIM];            // x, fragment-permuted tf32
__device__ float g_wqp[(size_t)QKV_N * KDIM];           // Wqkv^T permuted tf32
__device__ float g_wpp[(size_t)DMODEL * KDIM];          // Wproj^T permuted tf32
__device__ float g_aop[(size_t)MROWS * KDIM];           // attn out, permuted tf32
__device__ __nv_bfloat16 g_qh[(size_t)MROWS * DMODEL];  // Q scaled, split
__device__ __nv_bfloat16 g_ql[(size_t)MROWS * DMODEL];
__device__ __nv_bfloat16 g_kh[(size_t)MROWS * DMODEL];
__device__ __nv_bfloat16 g_kl[(size_t)MROWS * DMODEL];
__device__ __nv_bfloat16 g_vh[(size_t)MROWS * DMODEL];  // V [row][h*64+dh]
__device__ __nv_bfloat16 g_vl[(size_t)MROWS * DMODEL];
__device__ __nv_bfloat16 g_vth[(size_t)MROWS * DMODEL]; // V^T [bh][dh][t]
__device__ __nv_bfloat16 g_vtl[(size_t)MROWS * DMODEL];

// ---------------------------------------------------------------------------
// PTX helpers (base ISA only — compute_103 virtual arch, no tcgen05)
// ---------------------------------------------------------------------------
__device__ __forceinline__ uint32_t smem_to_u32(const void* p) {
    uint32_t a;
    asm("{ .reg .u64 t; cvta.to.shared.u64 t, %1; cvt.u32.u64 %0, t; }"
        : "=r"(a) : "l"(p));
    return a;
}

#define CP_ASYNC16(smem, gptr) \
    asm volatile("cp.async.cg.shared.global [%0], [%1], 16;" \
        :: "r"(smem), "l"(gptr) : "memory")
#define CP_COMMIT() asm volatile("cp.async.commit_group;" ::: "memory")
#define CP_WAIT(n)  asm volatile("cp.async.wait_group %0;" :: "n"(n) : "memory")

#define LDSM_X4(r0, r1, r2, r3, addr) \
    asm volatile("ldmatrix.sync.aligned.m8n8.x4.shared.b16 {%0,%1,%2,%3}, [%4];" \
        : "=r"(r0), "=r"(r1), "=r"(r2), "=r"(r3) : "r"(addr))

#define LDS128U(r, addr) \
    asm volatile("ld.shared.v4.b32 {%0,%1,%2,%3}, [%4];" \
        : "=r"((r)[0]), "=r"((r)[1]), "=r"((r)[2]), "=r"((r)[3]) : "r"(addr))

#define MMA16816(c, a, b0, b1) \
    asm volatile("mma.sync.aligned.m16n8k16.row.col.f32.bf16.bf16.f32 " \
        "{%0,%1,%2,%3}, {%4,%5,%6,%7}, {%8,%9}, {%0,%1,%2,%3};" \
        : "+f"((c)[0]), "+f"((c)[1]), "+f"((c)[2]), "+f"((c)[3]) \
        : "r"((a)[0]), "r"((a)[1]), "r"((a)[2]), "r"((a)[3]), \
          "r"(b0), "r"(b1))

#define MMATF32(c, a, b0, b1) \
    asm volatile("mma.sync.aligned.m16n8k8.row.col.f32.tf32.tf32.f32 " \
        "{%0,%1,%2,%3}, {%4,%5,%6,%7}, {%8,%9}, {%0,%1,%2,%3};" \
        : "+f"((c)[0]), "+f"((c)[1]), "+f"((c)[2]), "+f"((c)[3]) \
        : "r"((a)[0]), "r"((a)[1]), "r"((a)[2]), "r"((a)[3]), \
          "r"(b0), "r"(b1))

#define CVT_TF32(u, f) \
    asm("cvt.rna.tf32.f32 %0, %1;" : "=r"(u) : "f"(f))

// pack two floats to bf16x2 (lo addr half = first arg)
__device__ __forceinline__ uint32_t packbf(float lo, float hi) {
    uint32_t r;
    asm("cvt.rn.bf16x2.f32 %0, %1, %2;" : "=r"(r) : "f"(hi), "f"(lo));
    return r;
}

// ---------------------------------------------------------------------------
// Fragment-permuted layouts (fp32/tf32), per 128x32 tile (16KB):
// A-tile: blk = rb*4 + kb (rb = 16-row block, kb = k8 block), 512B blocks.
//   lane = (row&7)*4 + (k&3); word = ((k>>2)&1)*2 + ((row>>3)&1)
//   -> LDS.128 at blk*512 + lane*16 yields {a0,a1,a2,a3} of m16n8k8.
// B-tile: blk = nb*2 + kb16 (nb = n8 block, kb16 = k16 block).
//   lane = (n&7)*4 + (k&3); word = (k>>2)&3
//   -> LDS.128 yields {b0_s0, b1_s0, b0_s1, b1_s1} (two k8 steps).
// ---------------------------------------------------------------------------

// x [M][Kd] fp32 -> A-permuted tf32. grid (Kd/32, M/128), 128 thr
__global__ __launch_bounds__(128) void permute_a(
    const float* __restrict__ X, float* __restrict__ XP, int Kd)
{
    __shared__ float raw[128 * 36];
    const int t = threadIdx.x;
    const int tk = blockIdx.x, tm = blockIdx.y;
#pragma unroll
    for (int i = 0; i < 8; i++) {
        const int id = t + i * 128;
        const int row = id >> 3, c4 = id & 7;
        const float4 v = *reinterpret_cast<const float4*>(
            X + (size_t)(tm * 128 + row) * Kd + tk * 32 + c4 * 4);
        *reinterpret_cast<float4*>(&raw[row * 36 + c4 * 4]) = v;
    }
    __syncthreads();
    float* dst = XP + ((size_t)tm * (Kd >> 5) + tk) * 4096;
#pragma unroll
    for (int i = 0; i < 8; i++) {
        const int of  = t + i * 128;     // output float4 id
        const int blk = of >> 5;
        const int L   = of & 31;
        const int rb = blk >> 2, kb = blk & 3;
        const int r8 = L >> 2, c = L & 3;
        uint32_t ww[4];
#pragma unroll
        for (int w = 0; w < 4; w++) {
            const int hi = w & 1, k4 = w >> 1;
            const float f = raw[(rb * 16 + hi * 8 + r8) * 36 + kb * 8 + k4 * 4 + c];
            CVT_TF32(ww[w], f);
        }
        uint4 o; o.x = ww[0]; o.y = ww[1]; o.z = ww[2]; o.w = ww[3];
        *reinterpret_cast<uint4*>(dst + (size_t)of * 4) = o;
    }
}

// W [Kd][N] fp32 -> B-permuted (transposed) tf32. grid (Kd/32, N/128), 128 thr
__global__ __launch_bounds__(128) void permute_w(
    const float* __restrict__ W, float* __restrict__ WP, int Kd, int N)
{
    __shared__ float raw[32 * 132];
    const int t = threadIdx.x;
    const int tk = blockIdx.x, tn = blockIdx.y;
#pragma unroll
    for (int i = 0; i < 8; i++) {
        const int id = t + i * 128;
        const int row = id >> 5, c4 = id & 31;
        const float4 v = *reinterpret_cast<const float4*>(
            W + (size_t)(tk * 32 + row) * N + tn * 128 + c4 * 4);
        *reinterpret_cast<float4*>(&raw[row * 132 + c4 * 4]) = v;
    }
    __syncthreads();
    float* dst = WP + ((size_t)tn * (Kd >> 5) + tk) * 4096;
#pragma unroll
    for (int i = 0; i < 8; i++) {
        const int of  = t + i * 128;
        const int blk = of >> 5;
        const int L   = of & 31;
        const int nb = blk >> 1, kb16 = blk & 1;
        const int n8 = L >> 2, c = L & 3;
        uint32_t ww[4];
#pragma unroll
        for (int w = 0; w < 4; w++) {
            const float f = raw[(kb16 * 16 + w * 4 + c) * 132 + nb * 8 + n8];
            CVT_TF32(ww[w], f);
        }
        uint4 o; o.x = ww[0]; o.y = ww[1]; o.z = ww[2]; o.w = ww[3];
        *reinterpret_cast<uint4*>(dst + (size_t)of * 4) = o;
    }
}

// ---------------------------------------------------------------------------
// TF32 HMMA GEMM: C = A[M,K] @ (B[N,K])^T + bias, single product.
// A/B pre-permuted tf32. CTA 128x128, k-tile 32, 3-stage cp.async (linear
// 16KB tile copies), 2 CTAs/SM, 4 warps (2x2), warp tile 64x64.
// MODE 0: fp32 C out.  MODE 1: QKV epilogue -> split-bf16 q(scaled)/k/v.
// ---------------------------------------------------------------------------
#define STAGEB 32768
#define GEMM_SMEM (3 * STAGEB)

template <int MODE>
__global__ __launch_bounds__(128, 2) void gemm_tf32(
    const float* __restrict__ A, const float* __restrict__ B,
    const float* __restrict__ bias, float* __restrict__ C,
    __nv_bfloat16* __restrict__ qh, __nv_bfloat16* __restrict__ ql,
    __nv_bfloat16* __restrict__ kh, __nv_bfloat16* __restrict__ kl,
    __nv_bfloat16* __restrict__ vh, __nv_bfloat16* __restrict__ vl,
    int Ntot)
{
    extern __shared__ char dsm[];
    const uint32_t sb = smem_to_u32(dsm);

    const int t    = threadIdx.x;
    const int lane = t & 31;
    const int wid  = t >> 5;
    const int wm   = wid >> 1;
    const int wn   = wid & 1;
    const int bm   = blockIdx.y << 7;
    const int bn   = blockIdx.x << 7;

    // cp.async plan: A tile 16KB + B tile 16KB per stage, linear copy
    const float* gpA = A + ((size_t)blockIdx.y * NTK) * 4096 + t * 4;
    const float* gpB = B + ((size_t)blockIdx.x * NTK) * 4096 + t * 4;

    // LDS bases
    const uint32_t a_lane = (uint32_t)(lane * 16);
    const uint32_t b_lane = (uint32_t)(16384 + lane * 16);

    float acc[4][8][4];
#pragma unroll
    for (int mi = 0; mi < 4; mi++)
#pragma unroll
        for (int ni = 0; ni < 8; ni++)
#pragma unroll
            for (int e = 0; e < 4; e++) acc[mi][ni][e] = 0.0f;

    // prologue: stages 0 and 1
#pragma unroll
    for (int s = 0; s < 2; s++) {
        const uint32_t st = sb + (uint32_t)s * STAGEB;
#pragma unroll
        for (int p = 0; p < 8; p++) {
            CP_ASYNC16(st + t * 16 + p * 2048, gpA + (size_t)s * 4096 + p * 512);
            CP_ASYNC16(st + 16384 + t * 16 + p * 2048, gpB + (size_t)s * 4096 + p * 512);
        }
        CP_COMMIT();
    }

    int buf = 0, nbuf = 2;
#pragma unroll 1
    for (int kt = 0; kt < NTK; kt++) {
        CP_WAIT(1);
        __syncthreads();

        if (kt + 2 < NTK) {
            const uint32_t st = sb + (uint32_t)nbuf * STAGEB;
#pragma unroll
            for (int p = 0; p < 8; p++) {
                CP_ASYNC16(st + t * 16 + p * 2048,
                           gpA + (size_t)(kt + 2) * 4096 + p * 512);
                CP_ASYNC16(st + 16384 + t * 16 + p * 2048,
                           gpB + (size_t)(kt + 2) * 4096 + p * 512);
            }
        }
        CP_COMMIT();

        const uint32_t stg = sb + (uint32_t)buf * STAGEB;
        buf = (buf == 2) ? 0 : buf + 1;
        nbuf = (nbuf == 2) ? 0 : nbuf + 1;

#pragma unroll
        for (int ks16 = 0; ks16 < 2; ks16++) {
            uint32_t bfr[8][4];
#pragma unroll
            for (int g = 0; g < 8; g++)
                LDS128U(bfr[g], stg + b_lane +
                        (uint32_t)(((wn * 8 + g) * 2 + ks16) * 512));
            uint32_t afr[4][2][4];
#pragma unroll
            for (int mi = 0; mi < 4; mi++)
#pragma unroll
                for (int s = 0; s < 2; s++)
                    LDS128U(afr[mi][s], stg + a_lane +
                            (uint32_t)(((wm * 4 + mi) * 4 + ks16 * 2 + s) * 512));
#pragma unroll
            for (int s = 0; s < 2; s++)
#pragma unroll
                for (int mi = 0; mi < 4; mi++)
#pragma unroll
                    for (int g = 0; g < 8; g++)
                        MMATF32(acc[mi][g], afr[mi][s],
                                bfr[g][s * 2], bfr[g][s * 2 + 1]);
        }
    }

    // ---- epilogue ----
    const int er = bm + wm * 64 + (lane >> 2);
    const int ec = bn + wn * 64 + (lane & 3) * 2;

    if (MODE == 0) {
#pragma unroll
        for (int ni = 0; ni < 8; ni++) {
            const int col = ec + ni * 8;
            const float2 bv = *reinterpret_cast<const float2*>(bias + col);
#pragma unroll
            for (int mi = 0; mi < 4; mi++) {
                const int r0 = er + mi * 16;
                float2 o0, o1;
                o0.x = acc[mi][ni][0] + bv.x;
                o0.y = acc[mi][ni][1] + bv.y;
                o1.x = acc[mi][ni][2] + bv.x;
                o1.y = acc[mi][ni][3] + bv.y;
                *reinterpret_cast<float2*>(C + (size_t)r0 * Ntot + col) = o0;
                *reinterpret_cast<float2*>(C + (size_t)(r0 + 8) * Ntot + col) = o1;
            }
        }
    } else {
        // QKV epilogue: seg 0=Q(scale 0.125), 1=K, 2=V -> split-bf16
        const int seg = bn >> 10;
        __nv_bfloat16 *H, *L;
        float scale = 1.0f;
        if (seg == 0)      { H = qh; L = ql; scale = 0.125f; }
        else if (seg == 1) { H = kh; L = kl; }
        else               { H = vh; L = vl; }
        const int ecl = ec & 1023;
#pragma unroll
        for (int ni = 0; ni < 8; ni++) {
            const int col = ec + ni * 8;
            const float2 bv = *reinterpret_cast<const float2*>(bias + col);
            const int cl = ecl + ni * 8;
#pragma unroll
            for (int mi = 0; mi < 4; mi++) {
                const int r0 = er + mi * 16;
                const float v00 = (acc[mi][ni][0] + bv.x) * scale;
                const float v01 = (acc[mi][ni][1] + bv.y) * scale;
                const float v10 = (acc[mi][ni][2] + bv.x) * scale;
                const float v11 = (acc[mi][ni][3] + bv.y) * scale;
                const float h00 = __bfloat162float(__float2bfloat16(v00));
                const float h01 = __bfloat162float(__float2bfloat16(v01));
                const float h10 = __bfloat162float(__float2bfloat16(v10));
                const float h11 = __bfloat162float(__float2bfloat16(v11));
                *reinterpret_cast<uint32_t*>(H + (size_t)r0 * 1024 + cl) = packbf(v00, v01);
                *reinterpret_cast<uint32_t*>(L + (size_t)r0 * 1024 + cl) = packbf(v00 - h00, v01 - h01);
                *reinterpret_cast<uint32_t*>(H + (size_t)(r0 + 8) * 1024 + cl) = packbf(v10, v11);
                *reinterpret_cast<uint32_t*>(L + (size_t)(r0 + 8) * 1024 + cl) = packbf(v10 - h10, v11 - h11);
            }
        }
    }
}

// ---------------------------------------------------------------------------
// V transpose: vh/vl [B*T][1024] -> vth/vtl [(b*16+h)*64+dh][1024] (col = t)
// ---------------------------------------------------------------------------
__global__ __launch_bounds__(256) void transpose_v(
    const __nv_bfloat16* __restrict__ vh, const __nv_bfloat16* __restrict__ vl,
    __nv_bfloat16* __restrict__ vth, __nv_bfloat16* __restrict__ vtl)
{
    __shared__ __nv_bfloat16 th[32][33], tl[32][33];
    const int tx = threadIdx.x, ty = threadIdx.y;
    const int c0 = blockIdx.x * 32;
    const int r0 = blockIdx.y * 32;
#pragma unroll
    for (int i = 0; i < 4; i++) {
        const size_t src = (size_t)(r0 + ty + i * 8) * 1024 + c0 + tx;
        th[ty + i * 8][tx] = vh[src];
        tl[ty + i * 8][tx] = vl[src];
    }
    __syncthreads();
    const int b = r0 >> 10;
    const int tbase = (r0 & 1023) + tx;
#pragma unroll
    for (int i = 0; i < 4; i++) {
        const int cp = c0 + ty + i * 8;
        const int hh = cp >> 6, dh = cp & 63;
        const size_t dst = (size_t)(((b * 16 + hh) * 64) + dh) * 1024 + tbase;
        vth[dst] = th[tx][ty + i * 8];
        vtl[dst] = tl[tx][ty + i * 8];
    }
}

// ---------------------------------------------------------------------------
// HMMA flash attention (bf16 3-product), double-buffered K/V.
// Output written DIRECTLY in A-permuted tf32 layout (feeds proj tf32 GEMM).
// Grid (4, B*H), 2 passes: q-tiles {7-bx, bx} (BQ=128). 8 warps x 16 rows.
// ---------------------------------------------------------------------------
#define ASTR 144
#define QH_OFF 0
#define QL_OFF 18432
#define K_OFF  36864
#define V_OFF  73728
#define KVBUF  18432
#define MSK_OFF 110592
#define ATTN_SMEM (110592 + 512)

__global__ __launch_bounds__(256, 2) void attn_hmma(
    const __nv_bfloat16* __restrict__ qh, const __nv_bfloat16* __restrict__ ql,
    const __nv_bfloat16* __restrict__ kh, const __nv_bfloat16* __restrict__ kl,
    const __nv_bfloat16* __restrict__ vth, const __nv_bfloat16* __restrict__ vtl,
    const int* __restrict__ mask,
    float* __restrict__ aop)
{
    extern __shared__ char smc[];
    const uint32_t sb = smem_to_u32(smc);

    const int t    = threadIdx.x;
    const int lane = t & 31;
    const int w    = t >> 5;
    const int bh   = blockIdx.y;
    const int b    = bh >> 4;
    const int h    = bh & 15;
    float* msk_s = (float*)(smc + MSK_OFF);

    const uint32_t aq_base = sb + QH_OFF +
        (uint32_t)((16 * w + (lane & 15)) * ASTR + (lane >> 4) * 16);
    const uint32_t bk_base = sb + K_OFF +
        (uint32_t)(((lane & 7) + ((lane >> 4) << 3)) * ASTR + ((lane >> 3) & 1) * 16);
    const uint32_t bv_base = sb + V_OFF +
        (uint32_t)(((lane & 7) + ((lane >> 4) << 3)) * ASTR + ((lane >> 3) & 1) * 16);

#pragma unroll 1
    for (int pass = 0; pass < 2; pass++) {
        const int qt = pass ? (int)blockIdx.x : 7 - (int)blockIdx.x;
        __syncthreads();

        // ---- Q tile: 128 rows x 64 bf16 (hi+lo) ----
#pragma unroll
        for (int p = 0; p < 8; p++) {
            const int c   = t + (p << 8);
            const int m   = c >> 10;
            const int idx = c & 1023;
            const int row = idx >> 3;
            const int ch  = idx & 7;
            const __nv_bfloat16* src = (m ? ql : qh) +
                (size_t)(b * 1024 + qt * 128 + row) * 1024 + h * 64 + ch * 8;
            CP_ASYNC16(sb + (m ? QL_OFF : QH_OFF) + row * ASTR + ch * 16, src);
        }
        CP_COMMIT();

        const int kmax = 2 * qt + 1;

        // ---- prologue: K/V for kt=0 into buffer 0, mask[0] ----
#pragma unroll
        for (int p = 0; p < 8; p++) {
            const int c   = t + (p << 8);
            const int m   = c >> 9;
            const int idx = c & 511;
            const int row = idx >> 3;
            const int ch  = idx & 7;
            const __nv_bfloat16* src;
            uint32_t dst;
            if (m == 0) {
                src = kh + (size_t)(b * 1024 + row) * 1024 + h * 64 + ch * 8;
                dst = sb + K_OFF + row * ASTR + ch * 16;
            } else if (m == 1) {
                src = kl + (size_t)(b * 1024 + row) * 1024 + h * 64 + ch * 8;
                dst = sb + K_OFF + 9216 + row * ASTR + ch * 16;
            } else if (m == 2) {
                src = vth + (size_t)(bh * 64 + row) * 1024 + ch * 8;
                dst = sb + V_OFF + row * ASTR + ch * 16;
            } else {
                src = vtl + (size_t)(bh * 64 + row) * 1024 + ch * 8;
                dst = sb + V_OFF + 9216 + row * ASTR + ch * 16;
            }
            CP_ASYNC16(dst, src);
        }
        if (t < 64)
            msk_s[t] = (mask[b * TSEQ + t] != 0) ? 0.0f : -1e30f;
        CP_COMMIT();

        float m0 = -1e30f, m1 = -1e30f, l0 = 0.0f, l1 = 0.0f;
        float of[8][4];
#pragma unroll
        for (int j = 0; j < 8; j++)
#pragma unroll
            for (int e = 0; e < 4; e++) of[j][e] = 0.0f;

        const int qrow_w = qt * 128 + 16 * w;
        const int r0g = qrow_w + (lane >> 2);

#pragma unroll 1
        for (int kt = 0; kt <= kmax; kt++) {
            CP_WAIT(0);
            __syncthreads();

            if (kt < kmax) {
                const uint32_t kb = (uint32_t)(((kt + 1) & 1) * KVBUF);
#pragma unroll
                for (int p = 0; p < 8; p++) {
                    const int c   = t + (p << 8);
                    const int m   = c >> 9;
                    const int idx = c & 511;
                    const int row = idx >> 3;
                    const int ch  = idx & 7;
                    const __nv_bfloat16* src;
                    uint32_t dst;
                    if (m == 0) {
                        src = kh + (size_t)(b * 1024 + (kt + 1) * 64 + row) * 1024 + h * 64 + ch * 8;
                        dst = sb + K_OFF + kb + row * ASTR + ch * 16;
                    } else if (m == 1) {
                        src = kl + (size_t)(b * 1024 + (kt + 1) * 64 + row) * 1024 + h * 64 + ch * 8;
                        dst = sb + K_OFF + kb + 9216 + row * ASTR + ch * 16;
                    } else if (m == 2) {
                        src = vth + (size_t)(bh * 64 + row) * 1024 + (kt + 1) * 64 + ch * 8;
                        dst = sb + V_OFF + kb + row * ASTR + ch * 16;
                    } else {
                        src = vtl + (size_t)(bh * 64 + row) * 1024 + (kt + 1) * 64 + ch * 8;
                        dst = sb + V_OFF + kb + 9216 + row * ASTR + ch * 16;
                    }
                    CP_ASYNC16(dst, src);
                }
                if (t < 64)
                    msk_s[((kt + 1) & 1) * 64 + t] =
                        (mask[b * TSEQ + (kt + 1) * 64 + t] != 0) ? 0.0f : -1e30f;
            }
            CP_COMMIT();

            const uint32_t kb = (uint32_t)((kt & 1) * KVBUF);
            const float* msk = msk_s + (kt & 1) * 64;

            // ---- S = Q @ K^T ----
            float s[8][4];
#pragma unroll
            for (int j = 0; j < 8; j++)
#pragma unroll
                for (int e = 0; e < 4; e++) s[j][e] = 0.0f;

#pragma unroll
            for (int ks = 0; ks < 4; ks++) {
                uint32_t aqh[4], aql[4];
                LDSM_X4(aqh[0], aqh[1], aqh[2], aqh[3], aq_base + ks * 32);
                LDSM_X4(aql[0], aql[1], aql[2], aql[3],
                        aq_base + (QL_OFF - QH_OFF) + ks * 32);
#pragma unroll
                for (int g = 0; g < 4; g++) {
                    uint32_t bkh[4], bkl[4];
                    LDSM_X4(bkh[0], bkh[1], bkh[2], bkh[3],
                            bk_base + kb + g * (16 * ASTR) + ks * 32);
                    LDSM_X4(bkl[0], bkl[1], bkl[2], bkl[3],
                            bk_base + kb + 9216 + g * (16 * ASTR) + ks * 32);
                    MMA16816(s[2 * g],     aqh, bkh[0], bkh[1]);
                    MMA16816(s[2 * g],     aqh, bkl[0], bkl[1]);
                    MMA16816(s[2 * g],     aql, bkh[0], bkh[1]);
                    MMA16816(s[2 * g + 1], aqh, bkh[2], bkh[3]);
                    MMA16816(s[2 * g + 1], aqh, bkl[2], bkl[3]);
                    MMA16816(s[2 * g + 1], aql, bkh[2], bkh[3]);
                }
            }

            // ---- mask + causal ----
            const int lc = 2 * (lane & 3);
#pragma unroll
            for (int j = 0; j < 8; j++) {
                const float mj0 = msk[j * 8 + lc];
                const float mj1 = msk[j * 8 + lc + 1];
                s[j][0] += mj0; s[j][1] += mj1;
                s[j][2] += mj0; s[j][3] += mj1;
            }
            if (kt * 64 + 63 > qrow_w) {
                const int r1g = r0g + 8;
#pragma unroll
                for (int j = 0; j < 8; j++) {
                    const int c0 = kt * 64 + j * 8 + lc;
                    if (c0     > r0g) s[j][0] = -1e30f;
                    if (c0 + 1 > r0g) s[j][1] = -1e30f;
                    if (c0     > r1g) s[j][2] = -1e30f;
                    if (c0 + 1 > r1g) s[j][3] = -1e30f;
                }
            }

            // ---- online softmax ----
            float rm0 = -1e30f, rm1 = -1e30f;
#pragma unroll
            for (int j = 0; j < 8; j++) {
                rm0 = fmaxf(rm0, fmaxf(s[j][0], s[j][1]));
                rm1 = fmaxf(rm1, fmaxf(s[j][2], s[j][3]));
            }
            rm0 = fmaxf(rm0, __shfl_xor_sync(0xffffffffu, rm0, 1));
            rm0 = fmaxf(rm0, __shfl_xor_sync(0xffffffffu, rm0, 2));
            rm1 = fmaxf(rm1, __shfl_xor_sync(0xffffffffu, rm1, 1));
            rm1 = fmaxf(rm1, __shfl_xor_sync(0xffffffffu, rm1, 2));
            const float mn0 = fmaxf(m0, rm0), mn1 = fmaxf(m1, rm1);
            const float al0 = __expf(m0 - mn0), al1 = __expf(m1 - mn1);
            m0 = mn0; m1 = mn1;
            float ls0 = 0.0f, ls1 = 0.0f;
#pragma unroll
            for (int j = 0; j < 8; j++) {
                s[j][0] = __expf(s[j][0] - mn0); ls0 += s[j][0];
                s[j][1] = __expf(s[j][1] - mn0); ls0 += s[j][1];
                s[j][2] = __expf(s[j][2] - mn1); ls1 += s[j][2];
                s[j][3] = __expf(s[j][3] - mn1); ls1 += s[j][3];
            }
            ls0 += __shfl_xor_sync(0xffffffffu, ls0, 1);
            ls0 += __shfl_xor_sync(0xffffffffu, ls0, 2);
            ls1 += __shfl_xor_sync(0xffffffffu, ls1, 1);
            ls1 += __shfl_xor_sync(0xffffffffu, ls1, 2);
            l0 = l0 * al0 + ls0;
            l1 = l1 * al1 + ls1;
#pragma unroll
            for (int j = 0; j < 8; j++) {
                of[j][0] *= al0; of[j][1] *= al0;
                of[j][2] *= al1; of[j][3] *= al1;
            }

            // ---- O += P @ V ----
#pragma unroll
            for (int kt2 = 0; kt2 < 4; kt2++) {
                uint32_t aph[4], apl[4];
                {
                    const float* p0 = s[2 * kt2];
                    const float* p1 = s[2 * kt2 + 1];
                    float hl[8];
#pragma unroll
                    for (int e = 0; e < 4; e++) {
                        hl[e]     = p0[e] - __bfloat162float(__float2bfloat16(p0[e]));
                        hl[4 + e] = p1[e] - __bfloat162float(__float2bfloat16(p1[e]));
                    }
                    aph[0] = packbf(p0[0], p0[1]); aph[1] = packbf(p0[2], p0[3]);
                    aph[2] = packbf(p1[0], p1[1]); aph[3] = packbf(p1[2], p1[3]);
                    apl[0] = packbf(hl[0], hl[1]); apl[1] = packbf(hl[2], hl[3]);
                    apl[2] = packbf(hl[4], hl[5]); apl[3] = packbf(hl[6], hl[7]);
                }
#pragma unroll
                for (int g = 0; g < 4; g++) {
                    uint32_t bvh[4], bvl[4];
                    LDSM_X4(bvh[0], bvh[1], bvh[2], bvh[3],
                            bv_base + kb + g * (16 * ASTR) + kt2 * 32);
                    LDSM_X4(bvl[0], bvl[1], bvl[2], bvl[3],
                            bv_base + kb + 9216 + g * (16 * ASTR) + kt2 * 32);
                    MMA16816(of[2 * g],     aph, bvh[0], bvh[1]);
                    MMA16816(of[2 * g],     aph, bvl[0], bvl[1]);
                    MMA16816(of[2 * g],     apl, bvh[0], bvh[1]);
                    MMA16816(of[2 * g + 1], aph, bvh[2], bvh[3]);
                    MMA16816(of[2 * g + 1], aph, bvl[2], bvl[3]);
                    MMA16816(of[2 * g + 1], apl, bvh[2], bvh[3]);
                }
            }
        }

        // ---- normalize + store in A-permuted tf32 layout ----
        const float inv0 = 1.0f / l0, inv1 = 1.0f / l1;
        const int grow0 = b * TSEQ + r0g;
#pragma unroll
        for (int j = 0; j < 8; j++) {
            const int kcol0 = h * 64 + j * 8 + 2 * (lane & 3);
#pragma unroll
            for (int e = 0; e < 4; e++) {
                const int grow = grow0 + ((e >= 2) ? 8 : 0);
                const int kcol = kcol0 + (e & 1);
                const float val = of[j][e] * ((e >= 2) ? inv1 : inv0);
                uint32_t u;
                CVT_TF32(u, val);
                const int tm = grow >> 7, tk = kcol >> 5;
                const int rb = (grow >> 4) & 7, kbk = (kcol >> 3) & 3;
                const int r8 = grow & 7, hi = (grow >> 3) & 1;
                const int cc = kcol & 3, k4 = (kcol >> 2) & 1;
                const size_t fidx = ((size_t)tm * NTK + tk) * 4096
                    + (size_t)((rb * 4 + kbk) * 128 + (r8 * 4 + cc) * 4 + k4 * 2 + hi);
                *reinterpret_cast<uint32_t*>(aop + fidx) = u;
            }
        }
    }
}

// ---------------------------------------------------------------------------
extern "C" void kernel_launch(void* const* d_in, const int* in_sizes, int n_in,
                              void* d_out, int out_size)
{
    const float* x     = (const float*)d_in[0];
    const float* Wqkv  = (const float*)d_in[1];
    const float* bqkv  = (const float*)d_in[2];
    const float* Wproj = (const float*)d_in[3];
    const float* bproj = (const float*)d_in[4];
    const int*   mask  = (const int*)d_in[5];
    float* out = (float*)d_out;

    float *xp, *wqp, *wpp, *aop;
    __nv_bfloat16 *qh, *ql, *kh, *kl, *vh, *vl, *vth, *vtl;
    cudaGetSymbolAddress((void**)&xp,  g_xp);
    cudaGetSymbolAddress((void**)&wqp, g_wqp);
    cudaGetSymbolAddress((void**)&wpp, g_wpp);
    cudaGetSymbolAddress((void**)&aop, g_aop);
    cudaGetSymbolAddress((void**)&qh, g_qh);   cudaGetSymbolAddress((void**)&ql, g_ql);
    cudaGetSymbolAddress((void**)&kh, g_kh);   cudaGetSymbolAddress((void**)&kl, g_kl);
    cudaGetSymbolAddress((void**)&vh, g_vh);   cudaGetSymbolAddress((void**)&vl, g_vl);
    cudaGetSymbolAddress((void**)&vth, g_vth); cudaGetSymbolAddress((void**)&vtl, g_vtl);

    cudaFuncSetAttribute(attn_hmma,
                         cudaFuncAttributeMaxDynamicSharedMemorySize, ATTN_SMEM);
    cudaFuncSetAttribute(gemm_tf32<0>,
                         cudaFuncAttributeMaxDynamicSharedMemorySize, GEMM_SMEM);
    cudaFuncSetAttribute(gemm_tf32<1>,
                         cudaFuncAttributeMaxDynamicSharedMemorySize, GEMM_SMEM);

    // Permute inputs to tf32 fragment layouts
    permute_a<<<dim3(KDIM / 32, MROWS / 128), 128>>>(x, xp, KDIM);
    permute_w<<<dim3(KDIM / 32, QKV_N / 128), 128>>>(Wqkv, wqp, KDIM, QKV_N);
    permute_w<<<dim3(KDIM / 32, DMODEL / 128), 128>>>(Wproj, wpp, KDIM, DMODEL);

    // 1) QKV GEMM (tf32 single-product) -> split-bf16 Q(scaled)/K/V
    gemm_tf32<1><<<dim3(QKV_N / 128, MROWS / 128), 128, GEMM_SMEM>>>(
        xp, wqp, bqkv, nullptr, qh, ql, kh, kl, vh, vl, QKV_N);

    // 2) V transpose
    transpose_v<<<dim3(32, 128), dim3(32, 8)>>>(vh, vl, vth, vtl);

    // 3) Fused causal attention (bf16 3-product) -> permuted tf32 output
    attn_hmma<<<dim3(4, BATCH * NH), 256, ATTN_SMEM>>>(
        qh, ql, kh, kl, vth, vtl, mask, aop);

    // 4) out = attn @ Wproj + bproj (tf32 single-product)
    gemm_tf32<0><<<dim3(DMODEL / 128, MROWS / 128), 128, GEMM_SMEM>>>(
        aop, wpp, bproj, out,
        nullptr, nullptr, nullptr, nullptr, nullptr, nullptr, DMODEL);
}

// round 10
// speedup vs baseline: 4.6134x; 1.3743x over previous
#include <cuda_runtime.h>
#include <cuda_bf16.h>
#include <cuda_fp16.h>
#include <math.h>
#include <cstdint>

// Problem constants
#define BATCH 4
#define TSEQ  1024
#define DMODEL 1024
#define NH 16
#define DHEAD 64
#define QKV_N 3072   // 3*DMODEL
#define MROWS 4096   // BATCH*TSEQ
#define KDIM 1024    // K is 1024 for both GEMMs
#define NTK  32      // k-tiles (KDIM/32)

// Q scale: 1/sqrt(64) * log2(e)  (softmax done in exp2 domain)
#define QSCALE (0.125f * 1.44269504088896f)

// ---------------------------------------------------------------------------
// Scratch (device globals: allocation-free)
// ---------------------------------------------------------------------------
__device__ __half g_x16[(size_t)MROWS * DMODEL];         // x fp16 row-major
__device__ __half g_wq16[(size_t)QKV_N * DMODEL];        // Wqkv^T fp16 [N][K]
__device__ __half g_wp16[(size_t)DMODEL * DMODEL];       // Wproj^T fp16 [N][K]
__device__ __half g_ao16[(size_t)MROWS * DMODEL];        // attn out fp16
__device__ __nv_bfloat16 g_qh[(size_t)MROWS * DMODEL];   // Q scaled, split
__device__ __nv_bfloat16 g_ql[(size_t)MROWS * DMODEL];
__device__ __nv_bfloat16 g_kh[(size_t)MROWS * DMODEL];
__device__ __nv_bfloat16 g_kl[(size_t)MROWS * DMODEL];
__device__ __nv_bfloat16 g_vh[(size_t)MROWS * DMODEL];   // V [row][h*64+dh]
__device__ __nv_bfloat16 g_vl[(size_t)MROWS * DMODEL];
__device__ __nv_bfloat16 g_vth[(size_t)MROWS * DMODEL];  // V^T [bh][dh][t]
__device__ __nv_bfloat16 g_vtl[(size_t)MROWS * DMODEL];

// ---------------------------------------------------------------------------
// PTX helpers (base ISA only — compute_103 virtual arch, no tcgen05)
// ---------------------------------------------------------------------------
__device__ __forceinline__ uint32_t smem_to_u32(const void* p) {
    uint32_t a;
    asm("{ .reg .u64 t; cvta.to.shared.u64 t, %1; cvt.u32.u64 %0, t; }"
        : "=r"(a) : "l"(p));
    return a;
}

#define CP_ASYNC16(smem, gptr) \
    asm volatile("cp.async.cg.shared.global [%0], [%1], 16;" \
        :: "r"(smem), "l"(gptr) : "memory")
#define CP_COMMIT() asm volatile("cp.async.commit_group;" ::: "memory")
#define CP_WAIT(n)  asm volatile("cp.async.wait_group %0;" :: "n"(n) : "memory")

#define LDSM_X4(r0, r1, r2, r3, addr) \
    asm volatile("ldmatrix.sync.aligned.m8n8.x4.shared.b16 {%0,%1,%2,%3}, [%4];" \
        : "=r"(r0), "=r"(r1), "=r"(r2), "=r"(r3) : "r"(addr))

#define MMA16816(c, a, b0, b1) \
    asm volatile("mma.sync.aligned.m16n8k16.row.col.f32.bf16.bf16.f32 " \
        "{%0,%1,%2,%3}, {%4,%5,%6,%7}, {%8,%9}, {%0,%1,%2,%3};" \
        : "+f"((c)[0]), "+f"((c)[1]), "+f"((c)[2]), "+f"((c)[3]) \
        : "r"((a)[0]), "r"((a)[1]), "r"((a)[2]), "r"((a)[3]), \
          "r"(b0), "r"(b1))

#define MMAF16(c, a, b0, b1) \
    asm volatile("mma.sync.aligned.m16n8k16.row.col.f32.f16.f16.f32 " \
        "{%0,%1,%2,%3}, {%4,%5,%6,%7}, {%8,%9}, {%0,%1,%2,%3};" \
        : "+f"((c)[0]), "+f"((c)[1]), "+f"((c)[2]), "+f"((c)[3]) \
        : "r"((a)[0]), "r"((a)[1]), "r"((a)[2]), "r"((a)[3]), \
          "r"(b0), "r"(b1))

// pack two floats to bf16x2 / f16x2 (lo addr half = first arg)
__device__ __forceinline__ uint32_t packbf(float lo, float hi) {
    uint32_t r;
    asm("cvt.rn.bf16x2.f32 %0, %1, %2;" : "=r"(r) : "f"(hi), "f"(lo));
    return r;
}
__device__ __forceinline__ uint32_t packhf(float lo, float hi) {
    uint32_t r;
    asm("cvt.rn.f16x2.f32 %0, %1, %2;" : "=r"(r) : "f"(hi), "f"(lo));
    return r;
}
__device__ __forceinline__ float ex2(float x) {
    float r;
    asm("ex2.approx.f32 %0, %1;" : "=f"(r) : "f"(x));
    return r;
}

// Swizzled byte offset within one 8KB matrix tile (128 rows x 32 fp16):
// row-pair lines of 128B, chunk3 = (r&1)*4 + ch (ch = 16B k-chunk 0..3),
// swizzled with XOR (r>>1)&7.  (verified in rounds 7-8)
__device__ __forceinline__ uint32_t sw_off(int r, int ch) {
    const uint32_t chunk3 = (uint32_t)(((r & 1) << 2) | ch);
    return (uint32_t)((r >> 1) * 128) + ((chunk3 ^ ((uint32_t)(r >> 1) & 7u)) << 4);
}

// ---------------------------------------------------------------------------
// FP16 single-product HMMA GEMM: C = A[M,K] @ (B[N,K])^T + bias
// CTA 128x128, K-tile 32, 5-stage cp.async (swizzled smem, 16KB/stage),
// 2 CTAs/SM, 4 warps (2x2), warp tile 64x64.
// MODE 0: fp32 C out.  MODE 1: QKV epilogue -> split-bf16 q(scaled)/k/v.
// ---------------------------------------------------------------------------
#define MATB   8192
#define STAGEB 16384
#define NSTAGE 5
#define GEMM_SMEM (NSTAGE * STAGEB)

template <int MODE>
__global__ __launch_bounds__(128, 2) void gemm_f16(
    const __half* __restrict__ A, const __half* __restrict__ B,
    const float* __restrict__ bias, float* __restrict__ C,
    __nv_bfloat16* __restrict__ qh, __nv_bfloat16* __restrict__ ql,
    __nv_bfloat16* __restrict__ kh, __nv_bfloat16* __restrict__ kl,
    __nv_bfloat16* __restrict__ vh, __nv_bfloat16* __restrict__ vl,
    int Ntot)
{
    extern __shared__ char dsm[];
    const uint32_t sb = smem_to_u32(dsm);

    const int t    = threadIdx.x;
    const int lane = t & 31;
    const int wid  = t >> 5;
    const int wm   = wid >> 1;
    const int wn   = wid & 1;
    const int bm   = blockIdx.y << 7;
    const int bn   = blockIdx.x << 7;

    // cp.async plan: 2 matrices x 512 chunks(16B) / 128 thr = 8/thread
    const int rbase = t >> 2;       // 0..31
    const int ch0   = t & 3;        // k-chunk 0..3
    uint32_t soff[8];
    const __half* gp[8];
#pragma unroll
    for (int m = 0; m < 2; m++)
#pragma unroll
        for (int hh = 0; hh < 4; hh++) {
            const int r = rbase + hh * 32;
            soff[m * 4 + hh] = (uint32_t)(m * MATB) + sw_off(r, ch0);
            gp[m * 4 + hh]   = (m ? B : A) +
                (size_t)((m ? bn : bm) + r) * KDIM + ch0 * 8;
        }

    const uint32_t a_base = sw_off(wm * 64 + (lane & 15), lane >> 4);
    const uint32_t b_base = (uint32_t)MATB +
        sw_off(wn * 64 + (lane & 7) + ((lane >> 4) << 3), (lane >> 3) & 1);

    float acc[4][8][4];
#pragma unroll
    for (int mi = 0; mi < 4; mi++)
#pragma unroll
        for (int ni = 0; ni < 8; ni++)
#pragma unroll
            for (int e = 0; e < 4; e++) acc[mi][ni][e] = 0.0f;

    // prologue: stages 0..3
#pragma unroll
    for (int s = 0; s < NSTAGE - 1; s++) {
        const uint32_t st = sb + (uint32_t)s * STAGEB;
        const int ko = s * 32;
#pragma unroll
        for (int i = 0; i < 8; i++) CP_ASYNC16(st + soff[i], gp[i] + ko);
        CP_COMMIT();
    }

    int buf = 0, nbuf = NSTAGE - 1;
#pragma unroll 1
    for (int kt = 0; kt < NTK; kt++) {
        CP_WAIT(NSTAGE - 2);
        __syncthreads();

        // issue stage kt+4 into nbuf (last read at kt-1, ordered by barrier)
        if (kt + NSTAGE - 1 < NTK) {
            const uint32_t st = sb + (uint32_t)nbuf * STAGEB;
            const int ko = (kt + NSTAGE - 1) * 32;
#pragma unroll
            for (int i = 0; i < 8; i++) CP_ASYNC16(st + soff[i], gp[i] + ko);
        }
        CP_COMMIT();

        const uint32_t stg = sb + (uint32_t)buf * STAGEB;
        buf = (buf == NSTAGE - 1) ? 0 : buf + 1;
        nbuf = (nbuf == NSTAGE - 1) ? 0 : nbuf + 1;

#pragma unroll
        for (int ks = 0; ks < 2; ks++) {
            const uint32_t ksx = (uint32_t)(ks << 5);
            uint32_t ah[4][4];
#pragma unroll
            for (int mi = 0; mi < 4; mi++) {
                const uint32_t ao = (a_base + (uint32_t)(mi * 1024)) ^ ksx;
                LDSM_X4(ah[mi][0], ah[mi][1], ah[mi][2], ah[mi][3], stg + ao);
            }
            uint32_t rbh[4][4];
#pragma unroll
            for (int g = 0; g < 4; g++) {
                const uint32_t bo = (b_base + (uint32_t)(g * 1024)) ^ ksx;
                LDSM_X4(rbh[g][0], rbh[g][1], rbh[g][2], rbh[g][3], stg + bo);
            }
#pragma unroll
            for (int mi = 0; mi < 4; mi++)
#pragma unroll
                for (int ni = 0; ni < 8; ni++) {
                    const int g = ni >> 1, u = (ni & 1) * 2;
                    MMAF16(acc[mi][ni], ah[mi], rbh[g][u], rbh[g][u + 1]);
                }
        }
    }

    // ---- epilogue ----
    const int er = bm + wm * 64 + (lane >> 2);
    const int ec = bn + wn * 64 + (lane & 3) * 2;

    if (MODE == 0) {
#pragma unroll
        for (int ni = 0; ni < 8; ni++) {
            const int col = ec + ni * 8;
            const float2 bv = *reinterpret_cast<const float2*>(bias + col);
#pragma unroll
            for (int mi = 0; mi < 4; mi++) {
                const int r0 = er + mi * 16;
                float2 o0, o1;
                o0.x = acc[mi][ni][0] + bv.x;
                o0.y = acc[mi][ni][1] + bv.y;
                o1.x = acc[mi][ni][2] + bv.x;
                o1.y = acc[mi][ni][3] + bv.y;
                *reinterpret_cast<float2*>(C + (size_t)r0 * Ntot + col) = o0;
                *reinterpret_cast<float2*>(C + (size_t)(r0 + 8) * Ntot + col) = o1;
            }
        }
    } else {
        // QKV epilogue: seg 0=Q(scale log2e/8), 1=K, 2=V -> split-bf16
        const int seg = bn >> 10;
        __nv_bfloat16 *H, *L;
        float scale = 1.0f;
        if (seg == 0)      { H = qh; L = ql; scale = QSCALE; }
        else if (seg == 1) { H = kh; L = kl; }
        else               { H = vh; L = vl; }
        const int ecl = ec & 1023;
#pragma unroll
        for (int ni = 0; ni < 8; ni++) {
            const int col = ec + ni * 8;
            const float2 bv = *reinterpret_cast<const float2*>(bias + col);
            const int cl = ecl + ni * 8;
#pragma unroll
            for (int mi = 0; mi < 4; mi++) {
                const int r0 = er + mi * 16;
                const float v00 = (acc[mi][ni][0] + bv.x) * scale;
                const float v01 = (acc[mi][ni][1] + bv.y) * scale;
                const float v10 = (acc[mi][ni][2] + bv.x) * scale;
                const float v11 = (acc[mi][ni][3] + bv.y) * scale;
                const float h00 = __bfloat162float(__float2bfloat16(v00));
                const float h01 = __bfloat162float(__float2bfloat16(v01));
                const float h10 = __bfloat162float(__float2bfloat16(v10));
                const float h11 = __bfloat162float(__float2bfloat16(v11));
                *reinterpret_cast<uint32_t*>(H + (size_t)r0 * 1024 + cl) = packbf(v00, v01);
                *reinterpret_cast<uint32_t*>(L + (size_t)r0 * 1024 + cl) = packbf(v00 - h00, v01 - h01);
                *reinterpret_cast<uint32_t*>(H + (size_t)(r0 + 8) * 1024 + cl) = packbf(v10, v11);
                *reinterpret_cast<uint32_t*>(L + (size_t)(r0 + 8) * 1024 + cl) = packbf(v10 - h10, v11 - h11);
            }
        }
    }
}

// ---------------------------------------------------------------------------
// fp32 -> fp16 convert, 4 elems/thread
// ---------------------------------------------------------------------------
__global__ __launch_bounds__(256) void convert_h(
    const float* __restrict__ A, __half* __restrict__ H)
{
    const int i = blockIdx.x * blockDim.x + threadIdx.x;
    const float4 v = reinterpret_cast<const float4*>(A)[i];
    uint2 o;
    o.x = packhf(v.x, v.y);
    o.y = packhf(v.z, v.w);
    *reinterpret_cast<uint2*>(H + (size_t)i * 4) = o;
}

// ---------------------------------------------------------------------------
// W[K][N] fp32 -> W^T[N][K] fp16 (transpose + convert), block (32,8)
// ---------------------------------------------------------------------------
__global__ __launch_bounds__(256) void convert_wT(
    const float* __restrict__ W, __half* __restrict__ T, int K, int N)
{
    __shared__ float tile[32][33];
    const int tx = threadIdx.x, ty = threadIdx.y;
    const int n0 = blockIdx.x * 32, k0 = blockIdx.y * 32;
#pragma unroll
    for (int i = 0; i < 4; i++)
        tile[ty + i * 8][tx] = W[(size_t)(k0 + ty + i * 8) * N + n0 + tx];
    __syncthreads();
#pragma unroll
    for (int i = 0; i < 4; i++) {
        const float v = tile[tx][ty + i * 8];
        T[(size_t)(n0 + ty + i * 8) * K + k0 + tx] = __float2half_rn(v);
    }
}

// ---------------------------------------------------------------------------
// V transpose: vh/vl [B*T][1024] -> vth/vtl [(b*16+h)*64+dh][1024] (col = t)
// ---------------------------------------------------------------------------
__global__ __launch_bounds__(256) void transpose_v(
    const __nv_bfloat16* __restrict__ vh, const __nv_bfloat16* __restrict__ vl,
    __nv_bfloat16* __restrict__ vth, __nv_bfloat16* __restrict__ vtl)
{
    __shared__ __nv_bfloat16 th[32][33], tl[32][33];
    const int tx = threadIdx.x, ty = threadIdx.y;
    const int c0 = blockIdx.x * 32;
    const int r0 = blockIdx.y * 32;
#pragma unroll
    for (int i = 0; i < 4; i++) {
        const size_t src = (size_t)(r0 + ty + i * 8) * 1024 + c0 + tx;
        th[ty + i * 8][tx] = vh[src];
        tl[ty + i * 8][tx] = vl[src];
    }
    __syncthreads();
    const int b = r0 >> 10;
    const int tbase = (r0 & 1023) + tx;
#pragma unroll
    for (int i = 0; i < 4; i++) {
        const int cp = c0 + ty + i * 8;
        const int hh = cp >> 6, dh = cp & 63;
        const size_t dst = (size_t)(((b * 16 + hh) * 64) + dh) * 1024 + tbase;
        vth[dst] = th[tx][ty + i * 8];
        vtl[dst] = tl[tx][ty + i * 8];
    }
}

// ---------------------------------------------------------------------------
// HMMA flash attention (bf16 3-product), double-buffered K/V, exp2 softmax.
// Output written as single fp16 row-major (feeds proj fp16 GEMM).
// Grid (4, B*H), 2 passes: q-tiles {7-bx, bx} (BQ=128). 8 warps x 16 rows.
// ---------------------------------------------------------------------------
#define ASTR 144
#define QH_OFF 0
#define QL_OFF 18432
#define K_OFF  36864
#define V_OFF  73728
#define KVBUF  18432
#define MSK_OFF 110592
#define ATTN_SMEM (110592 + 512)

__global__ __launch_bounds__(256, 2) void attn_hmma(
    const __nv_bfloat16* __restrict__ qh, const __nv_bfloat16* __restrict__ ql,
    const __nv_bfloat16* __restrict__ kh, const __nv_bfloat16* __restrict__ kl,
    const __nv_bfloat16* __restrict__ vth, const __nv_bfloat16* __restrict__ vtl,
    const int* __restrict__ mask,
    __half* __restrict__ ao)
{
    extern __shared__ char smc[];
    const uint32_t sb = smem_to_u32(smc);

    const int t    = threadIdx.x;
    const int lane = t & 31;
    const int w    = t >> 5;
    const int bh   = blockIdx.y;
    const int b    = bh >> 4;
    const int h    = bh & 15;
    float* msk_s = (float*)(smc + MSK_OFF);

    const uint32_t aq_base = sb + QH_OFF +
        (uint32_t)((16 * w + (lane & 15)) * ASTR + (lane >> 4) * 16);
    const uint32_t bk_base = sb + K_OFF +
        (uint32_t)(((lane & 7) + ((lane >> 4) << 3)) * ASTR + ((lane >> 3) & 1) * 16);
    const uint32_t bv_base = sb + V_OFF +
        (uint32_t)(((lane & 7) + ((lane >> 4) << 3)) * ASTR + ((lane >> 3) & 1) * 16);

#pragma unroll 1
    for (int pass = 0; pass < 2; pass++) {
        const int qt = pass ? (int)blockIdx.x : 7 - (int)blockIdx.x;
        __syncthreads();

        // ---- Q tile: 128 rows x 64 bf16 (hi+lo) ----
#pragma unroll
        for (int p = 0; p < 8; p++) {
            const int c   = t + (p << 8);
            const int m   = c >> 10;
            const int idx = c & 1023;
            const int row = idx >> 3;
            const int ch  = idx & 7;
            const __nv_bfloat16* src = (m ? ql : qh) +
                (size_t)(b * 1024 + qt * 128 + row) * 1024 + h * 64 + ch * 8;
            CP_ASYNC16(sb + (m ? QL_OFF : QH_OFF) + row * ASTR + ch * 16, src);
        }
        CP_COMMIT();

        const int kmax = 2 * qt + 1;

        // ---- prologue: K/V for kt=0 into buffer 0, mask[0] ----
#pragma unroll
        for (int p = 0; p < 8; p++) {
            const int c   = t + (p << 8);
            const int m   = c >> 9;
            const int idx = c & 511;
            const int row = idx >> 3;
            const int ch  = idx & 7;
            const __nv_bfloat16* src;
            uint32_t dst;
            if (m == 0) {
                src = kh + (size_t)(b * 1024 + row) * 1024 + h * 64 + ch * 8;
                dst = sb + K_OFF + row * ASTR + ch * 16;
            } else if (m == 1) {
                src = kl + (size_t)(b * 1024 + row) * 1024 + h * 64 + ch * 8;
                dst = sb + K_OFF + 9216 + row * ASTR + ch * 16;
            } else if (m == 2) {
                src = vth + (size_t)(bh * 64 + row) * 1024 + ch * 8;
                dst = sb + V_OFF + row * ASTR + ch * 16;
            } else {
                src = vtl + (size_t)(bh * 64 + row) * 1024 + ch * 8;
                dst = sb + V_OFF + 9216 + row * ASTR + ch * 16;
            }
            CP_ASYNC16(dst, src);
        }
        if (t < 64)
            msk_s[t] = (mask[b * TSEQ + t] != 0) ? 0.0f : -1e30f;
        CP_COMMIT();

        float m0 = -1e30f, m1 = -1e30f, l0 = 0.0f, l1 = 0.0f;
        float of[8][4];
#pragma unroll
        for (int j = 0; j < 8; j++)
#pragma unroll
            for (int e = 0; e < 4; e++) of[j][e] = 0.0f;

        const int qrow_w = qt * 128 + 16 * w;
        const int r0g = qrow_w + (lane >> 2);

#pragma unroll 1
        for (int kt = 0; kt <= kmax; kt++) {
            CP_WAIT(0);
            __syncthreads();

            if (kt < kmax) {
                const uint32_t kb = (uint32_t)(((kt + 1) & 1) * KVBUF);
#pragma unroll
                for (int p = 0; p < 8; p++) {
                    const int c   = t + (p << 8);
                    const int m   = c >> 9;
                    const int idx = c & 511;
                    const int row = idx >> 3;
                    const int ch  = idx & 7;
                    const __nv_bfloat16* src;
                    uint32_t dst;
                    if (m == 0) {
                        src = kh + (size_t)(b * 1024 + (kt + 1) * 64 + row) * 1024 + h * 64 + ch * 8;
                        dst = sb + K_OFF + kb + row * ASTR + ch * 16;
                    } else if (m == 1) {
                        src = kl + (size_t)(b * 1024 + (kt + 1) * 64 + row) * 1024 + h * 64 + ch * 8;
                        dst = sb + K_OFF + kb + 9216 + row * ASTR + ch * 16;
                    } else if (m == 2) {
                        src = vth + (size_t)(bh * 64 + row) * 1024 + (kt + 1) * 64 + ch * 8;
                        dst = sb + V_OFF + kb + row * ASTR + ch * 16;
                    } else {
                        src = vtl + (size_t)(bh * 64 + row) * 1024 + (kt + 1) * 64 + ch * 8;
                        dst = sb + V_OFF + kb + 9216 + row * ASTR + ch * 16;
                    }
                    CP_ASYNC16(dst, src);
                }
                if (t < 64)
                    msk_s[((kt + 1) & 1) * 64 + t] =
                        (mask[b * TSEQ + (kt + 1) * 64 + t] != 0) ? 0.0f : -1e30f;
            }
            CP_COMMIT();

            const uint32_t kb = (uint32_t)((kt & 1) * KVBUF);
            const float* msk = msk_s + (kt & 1) * 64;

            // ---- S = Q @ K^T (scores already in log2 units via QSCALE) ----
            float s[8][4];
#pragma unroll
            for (int j = 0; j < 8; j++)
#pragma unroll
                for (int e = 0; e < 4; e++) s[j][e] = 0.0f;

#pragma unroll
            for (int ks = 0; ks < 4; ks++) {
                uint32_t aqh[4], aql[4];
                LDSM_X4(aqh[0], aqh[1], aqh[2], aqh[3], aq_base + ks * 32);
                LDSM_X4(aql[0], aql[1], aql[2], aql[3],
                        aq_base + (QL_OFF - QH_OFF) + ks * 32);
#pragma unroll
                for (int g = 0; g < 4; g++) {
                    uint32_t bkh[4], bkl[4];
                    LDSM_X4(bkh[0], bkh[1], bkh[2], bkh[3],
                            bk_base + kb + g * (16 * ASTR) + ks * 32);
                    LDSM_X4(bkl[0], bkl[1], bkl[2], bkl[3],
                            bk_base + kb + 9216 + g * (16 * ASTR) + ks * 32);
                    MMA16816(s[2 * g],     aqh, bkh[0], bkh[1]);
                    MMA16816(s[2 * g],     aqh, bkl[0], bkl[1]);
                    MMA16816(s[2 * g],     aql, bkh[0], bkh[1]);
                    MMA16816(s[2 * g + 1], aqh, bkh[2], bkh[3]);
                    MMA16816(s[2 * g + 1], aqh, bkl[2], bkl[3]);
                    MMA16816(s[2 * g + 1], aql, bkh[2], bkh[3]);
                }
            }

            // ---- mask + causal ----
            const int lc = 2 * (lane & 3);
#pragma unroll
            for (int j = 0; j < 8; j++) {
                const float mj0 = msk[j * 8 + lc];
                const float mj1 = msk[j * 8 + lc + 1];
                s[j][0] += mj0; s[j][1] += mj1;
                s[j][2] += mj0; s[j][3] += mj1;
            }
            if (kt * 64 + 63 > qrow_w) {
                const int r1g = r0g + 8;
#pragma unroll
                for (int j = 0; j < 8; j++) {
                    const int c0 = kt * 64 + j * 8 + lc;
                    if (c0     > r0g) s[j][0] = -1e30f;
                    if (c0 + 1 > r0g) s[j][1] = -1e30f;
                    if (c0     > r1g) s[j][2] = -1e30f;
                    if (c0 + 1 > r1g) s[j][3] = -1e30f;
                }
            }

            // ---- online softmax (exp2 domain) ----
            float rm0 = -1e30f, rm1 = -1e30f;
#pragma unroll
            for (int j = 0; j < 8; j++) {
                rm0 = fmaxf(rm0, fmaxf(s[j][0], s[j][1]));
                rm1 = fmaxf(rm1, fmaxf(s[j][2], s[j][3]));
            }
            rm0 = fmaxf(rm0, __shfl_xor_sync(0xffffffffu, rm0, 1));
            rm0 = fmaxf(rm0, __shfl_xor_sync(0xffffffffu, rm0, 2));
            rm1 = fmaxf(rm1, __shfl_xor_sync(0xffffffffu, rm1, 1));
            rm1 = fmaxf(rm1, __shfl_xor_sync(0xffffffffu, rm1, 2));
            const float mn0 = fmaxf(m0, rm0), mn1 = fmaxf(m1, rm1);
            const float al0 = ex2(m0 - mn0), al1 = ex2(m1 - mn1);
            m0 = mn0; m1 = mn1;
            float ls0 = 0.0f, ls1 = 0.0f;
#pragma unroll
            for (int j = 0; j < 8; j++) {
                s[j][0] = ex2(s[j][0] - mn0); ls0 += s[j][0];
                s[j][1] = ex2(s[j][1] - mn0); ls0 += s[j][1];
                s[j][2] = ex2(s[j][2] - mn1); ls1 += s[j][2];
                s[j][3] = ex2(s[j][3] - mn1); ls1 += s[j][3];
            }
            ls0 += __shfl_xor_sync(0xffffffffu, ls0, 1);
            ls0 += __shfl_xor_sync(0xffffffffu, ls0, 2);
            ls1 += __shfl_xor_sync(0xffffffffu, ls1, 1);
            ls1 += __shfl_xor_sync(0xffffffffu, ls1, 2);
            l0 = l0 * al0 + ls0;
            l1 = l1 * al1 + ls1;
#pragma unroll
            for (int j = 0; j < 8; j++) {
                of[j][0] *= al0; of[j][1] *= al0;
                of[j][2] *= al1; of[j][3] *= al1;
            }

            // ---- O += P @ V ----
#pragma unroll
            for (int kt2 = 0; kt2 < 4; kt2++) {
                uint32_t aph[4], apl[4];
                {
                    const float* p0 = s[2 * kt2];
                    const float* p1 = s[2 * kt2 + 1];
                    float hl[8];
#pragma unroll
                    for (int e = 0; e < 4; e++) {
                        hl[e]     = p0[e] - __bfloat162float(__float2bfloat16(p0[e]));
                        hl[4 + e] = p1[e] - __bfloat162float(__float2bfloat16(p1[e]));
                    }
                    aph[0] = packbf(p0[0], p0[1]); aph[1] = packbf(p0[2], p0[3]);
                    aph[2] = packbf(p1[0], p1[1]); aph[3] = packbf(p1[2], p1[3]);
                    apl[0] = packbf(hl[0], hl[1]); apl[1] = packbf(hl[2], hl[3]);
                    apl[2] = packbf(hl[4], hl[5]); apl[3] = packbf(hl[6], hl[7]);
                }
#pragma unroll
                for (int g = 0; g < 4; g++) {
                    uint32_t bvh[4], bvl[4];
                    LDSM_X4(bvh[0], bvh[1], bvh[2], bvh[3],
                            bv_base + kb + g * (16 * ASTR) + kt2 * 32);
                    LDSM_X4(bvl[0], bvl[1], bvl[2], bvl[3],
                            bv_base + kb + 9216 + g * (16 * ASTR) + kt2 * 32);
                    MMA16816(of[2 * g],     aph, bvh[0], bvh[1]);
                    MMA16816(of[2 * g],     aph, bvl[0], bvl[1]);
                    MMA16816(of[2 * g],     apl, bvh[0], bvh[1]);
                    MMA16816(of[2 * g + 1], aph, bvh[2], bvh[3]);
                    MMA16816(of[2 * g + 1], aph, bvl[2], bvl[3]);
                    MMA16816(of[2 * g + 1], apl, bvh[2], bvh[3]);
                }
            }
        }

        // ---- normalize + store single fp16 row-major [B*T, D] ----
        const float inv0 = 1.0f / l0, inv1 = 1.0f / l1;
        const size_t obase = ((size_t)(b * TSEQ) + r0g) * DMODEL + h * DHEAD + 2 * (lane & 3);
#pragma unroll
        for (int j = 0; j < 8; j++) {
            *reinterpret_cast<uint32_t*>(ao + obase + j * 8) =
                packhf(of[j][0] * inv0, of[j][1] * inv0);
            *reinterpret_cast<uint32_t*>(ao + obase + (size_t)8 * DMODEL + j * 8) =
                packhf(of[j][2] * inv1, of[j][3] * inv1);
        }
    }
}

// ---------------------------------------------------------------------------
extern "C" void kernel_launch(void* const* d_in, const int* in_sizes, int n_in,
                              void* d_out, int out_size)
{
    const float* x     = (const float*)d_in[0];
    const float* Wqkv  = (const float*)d_in[1];
    const float* bqkv  = (const float*)d_in[2];
    const float* Wproj = (const float*)d_in[3];
    const float* bproj = (const float*)d_in[4];
    const int*   mask  = (const int*)d_in[5];
    float* out = (float*)d_out;

    __half *x16, *wq16, *wp16, *ao16;
    __nv_bfloat16 *qh, *ql, *kh, *kl, *vh, *vl, *vth, *vtl;
    cudaGetSymbolAddress((void**)&x16,  g_x16);
    cudaGetSymbolAddress((void**)&wq16, g_wq16);
    cudaGetSymbolAddress((void**)&wp16, g_wp16);
    cudaGetSymbolAddress((void**)&ao16, g_ao16);
    cudaGetSymbolAddress((void**)&qh, g_qh);   cudaGetSymbolAddress((void**)&ql, g_ql);
    cudaGetSymbolAddress((void**)&kh, g_kh);   cudaGetSymbolAddress((void**)&kl, g_kl);
    cudaGetSymbolAddress((void**)&vh, g_vh);   cudaGetSymbolAddress((void**)&vl, g_vl);
    cudaGetSymbolAddress((void**)&vth, g_vth); cudaGetSymbolAddress((void**)&vtl, g_vtl);

    cudaFuncSetAttribute(attn_hmma,
                         cudaFuncAttributeMaxDynamicSharedMemorySize, ATTN_SMEM);
    cudaFuncSetAttribute(gemm_f16<0>,
                         cudaFuncAttributeMaxDynamicSharedMemorySize, GEMM_SMEM);
    cudaFuncSetAttribute(gemm_f16<1>,
                         cudaFuncAttributeMaxDynamicSharedMemorySize, GEMM_SMEM);

    // Convert input and weights (weights transposed to [N][K]) to fp16
    convert_h<<<(MROWS * DMODEL) / 1024, 256>>>(x, x16);
    convert_wT<<<dim3(QKV_N / 32, DMODEL / 32), dim3(32, 8)>>>(
        Wqkv, wq16, DMODEL, QKV_N);
    convert_wT<<<dim3(DMODEL / 32, DMODEL / 32), dim3(32, 8)>>>(
        Wproj, wp16, DMODEL, DMODEL);

    // 1) QKV GEMM (fp16 single-product) -> split-bf16 Q(scaled)/K/V
    gemm_f16<1><<<dim3(QKV_N / 128, MROWS / 128), 128, GEMM_SMEM>>>(
        x16, wq16, bqkv, nullptr, qh, ql, kh, kl, vh, vl, QKV_N);

    // 2) V transpose
    transpose_v<<<dim3(32, 128), dim3(32, 8)>>>(vh, vl, vth, vtl);

    // 3) Fused causal attention (bf16 3-product, exp2 softmax) -> fp16 out
    attn_hmma<<<dim3(4, BATCH * NH), 256, ATTN_SMEM>>>(
        qh, ql, kh, kl, vth, vtl, mask, ao16);

    // 4) out = attn @ Wproj + bproj (fp16 single-product)
    gemm_f16<0><<<dim3(DMODEL / 128, MROWS / 128), 128, GEMM_SMEM>>>(
        ao16, wp16, bproj, out,
        nullptr, nullptr, nullptr, nullptr, nullptr, nullptr, DMODEL);
}